// round 4
// baseline (speedup 1.0000x reference)
#include <cuda_runtime.h>
#include <math.h>

#define BATCH 4
#define S 96
#define DP 48
#define L (DP*DP*DP)            // 110592
#define NTOK (BATCH*L)          // 442368
#define MRF 32
#define NCH 108
#define TILE 128
#define NBLK (NTOK/TILE)        // 3456
#define WS2 132                 // duplicated-weight row stride (floats), 16B-aligned

typedef unsigned long long u64;

// ---------------- scratch ----------------
__device__ float g_kp[(size_t)NTOK * MRF];
__device__ float g_qp[(size_t)NTOK * MRF];
__device__ float g_v [(size_t)NTOK * 64];
__device__ float g_part_kptv[BATCH * NCH * 64 * MRF];
__device__ float g_part_ksum[BATCH * NCH * MRF];
__device__ float g_kptv[BATCH * 64 * MRF];
__device__ float g_ksum[BATCH * MRF];

// ---------------- f32x2 helpers ----------------
__device__ __forceinline__ u64 dup2(float v) {
    u64 r; asm("mov.b64 %0, {%1, %1};" : "=l"(r) : "f"(v)); return r;
}
__device__ __forceinline__ void fma2(u64 &d, u64 a, u64 b) {
    asm("fma.rn.f32x2 %0, %1, %2, %0;" : "+l"(d) : "l"(a), "l"(b));
}
__device__ __forceinline__ u64 mul2(u64 a, u64 b) {
    u64 r; asm("mul.rn.f32x2 %0, %1, %2;" : "=l"(r) : "l"(a), "l"(b)); return r;
}
__device__ __forceinline__ u64 add2(u64 a, u64 b) {
    u64 r; asm("add.rn.f32x2 %0, %1, %2;" : "=l"(r) : "l"(a), "l"(b)); return r;
}
__device__ __forceinline__ float2 up2(u64 v) {
    float lo, hi; asm("mov.b64 {%0, %1}, %2;" : "=f"(lo), "=f"(hi) : "l"(v));
    return make_float2(lo, hi);
}

// ============================================================================
// Microkernels. 128 threads: og = tid>>4 (8 groups), tg = tid&15 (8 tokens).
// sW2: duplicated weights [K][WS2], pair {w[o],w[o]} at offset 2o.
// sX:  activations [K][128].
// ============================================================================
template<int KK>
__device__ __forceinline__ void mmW8(const float* __restrict__ sW2,
                                     const float* __restrict__ sX,
                                     int og, int tg, u64 acc[8][4])
{
    const float* wp = sW2 + og * 16;
    const float* xp = sX + tg * 8;
    #pragma unroll 8
    for (int k = 0; k < KK; k++) {
        ulonglong2 wa = *(const ulonglong2*)(wp + k * WS2);
        ulonglong2 wb = *(const ulonglong2*)(wp + k * WS2 + 4);
        ulonglong2 wc = *(const ulonglong2*)(wp + k * WS2 + 8);
        ulonglong2 wd = *(const ulonglong2*)(wp + k * WS2 + 12);
        ulonglong2 xa = *(const ulonglong2*)(xp + k * 128);
        ulonglong2 xb = *(const ulonglong2*)(xp + k * 128 + 4);
        u64 w[8] = {wa.x, wa.y, wb.x, wb.y, wc.x, wc.y, wd.x, wd.y};
        u64 xv[4] = {xa.x, xa.y, xb.x, xb.y};
        #pragma unroll
        for (int o = 0; o < 8; o++)
            #pragma unroll
            for (int tp = 0; tp < 4; tp++) fma2(acc[o][tp], w[o], xv[tp]);
    }
}

// 4 outputs (rows og*4..og*4+3) x 8 tokens — for the 32-row RF GEMM.
template<int KK>
__device__ __forceinline__ void mmW4(const float* __restrict__ sW2,
                                     const float* __restrict__ sX,
                                     int og, int tg, u64 acc[4][4])
{
    const float* wp = sW2 + og * 8;
    const float* xp = sX + tg * 8;
    #pragma unroll 8
    for (int k = 0; k < KK; k++) {
        ulonglong2 wa = *(const ulonglong2*)(wp + k * WS2);
        ulonglong2 wb = *(const ulonglong2*)(wp + k * WS2 + 4);
        ulonglong2 xa = *(const ulonglong2*)(xp + k * 128);
        ulonglong2 xb = *(const ulonglong2*)(xp + k * 128 + 4);
        u64 w[4] = {wa.x, wa.y, wb.x, wb.y};
        u64 xv[4] = {xa.x, xa.y, xb.x, xb.y};
        #pragma unroll
        for (int o = 0; o < 4; o++)
            #pragma unroll
            for (int tp = 0; tp < 4; tp++) fma2(acc[o][tp], w[o], xv[tp]);
    }
}

// ============================================================================
// Pass 1: unfold + LN1 + kqv GEMMs + prm_exp; writes g_kp, g_qp, g_v
// ============================================================================
// smem (floats):
#define P1_SH   0                       // [64][128]
#define P1_ST   8192                    // [64][128]
#define P1_SW   16384                   // [64][WS2] duplicated weights
#define P1_RED  (16384 + 64*WS2)        // [8][128]
#define P1_XD   (P1_RED + 1024)         // [128]
#define P1_LNG  (P1_XD + 128)
#define P1_LNB  (P1_LNG + 64)
#define P1_BIAS (P1_LNB + 64)
#define P1_SMEMF (P1_BIAS + 64)
#define P1_SMEMB (P1_SMEMF*4)

__global__ __launch_bounds__(128) void pass1_kernel(
    const float* __restrict__ x,
    const float* __restrict__ ln1g, const float* __restrict__ ln1b,
    const float* __restrict__ wkqv, const float* __restrict__ bkqv,
    const float* __restrict__ wrf)
{
    extern __shared__ float sm[];
    float* s_h    = sm + P1_SH;
    float* s_t    = sm + P1_ST;
    float* s_w2   = sm + P1_SW;
    float* s_red  = sm + P1_RED;
    float* s_xd   = sm + P1_XD;
    float* s_lng  = sm + P1_LNG;
    float* s_lnb  = sm + P1_LNB;
    float* s_bias = sm + P1_BIAS;

    const int tid = threadIdx.x;
    const int n0  = blockIdx.x * TILE;
    const int b   = n0 / L;
    const int l0  = n0 % L;

    if (tid < 64) { s_lng[tid] = ln1g[tid]; s_lnb[tid] = ln1b[tid]; }

    // ---- gather one token per thread ----
    const int l  = l0 + tid;
    const int dz = l / (DP * DP), hy = (l / DP) % DP, wx = l % DP;
    const float* xb = x + (size_t)b * S * S * S;

    float h[64];
    float sum = 0.0f, sq = 0.0f;
    #pragma unroll
    for (int kd = 0; kd < 4; kd++) {
        const int iz = 2 * dz - 1 + kd;
        const bool zok = (unsigned)iz < (unsigned)S;
        #pragma unroll
        for (int kh = 0; kh < 4; kh++) {
            const int iy = 2 * hy - 1 + kh;
            const bool yok = zok && ((unsigned)iy < (unsigned)S);
            #pragma unroll
            for (int kw = 0; kw < 4; kw++) {
                const int ix = 2 * wx - 1 + kw;
                const float v = (yok && (unsigned)ix < (unsigned)S)
                              ? xb[((size_t)iz * S + iy) * S + ix] : 0.0f;
                h[kd * 16 + kh * 4 + kw] = v; sum += v; sq += v * v;
            }
        }
    }
    const float mu  = sum * (1.0f / 64.0f);
    const float var = sq * (1.0f / 64.0f) - mu * mu;
    const float rs  = rsqrtf(var + 1e-5f);

    __syncthreads();   // s_lng/s_lnb ready
    #pragma unroll
    for (int f = 0; f < 64; f++)
        s_h[f * 128 + tid] = (h[f] - mu) * rs * s_lng[f] + s_lnb[f];

    const int og = tid >> 4, tg = tid & 15;
    const float rfscale = 0.1767766952966369f;   // 1/sqrt(32)

    for (int c = 0; c < 3; c++) {
        __syncthreads();   // prior readers of s_w2 / s_t done (covers s_h for c=0)
        // stage duplicated weight chunk
        for (int i = tid; i < 4096; i += 128) {
            const int o = i >> 6, k = i & 63;
            const float w = wkqv[c * 4096 + i];
            s_w2[k * WS2 + 2 * o] = w; s_w2[k * WS2 + 2 * o + 1] = w;
        }
        if (tid < 64) s_bias[tid] = bkqv[c * 64 + tid];
        __syncthreads();

        u64 acc[8][4];
        #pragma unroll
        for (int o = 0; o < 8; o++) {
            const u64 bv = dup2(s_bias[og * 8 + o]);
            #pragma unroll
            for (int tp = 0; tp < 4; tp++) acc[o][tp] = bv;
        }
        mmW8<64>(s_w2, s_h, og, tg, acc);

        if (c < 2) {
            // per-token sum of squares (packed) + write kqv to s_t
            u64 psq[4] = {0ull, 0ull, 0ull, 0ull};
            #pragma unroll
            for (int o = 0; o < 8; o++) {
                #pragma unroll
                for (int tp = 0; tp < 4; tp++) fma2(psq[tp], acc[o][tp], acc[o][tp]);
                float2 p0 = up2(acc[o][0]), p1 = up2(acc[o][1]);
                float2 p2 = up2(acc[o][2]), p3 = up2(acc[o][3]);
                float* tp0 = &s_t[(og * 8 + o) * 128 + tg * 8];
                *(float4*)tp0       = make_float4(p0.x, p0.y, p1.x, p1.y);
                *(float4*)(tp0 + 4) = make_float4(p2.x, p2.y, p3.x, p3.y);
            }
            #pragma unroll
            for (int tp = 0; tp < 4; tp++) {
                float2 p = up2(psq[tp]);
                s_red[og * 128 + tg * 8 + 2 * tp]     = p.x;
                s_red[og * 128 + tg * 8 + 2 * tp + 1] = p.y;
            }
            __syncthreads();

            // xd per token + stage duplicated wrf (overwrites s_w2)
            {
                float s2 = 0.0f;
                #pragma unroll
                for (int g = 0; g < 8; g++) s2 += s_red[g * 128 + tid];
                s_xd[tid] = 0.5f * s2;
            }
            for (int i = tid; i < 2048; i += 128) {
                const int m = i >> 6, j = i & 63;   // wrf[m][j], K-dim = j
                const float w = wrf[i];
                s_w2[j * WS2 + 2 * m] = w; s_w2[j * WS2 + 2 * m + 1] = w;
            }
            __syncthreads();

            u64 wa[4][4];
            #pragma unroll
            for (int o = 0; o < 4; o++)
                #pragma unroll
                for (int tp = 0; tp < 4; tp++) wa[o][tp] = 0ull;
            mmW4<64>(s_w2, s_t, og, tg, wa);

            float* dst = (c == 0) ? g_kp : g_qp;
            #pragma unroll
            for (int mm = 0; mm < 4; mm++) {
                const int row = og * 4 + mm;
                float o8[8];
                #pragma unroll
                for (int tp = 0; tp < 4; tp++) {
                    float2 wv = up2(wa[mm][tp]);
                    o8[2 * tp]     = expf(wv.x - s_xd[tg * 8 + 2 * tp])     * rfscale;
                    o8[2 * tp + 1] = expf(wv.y - s_xd[tg * 8 + 2 * tp + 1]) * rfscale;
                }
                float* dp = &dst[(size_t)row * NTOK + n0 + tg * 8];
                *(float4*)dp       = make_float4(o8[0], o8[1], o8[2], o8[3]);
                *(float4*)(dp + 4) = make_float4(o8[4], o8[5], o8[6], o8[7]);
            }
        } else {
            #pragma unroll
            for (int o = 0; o < 8; o++) {
                const int row = og * 8 + o;
                float2 p0 = up2(acc[o][0]), p1 = up2(acc[o][1]);
                float2 p2 = up2(acc[o][2]), p3 = up2(acc[o][3]);
                float* dp = &g_v[(size_t)row * NTOK + n0 + tg * 8];
                *(float4*)dp       = make_float4(p0.x, p0.y, p1.x, p1.y);
                *(float4*)(dp + 4) = make_float4(p2.x, p2.y, p3.x, p3.y);
            }
        }
    }
}

// ============================================================================
// Reduce 1 & 2 (unchanged)
// ============================================================================
__global__ __launch_bounds__(256) void reduce1_kernel()
{
    __shared__ float sv[64 * 65];
    __shared__ float sk[MRF * 65];

    const int b = blockIdx.y;
    const int c = blockIdx.x;
    const int t = threadIdx.x;
    const int n0 = b * L + c * 1024;

    const int e  = t >> 2;
    const int mb = (t & 3) * 8;

    float acc[8];
    #pragma unroll
    for (int i = 0; i < 8; i++) acc[i] = 0.0f;
    float ksum = 0.0f;

    for (int tile = 0; tile < 16; tile++) {
        const int base = n0 + tile * 64;
        __syncthreads();
        for (int idx = t; idx < 64 * 64; idx += 256) {
            const int ee = idx >> 6, tt = idx & 63;
            sv[ee * 65 + tt] = g_v[(size_t)ee * NTOK + base + tt];
        }
        for (int idx = t; idx < MRF * 64; idx += 256) {
            const int mm = idx >> 6, tt = idx & 63;
            sk[mm * 65 + tt] = g_kp[(size_t)mm * NTOK + base + tt];
        }
        __syncthreads();

        for (int tt = 0; tt < 64; tt++) {
            const float ve = sv[e * 65 + tt];
            #pragma unroll
            for (int i = 0; i < 8; i++) acc[i] += ve * sk[(mb + i) * 65 + tt];
        }
        if (t < MRF) {
            for (int tt = 0; tt < 64; tt++) ksum += sk[t * 65 + tt];
        }
    }

    const int slot = b * NCH + c;
    #pragma unroll
    for (int i = 0; i < 8; i++)
        g_part_kptv[slot * (64 * MRF) + e * MRF + mb + i] = acc[i];
    if (t < MRF) g_part_ksum[slot * MRF + t] = ksum;
}

__global__ __launch_bounds__(256) void reduce2_kernel()
{
    const int b = blockIdx.x;
    const int t = threadIdx.x;

    float acc[8];
    #pragma unroll
    for (int i = 0; i < 8; i++) acc[i] = 0.0f;
    for (int c = 0; c < NCH; c++) {
        const float* p = &g_part_kptv[(b * NCH + c) * (64 * MRF)];
        #pragma unroll
        for (int i = 0; i < 8; i++) acc[i] += p[t * 8 + i];
    }
    #pragma unroll
    for (int i = 0; i < 8; i++) g_kptv[b * (64 * MRF) + t * 8 + i] = acc[i];

    if (t < MRF) {
        float s = 0.0f;
        for (int c = 0; c < NCH; c++) s += g_part_ksum[(b * NCH + c) * MRF + t];
        g_ksum[b * MRF + t] = s;
    }
}

// ============================================================================
// Pass 2: attn-apply + proj + skip + LN2 + MLP  (y kept in registers)
// ============================================================================
#define P2_SA  0                        // [64][128]
#define P2_SW  8192                     // [64][WS2]
#define P2_QP  (8192 + 64*WS2)          // [32][128]
#define P2_RED (P2_QP + 4096)           // [8][128]
#define P2_RED2 (P2_RED + 1024)         // [8][128]
#define P2_SD  (P2_RED2 + 1024)         // [128] 1/D
#define P2_NMU (P2_SD + 128)            // [128] -mu
#define P2_RS  (P2_NMU + 128)           // [128] rsigma
#define P2_SC  (P2_RS + 128)            // [352]
#define P2_SMEMF (P2_SC + 352)
#define P2_SMEMB (P2_SMEMF*4)

__global__ __launch_bounds__(128) void pass2_kernel(
    const float* __restrict__ wproj, const float* __restrict__ bproj,
    const float* __restrict__ ln2g,  const float* __restrict__ ln2b,
    const float* __restrict__ wfc1,  const float* __restrict__ bfc1,
    const float* __restrict__ wfc2,  const float* __restrict__ bfc2,
    float* __restrict__ out)
{
    extern __shared__ float sm[];
    float* s_a   = sm + P2_SA;
    float* s_w2  = sm + P2_SW;
    float* s_qp  = sm + P2_QP;
    float* s_red = sm + P2_RED;
    float* s_red2= sm + P2_RED2;
    float* s_d   = sm + P2_SD;
    float* s_nmu = sm + P2_NMU;
    float* s_rs  = sm + P2_RS;
    float* s_c   = sm + P2_SC;

    const int tid = threadIdx.x;
    const int n0  = blockIdx.x * TILE;
    const int b   = n0 / L;
    const int og  = tid >> 4, tg = tid & 15;

    // ---- stage qp tile, kA2 (duplicated kptv^T), consts ----
    for (int i = tid; i < 1024; i += 128) {
        const int m = i >> 5, t4 = i & 31;
        *(float4*)&s_qp[m * 128 + t4 * 4] =
            *(const float4*)&g_qp[(size_t)m * NTOK + n0 + t4 * 4];
    }
    for (int i = tid; i < 2048; i += 128) {
        const int j = i >> 5, m = i & 31;   // kptv[e=j][m]; K-dim = m, outs = j
        const float w = g_kptv[b * 2048 + i];
        s_w2[m * WS2 + 2 * j] = w; s_w2[m * WS2 + 2 * j + 1] = w;
    }
    if (tid < 64) {
        s_c[tid]       = bproj[tid];
        s_c[96 + tid]  = ln2g[tid];
        s_c[160 + tid] = ln2b[tid];
        s_c[224 + tid] = bfc1[tid];
        s_c[288 + tid] = bfc2[tid];
    }
    if (tid < 32) s_c[64 + tid] = g_ksum[b * 32 + tid];
    __syncthreads();

    {
        float D = 0.0f;
        #pragma unroll
        for (int m = 0; m < 32; m++) D += s_qp[m * 128 + tid] * s_c[64 + m];
        s_d[tid] = 1.0f / (D + 1e-8f);
    }
    __syncthreads();

    // ---- P1: ya = (kptv^T @ qp) * invD -> s_a ----
    {
        u64 acc[8][4];
        #pragma unroll
        for (int o = 0; o < 8; o++)
            #pragma unroll
            for (int tp = 0; tp < 4; tp++) acc[o][tp] = 0ull;
        mmW8<32>(s_w2, s_qp, og, tg, acc);

        ulonglong2 da = *(const ulonglong2*)(s_d + tg * 8);
        ulonglong2 db = *(const ulonglong2*)(s_d + tg * 8 + 4);
        u64 dp[4] = {da.x, da.y, db.x, db.y};
        #pragma unroll
        for (int o = 0; o < 8; o++) {
            float2 p0 = up2(mul2(acc[o][0], dp[0])), p1 = up2(mul2(acc[o][1], dp[1]));
            float2 p2 = up2(mul2(acc[o][2], dp[2])), p3 = up2(mul2(acc[o][3], dp[3]));
            float* ap = &s_a[(og * 8 + o) * 128 + tg * 8];
            *(float4*)ap       = make_float4(p0.x, p0.y, p1.x, p1.y);
            *(float4*)(ap + 4) = make_float4(p2.x, p2.y, p3.x, p3.y);
        }
    }
    __syncthreads();

    // stage wproj (duplicated)
    for (int i = tid; i < 4096; i += 128) {
        const int o = i >> 6, k = i & 63;
        const float w = wproj[i];
        s_w2[k * WS2 + 2 * o] = w; s_w2[k * WS2 + 2 * o + 1] = w;
    }
    __syncthreads();

    // ---- P2: y = v + wproj @ ya + bproj   (y stays in registers, packed) ----
    u64 y[8][4];
    {
        u64 acc[8][4];
        #pragma unroll
        for (int o = 0; o < 8; o++) {
            const u64 bv = dup2(s_c[og * 8 + o]);
            #pragma unroll
            for (int tp = 0; tp < 4; tp++) acc[o][tp] = bv;
        }
        mmW8<64>(s_w2, s_a, og, tg, acc);
        #pragma unroll
        for (int o = 0; o < 8; o++) {
            const float* vp = &g_v[(size_t)(og * 8 + o) * NTOK + n0 + tg * 8];
            ulonglong2 va = *(const ulonglong2*)vp;
            ulonglong2 vb = *(const ulonglong2*)(vp + 4);
            y[o][0] = add2(acc[o][0], va.x); y[o][1] = add2(acc[o][1], va.y);
            y[o][2] = add2(acc[o][2], vb.x); y[o][3] = add2(acc[o][3], vb.y);
        }
    }

    // ---- LN2 stats: packed per-token partial sums across this thread's 8 rows
    {
        u64 ps[4], pq[4];
        #pragma unroll
        for (int tp = 0; tp < 4; tp++) { ps[tp] = 0ull; pq[tp] = 0ull; }
        #pragma unroll
        for (int o = 0; o < 8; o++)
            #pragma unroll
            for (int tp = 0; tp < 4; tp++) {
                ps[tp] = add2(ps[tp], y[o][tp]);
                fma2(pq[tp], y[o][tp], y[o][tp]);
            }
        #pragma unroll
        for (int tp = 0; tp < 4; tp++) {
            float2 a = up2(ps[tp]), q = up2(pq[tp]);
            s_red [og * 128 + tg * 8 + 2 * tp]     = a.x;
            s_red [og * 128 + tg * 8 + 2 * tp + 1] = a.y;
            s_red2[og * 128 + tg * 8 + 2 * tp]     = q.x;
            s_red2[og * 128 + tg * 8 + 2 * tp + 1] = q.y;
        }
    }
    __syncthreads();
    {
        float s1 = 0.0f, s2 = 0.0f;
        #pragma unroll
        for (int g = 0; g < 8; g++) { s1 += s_red[g * 128 + tid]; s2 += s_red2[g * 128 + tid]; }
        const float mu  = s1 * (1.0f / 64.0f);
        const float var = s2 * (1.0f / 64.0f) - mu * mu;
        s_nmu[tid] = -mu;
        s_rs[tid]  = rsqrtf(var + 1e-5f);
    }
    // stage wfc1 (wproj reads done before previous sync)
    for (int i = tid; i < 4096; i += 128) {
        const int o = i >> 6, k = i & 63;
        const float w = wfc1[i];
        s_w2[k * WS2 + 2 * o] = w; s_w2[k * WS2 + 2 * o + 1] = w;
    }
    __syncthreads();

    // ---- zn -> s_a ----
    {
        ulonglong2 ma = *(const ulonglong2*)(s_nmu + tg * 8);
        ulonglong2 mb2 = *(const ulonglong2*)(s_nmu + tg * 8 + 4);
        ulonglong2 ra = *(const ulonglong2*)(s_rs + tg * 8);
        ulonglong2 rb = *(const ulonglong2*)(s_rs + tg * 8 + 4);
        u64 nm[4] = {ma.x, ma.y, mb2.x, mb2.y};
        u64 rp[4] = {ra.x, ra.y, rb.x, rb.y};
        #pragma unroll
        for (int o = 0; o < 8; o++) {
            const int row = og * 8 + o;
            const u64 gd = dup2(s_c[96 + row]);
            const u64 bd = dup2(s_c[160 + row]);
            float2 r4[4];
            #pragma unroll
            for (int tp = 0; tp < 4; tp++) {
                u64 t2 = mul2(add2(y[o][tp], nm[tp]), rp[tp]);
                u64 zz = bd;
                fma2(zz, t2, gd);
                r4[tp] = up2(zz);
            }
            float* ap = &s_a[row * 128 + tg * 8];
            *(float4*)ap       = make_float4(r4[0].x, r4[0].y, r4[1].x, r4[1].y);
            *(float4*)(ap + 4) = make_float4(r4[2].x, r4[2].y, r4[3].x, r4[3].y);
        }
    }
    __syncthreads();

    // ---- P4: u = gelu(wfc1 @ zn + bfc1) -> s_a ----
    {
        u64 acc[8][4];
        #pragma unroll
        for (int o = 0; o < 8; o++) {
            const u64 bv = dup2(s_c[224 + og * 8 + o]);
            #pragma unroll
            for (int tp = 0; tp < 4; tp++) acc[o][tp] = bv;
        }
        mmW8<64>(s_w2, s_a, og, tg, acc);
        __syncthreads();   // all zn reads done before overwrite

        #pragma unroll
        for (int o = 0; o < 8; o++) {
            float u8[8];
            #pragma unroll
            for (int tp = 0; tp < 4; tp++) {
                float2 p = up2(acc[o][tp]);
                u8[2*tp]   = 0.5f * p.x * (1.0f + erff(p.x * 0.7071067811865476f));
                u8[2*tp+1] = 0.5f * p.y * (1.0f + erff(p.y * 0.7071067811865476f));
            }
            float* ap = &s_a[(og * 8 + o) * 128 + tg * 8];
            *(float4*)ap       = make_float4(u8[0], u8[1], u8[2], u8[3]);
            *(float4*)(ap + 4) = make_float4(u8[4], u8[5], u8[6], u8[7]);
        }
        // stage wfc2 (wfc1 reads done at the sync above)
        for (int i = tid; i < 4096; i += 128) {
            const int o = i >> 6, k = i & 63;
            const float w = wfc2[i];
            s_w2[k * WS2 + 2 * o] = w; s_w2[k * WS2 + 2 * o + 1] = w;
        }
    }
    __syncthreads();

    // ---- P5: out = y + wfc2 @ u + bfc2 ----
    {
        u64 acc[8][4];
        #pragma unroll
        for (int o = 0; o < 8; o++) {
            const u64 bv = dup2(s_c[288 + og * 8 + o]);
            #pragma unroll
            for (int tp = 0; tp < 4; tp++) acc[o][tp] = bv;
        }
        mmW8<64>(s_w2, s_a, og, tg, acc);

        float res[8][8];
        #pragma unroll
        for (int o = 0; o < 8; o++)
            #pragma unroll
            for (int tp = 0; tp < 4; tp++) {
                float2 p = up2(add2(acc[o][tp], y[o][tp]));
                res[o][2*tp] = p.x; res[o][2*tp+1] = p.y;
            }
        #pragma unroll
        for (int j = 0; j < 8; j++) {
            float* op = out + (size_t)(n0 + tg * 8 + j) * 64 + og * 8;
            *(float4*)op       = make_float4(res[0][j], res[1][j], res[2][j], res[3][j]);
            *(float4*)(op + 4) = make_float4(res[4][j], res[5][j], res[6][j], res[7][j]);
        }
    }
}

// ============================================================================
extern "C" void kernel_launch(void* const* d_in, const int* in_sizes, int n_in,
                              void* d_out, int out_size)
{
    const float* x     = (const float*)d_in[0];
    const float* ln1g  = (const float*)d_in[1];
    const float* ln1b  = (const float*)d_in[2];
    const float* wkqv  = (const float*)d_in[3];
    const float* bkqv  = (const float*)d_in[4];
    const float* wproj = (const float*)d_in[5];
    const float* bproj = (const float*)d_in[6];
    const float* ln2g  = (const float*)d_in[7];
    const float* ln2b  = (const float*)d_in[8];
    const float* wfc1  = (const float*)d_in[9];
    const float* bfc1  = (const float*)d_in[10];
    const float* wfc2  = (const float*)d_in[11];
    const float* bfc2  = (const float*)d_in[12];
    const float* wrf   = (const float*)d_in[13];

    cudaFuncSetAttribute(pass1_kernel, cudaFuncAttributeMaxDynamicSharedMemorySize, P1_SMEMB);
    cudaFuncSetAttribute(pass2_kernel, cudaFuncAttributeMaxDynamicSharedMemorySize, P2_SMEMB);

    pass1_kernel<<<NBLK, 128, P1_SMEMB>>>(x, ln1g, ln1b, wkqv, bkqv, wrf);
    reduce1_kernel<<<dim3(NCH, BATCH), 256>>>();
    reduce2_kernel<<<BATCH, 256>>>();
    pass2_kernel<<<NBLK, 128, P2_SMEMB>>>(wproj, bproj, ln2g, ln2b,
                                          wfc1, bfc1, wfc2, bfc2, (float*)d_out);
}

// round 5
// speedup vs baseline: 1.0950x; 1.0950x over previous
#include <cuda_runtime.h>
#include <math.h>

#define BATCH 4
#define S 96
#define DP 48
#define L (DP*DP*DP)            // 110592
#define NTOK (BATCH*L)          // 442368
#define MRF 32
#define NCH 108
#define TILE 128
#define NBLK (NTOK/TILE)        // 3456
#define WS2 132                 // duplicated-weight row stride (floats)

typedef unsigned long long u64;

// ---------------- scratch ----------------
__device__ float g_kp[(size_t)NTOK * MRF];
__device__ float g_qp[(size_t)NTOK * MRF];
__device__ float g_v [(size_t)NTOK * 64];
__device__ float g_part_kptv[BATCH * NCH * 64 * MRF];
__device__ float g_part_ksum[BATCH * NCH * MRF];
__device__ float g_kptv[BATCH * 64 * MRF];
__device__ float g_ksum[BATCH * MRF];

// ---------------- f32x2 helpers ----------------
__device__ __forceinline__ u64 dup2(float v) {
    u64 r; asm("mov.b64 %0, {%1, %1};" : "=l"(r) : "f"(v)); return r;
}
__device__ __forceinline__ void fma2(u64 &d, u64 a, u64 b) {
    asm("fma.rn.f32x2 %0, %1, %2, %0;" : "+l"(d) : "l"(a), "l"(b));
}
__device__ __forceinline__ u64 mul2(u64 a, u64 b) {
    u64 r; asm("mul.rn.f32x2 %0, %1, %2;" : "=l"(r) : "l"(a), "l"(b)); return r;
}
__device__ __forceinline__ u64 add2(u64 a, u64 b) {
    u64 r; asm("add.rn.f32x2 %0, %1, %2;" : "=l"(r) : "l"(a), "l"(b)); return r;
}
__device__ __forceinline__ float2 up2(u64 v) {
    float lo, hi; asm("mov.b64 {%0, %1}, %2;" : "=f"(lo), "=f"(hi) : "l"(v));
    return make_float2(lo, hi);
}

// ============================================================================
// Microkernels. 256 threads: og = tid>>5 (8 output groups of 8), tg = tid&31
// (32 token groups of 4). sW2: duplicated weights [K][WS2] (pair {w,w} at 2o).
// sX: activations [K][128]. acc[o][tp] = f32x2 over token pairs.
// ============================================================================
template<int KK>
__device__ __forceinline__ void mmD8(const float* __restrict__ sW2,
                                     const float* __restrict__ sX,
                                     int og, int tg, u64 acc[8][2])
{
    const float* wp = sW2 + og * 16;
    const float* xp = sX + tg * 4;
    #pragma unroll 8
    for (int k = 0; k < KK; k++) {
        ulonglong2 wa = *(const ulonglong2*)(wp + k * WS2);
        ulonglong2 wb = *(const ulonglong2*)(wp + k * WS2 + 4);
        ulonglong2 wc = *(const ulonglong2*)(wp + k * WS2 + 8);
        ulonglong2 wd = *(const ulonglong2*)(wp + k * WS2 + 12);
        ulonglong2 xa = *(const ulonglong2*)(xp + k * 128);
        fma2(acc[0][0], wa.x, xa.x); fma2(acc[0][1], wa.x, xa.y);
        fma2(acc[1][0], wa.y, xa.x); fma2(acc[1][1], wa.y, xa.y);
        fma2(acc[2][0], wb.x, xa.x); fma2(acc[2][1], wb.x, xa.y);
        fma2(acc[3][0], wb.y, xa.x); fma2(acc[3][1], wb.y, xa.y);
        fma2(acc[4][0], wc.x, xa.x); fma2(acc[4][1], wc.x, xa.y);
        fma2(acc[5][0], wc.y, xa.x); fma2(acc[5][1], wc.y, xa.y);
        fma2(acc[6][0], wd.x, xa.x); fma2(acc[6][1], wd.x, xa.y);
        fma2(acc[7][0], wd.y, xa.x); fma2(acc[7][1], wd.y, xa.y);
    }
}

// 4 outputs (rows og*4..+3) x 4 tokens — for the 32-row RF GEMM.
template<int KK>
__device__ __forceinline__ void mmD4(const float* __restrict__ sW2,
                                     const float* __restrict__ sX,
                                     int og, int tg, u64 acc[4][2])
{
    const float* wp = sW2 + og * 8;
    const float* xp = sX + tg * 4;
    #pragma unroll 8
    for (int k = 0; k < KK; k++) {
        ulonglong2 wa = *(const ulonglong2*)(wp + k * WS2);
        ulonglong2 wb = *(const ulonglong2*)(wp + k * WS2 + 4);
        ulonglong2 xa = *(const ulonglong2*)(xp + k * 128);
        fma2(acc[0][0], wa.x, xa.x); fma2(acc[0][1], wa.x, xa.y);
        fma2(acc[1][0], wa.y, xa.x); fma2(acc[1][1], wa.y, xa.y);
        fma2(acc[2][0], wb.x, xa.x); fma2(acc[2][1], wb.x, xa.y);
        fma2(acc[3][0], wb.y, xa.x); fma2(acc[3][1], wb.y, xa.y);
    }
}

__device__ __forceinline__ void st4(float* p, u64 a, u64 b) {
    float2 p0 = up2(a), p1 = up2(b);
    *(float4*)p = make_float4(p0.x, p0.y, p1.x, p1.y);
}

// ============================================================================
// Pass 1: unfold + LN1 + kqv GEMMs + prm_exp; writes g_kp, g_qp, g_v
// ============================================================================
#define P1_SH   0                       // [64][128]
#define P1_ST   8192                    // [64][128]
#define P1_SW   16384                   // [64][WS2] duplicated weights
#define P1_RED  (16384 + 64*WS2)        // [8][128]
#define P1_XD   (P1_RED + 1024)        // [128]
#define P1_LNG  (P1_XD + 128)
#define P1_LNB  (P1_LNG + 64)
#define P1_BIAS (P1_LNB + 64)
#define P1_SMEMF (P1_BIAS + 64)
#define P1_SMEMB (P1_SMEMF*4)

__global__ __launch_bounds__(256, 2) void pass1_kernel(
    const float* __restrict__ x,
    const float* __restrict__ ln1g, const float* __restrict__ ln1b,
    const float* __restrict__ wkqv, const float* __restrict__ bkqv,
    const float* __restrict__ wrf)
{
    extern __shared__ float sm[];
    float* s_h    = sm + P1_SH;
    float* s_t    = sm + P1_ST;
    float* s_w2   = sm + P1_SW;
    float* s_red  = sm + P1_RED;
    float* s_xd   = sm + P1_XD;
    float* s_lng  = sm + P1_LNG;
    float* s_lnb  = sm + P1_LNB;
    float* s_bias = sm + P1_BIAS;

    const int tid = threadIdx.x;
    const int n0  = blockIdx.x * TILE;
    const int b   = n0 / L;
    const int l0  = n0 % L;

    if (tid < 64) { s_lng[tid] = ln1g[tid]; s_lnb[tid] = ln1b[tid]; }

    // ---- gather + LN1 (2 threads per token) ----
    const int tok = tid >> 1, half = tid & 1;
    const int l  = l0 + tok;
    const int dz = l / (DP * DP), hy = (l / DP) % DP, wx = l % DP;
    const float* xb = x + (size_t)b * S * S * S;

    float hv[32];
    float sum = 0.0f, sq = 0.0f;
    #pragma unroll
    for (int kd2 = 0; kd2 < 2; kd2++) {
        const int iz = 2 * dz - 1 + half * 2 + kd2;
        const bool zok = (unsigned)iz < (unsigned)S;
        #pragma unroll
        for (int kh = 0; kh < 4; kh++) {
            const int iy = 2 * hy - 1 + kh;
            const bool yok = zok && ((unsigned)iy < (unsigned)S);
            #pragma unroll
            for (int kw = 0; kw < 4; kw++) {
                const int ix = 2 * wx - 1 + kw;
                const float v = (yok && (unsigned)ix < (unsigned)S)
                              ? xb[((size_t)iz * S + iy) * S + ix] : 0.0f;
                hv[kd2 * 16 + kh * 4 + kw] = v; sum += v; sq += v * v;
            }
        }
    }
    sum += __shfl_xor_sync(0xffffffffu, sum, 1);
    sq  += __shfl_xor_sync(0xffffffffu, sq, 1);
    const float mu  = sum * (1.0f / 64.0f);
    const float var = sq * (1.0f / 64.0f) - mu * mu;
    const float rs  = rsqrtf(var + 1e-5f);

    __syncthreads();   // s_lng/s_lnb ready
    #pragma unroll
    for (int i2 = 0; i2 < 32; i2++) {
        const int f = half * 32 + i2;
        s_h[f * 128 + tok] = (hv[i2] - mu) * rs * s_lng[f] + s_lnb[f];
    }

    const int og = tid >> 5, tg = tid & 31;
    const float rfscale = 0.1767766952966369f;   // 1/sqrt(32)

    for (int c = 0; c < 3; c++) {
        __syncthreads();   // prior readers of s_w2/s_t done (covers s_h for c=0)
        for (int i = tid; i < 4096; i += 256) {
            const int o = i >> 6, k = i & 63;
            const float w = wkqv[c * 4096 + i];
            *(float2*)&s_w2[k * WS2 + 2 * o] = make_float2(w, w);
        }
        if (tid < 64) s_bias[tid] = bkqv[c * 64 + tid];
        __syncthreads();

        u64 acc[8][2];
        #pragma unroll
        for (int o = 0; o < 8; o++) {
            const u64 bv = dup2(s_bias[og * 8 + o]);
            acc[o][0] = bv; acc[o][1] = bv;
        }
        mmD8<64>(s_w2, s_h, og, tg, acc);

        if (c < 2) {
            // per-token sum of squares (packed) + write kqv to s_t
            u64 psq[2] = {0ull, 0ull};
            #pragma unroll
            for (int o = 0; o < 8; o++) {
                fma2(psq[0], acc[o][0], acc[o][0]);
                fma2(psq[1], acc[o][1], acc[o][1]);
                st4(&s_t[(og * 8 + o) * 128 + tg * 4], acc[o][0], acc[o][1]);
            }
            st4(&s_red[og * 128 + tg * 4], psq[0], psq[1]);
            __syncthreads();

            // xd per token; stage duplicated wrf (mmD8 reads of s_w2 done)
            if (tid < 128) {
                float s2 = 0.0f;
                #pragma unroll
                for (int g = 0; g < 8; g++) s2 += s_red[g * 128 + tid];
                s_xd[tid] = 0.5f * s2;
            }
            for (int i = tid; i < 2048; i += 256) {
                const int m = i >> 6, j = i & 63;   // wrf[m][j], K-dim = j
                const float w = wrf[i];
                *(float2*)&s_w2[j * WS2 + 2 * m] = make_float2(w, w);
            }
            __syncthreads();

            u64 wa[4][2];
            #pragma unroll
            for (int o = 0; o < 4; o++) { wa[o][0] = 0ull; wa[o][1] = 0ull; }
            mmD4<64>(s_w2, s_t, og, tg, wa);

            float* dst = (c == 0) ? g_kp : g_qp;
            const float4 xd4 = *(const float4*)&s_xd[tg * 4];
            #pragma unroll
            for (int mm = 0; mm < 4; mm++) {
                const int row = og * 4 + mm;
                float2 w0 = up2(wa[mm][0]), w1 = up2(wa[mm][1]);
                float4 o4 = make_float4(
                    __expf(w0.x - xd4.x) * rfscale,
                    __expf(w0.y - xd4.y) * rfscale,
                    __expf(w1.x - xd4.z) * rfscale,
                    __expf(w1.y - xd4.w) * rfscale);
                *(float4*)&dst[(size_t)row * NTOK + n0 + tg * 4] = o4;
            }
        } else {
            #pragma unroll
            for (int o = 0; o < 8; o++)
                st4(&g_v[(size_t)(og * 8 + o) * NTOK + n0 + tg * 4],
                    acc[o][0], acc[o][1]);
        }
    }
}

// ============================================================================
// Reduce 1 & 2 (unchanged)
// ============================================================================
__global__ __launch_bounds__(256) void reduce1_kernel()
{
    __shared__ float sv[64 * 65];
    __shared__ float sk[MRF * 65];

    const int b = blockIdx.y;
    const int c = blockIdx.x;
    const int t = threadIdx.x;
    const int n0 = b * L + c * 1024;

    const int e  = t >> 2;
    const int mb = (t & 3) * 8;

    float acc[8];
    #pragma unroll
    for (int i = 0; i < 8; i++) acc[i] = 0.0f;
    float ksum = 0.0f;

    for (int tile = 0; tile < 16; tile++) {
        const int base = n0 + tile * 64;
        __syncthreads();
        for (int idx = t; idx < 64 * 64; idx += 256) {
            const int ee = idx >> 6, tt = idx & 63;
            sv[ee * 65 + tt] = g_v[(size_t)ee * NTOK + base + tt];
        }
        for (int idx = t; idx < MRF * 64; idx += 256) {
            const int mm = idx >> 6, tt = idx & 63;
            sk[mm * 65 + tt] = g_kp[(size_t)mm * NTOK + base + tt];
        }
        __syncthreads();

        for (int tt = 0; tt < 64; tt++) {
            const float ve = sv[e * 65 + tt];
            #pragma unroll
            for (int i = 0; i < 8; i++) acc[i] += ve * sk[(mb + i) * 65 + tt];
        }
        if (t < MRF) {
            for (int tt = 0; tt < 64; tt++) ksum += sk[t * 65 + tt];
        }
    }

    const int slot = b * NCH + c;
    #pragma unroll
    for (int i = 0; i < 8; i++)
        g_part_kptv[slot * (64 * MRF) + e * MRF + mb + i] = acc[i];
    if (t < MRF) g_part_ksum[slot * MRF + t] = ksum;
}

__global__ __launch_bounds__(256) void reduce2_kernel()
{
    const int b = blockIdx.x;
    const int t = threadIdx.x;

    float acc[8];
    #pragma unroll
    for (int i = 0; i < 8; i++) acc[i] = 0.0f;
    for (int c = 0; c < NCH; c++) {
        const float* p = &g_part_kptv[(b * NCH + c) * (64 * MRF)];
        #pragma unroll
        for (int i = 0; i < 8; i++) acc[i] += p[t * 8 + i];
    }
    #pragma unroll
    for (int i = 0; i < 8; i++) g_kptv[b * (64 * MRF) + t * 8 + i] = acc[i];

    if (t < MRF) {
        float s = 0.0f;
        for (int c = 0; c < NCH; c++) s += g_part_ksum[(b * NCH + c) * MRF + t];
        g_ksum[b * MRF + t] = s;
    }
}

// ============================================================================
// Pass 2: attn-apply + proj + skip + LN2 + MLP (y in smem, aliased over qp)
// ============================================================================
#define P2_SA   0                        // [64][128] ya -> zn -> u
#define P2_SY   8192                     // [64][128] y; first half doubles as qp
#define P2_SW   16384                    // [64][WS2]
#define P2_RED  (16384 + 64*WS2)         // [8][128]
#define P2_RED2 (P2_RED + 1024)          // [8][128]
#define P2_SD   (P2_RED2 + 1024)         // [128] 1/D
#define P2_NMU  (P2_SD + 128)            // [128] -mu
#define P2_RS   (P2_NMU + 128)           // [128] rsigma
#define P2_SC   (P2_RS + 128)            // [352]
#define P2_SMEMF (P2_SC + 352)
#define P2_SMEMB (P2_SMEMF*4)

__global__ __launch_bounds__(256, 2) void pass2_kernel(
    const float* __restrict__ wproj, const float* __restrict__ bproj,
    const float* __restrict__ ln2g,  const float* __restrict__ ln2b,
    const float* __restrict__ wfc1,  const float* __restrict__ bfc1,
    const float* __restrict__ wfc2,  const float* __restrict__ bfc2,
    float* __restrict__ out)
{
    extern __shared__ float sm[];
    float* s_a   = sm + P2_SA;
    float* s_y   = sm + P2_SY;
    float* s_qp  = sm + P2_SY;       // alias: qp dead before y written
    float* s_w2  = sm + P2_SW;
    float* s_red = sm + P2_RED;
    float* s_red2= sm + P2_RED2;
    float* s_d   = sm + P2_SD;
    float* s_nmu = sm + P2_NMU;
    float* s_rs  = sm + P2_RS;
    float* s_c   = sm + P2_SC;

    const int tid = threadIdx.x;
    const int n0  = blockIdx.x * TILE;
    const int b   = n0 / L;
    const int og  = tid >> 5, tg = tid & 31;

    // ---- P0: stage qp tile, duplicated kptv^T, consts ----
    for (int i = tid; i < 1024; i += 256) {
        const int m = i >> 5, t4 = i & 31;
        *(float4*)&s_qp[m * 128 + t4 * 4] =
            *(const float4*)&g_qp[(size_t)m * NTOK + n0 + t4 * 4];
    }
    for (int i = tid; i < 2048; i += 256) {
        const int j = i >> 5, m = i & 31;   // kptv[e=j][m]; K-dim = m
        const float w = g_kptv[b * 2048 + i];
        *(float2*)&s_w2[m * WS2 + 2 * j] = make_float2(w, w);
    }
    if (tid < 64) {
        s_c[tid]       = bproj[tid];
        s_c[96 + tid]  = ln2g[tid];
        s_c[160 + tid] = ln2b[tid];
        s_c[224 + tid] = bfc1[tid];
        s_c[288 + tid] = bfc2[tid];
    }
    if (tid < 32) s_c[64 + tid] = g_ksum[b * 32 + tid];
    __syncthreads();

    if (tid < 128) {
        float D = 0.0f;
        #pragma unroll
        for (int m = 0; m < 32; m++) D += s_qp[m * 128 + tid] * s_c[64 + m];
        s_d[tid] = 1.0f / (D + 1e-8f);
    }
    __syncthreads();

    // ---- P1: ya = (kptv^T @ qp) * invD -> s_a ----
    {
        u64 acc[8][2];
        #pragma unroll
        for (int o = 0; o < 8; o++) { acc[o][0] = 0ull; acc[o][1] = 0ull; }
        mmD8<32>(s_w2, s_qp, og, tg, acc);

        ulonglong2 dd = *(const ulonglong2*)(s_d + tg * 4);
        #pragma unroll
        for (int o = 0; o < 8; o++)
            st4(&s_a[(og * 8 + o) * 128 + tg * 4],
                mul2(acc[o][0], dd.x), mul2(acc[o][1], dd.y));
    }
    __syncthreads();

    for (int i = tid; i < 4096; i += 256) {
        const int o = i >> 6, k = i & 63;
        const float w = wproj[i];
        *(float2*)&s_w2[k * WS2 + 2 * o] = make_float2(w, w);
    }
    __syncthreads();

    // ---- P2: y = v + wproj @ ya + bproj -> s_y; LN2 partials ----
    {
        u64 acc[8][2];
        #pragma unroll
        for (int o = 0; o < 8; o++) {
            const u64 bv = dup2(s_c[og * 8 + o]);
            acc[o][0] = bv; acc[o][1] = bv;
        }
        mmD8<64>(s_w2, s_a, og, tg, acc);

        u64 ps[2] = {0ull, 0ull}, pq[2] = {0ull, 0ull};
        #pragma unroll
        for (int o = 0; o < 8; o++) {
            const float* vp = &g_v[(size_t)(og * 8 + o) * NTOK + n0 + tg * 4];
            ulonglong2 vv = *(const ulonglong2*)vp;
            u64 y0 = add2(acc[o][0], vv.x);
            u64 y1 = add2(acc[o][1], vv.y);
            ps[0] = add2(ps[0], y0); ps[1] = add2(ps[1], y1);
            fma2(pq[0], y0, y0);     fma2(pq[1], y1, y1);
            st4(&s_y[(og * 8 + o) * 128 + tg * 4], y0, y1);
        }
        st4(&s_red [og * 128 + tg * 4], ps[0], ps[1]);
        st4(&s_red2[og * 128 + tg * 4], pq[0], pq[1]);
    }
    __syncthreads();

    if (tid < 128) {
        float s1 = 0.0f, s2 = 0.0f;
        #pragma unroll
        for (int g = 0; g < 8; g++) { s1 += s_red[g * 128 + tid]; s2 += s_red2[g * 128 + tid]; }
        const float mu  = s1 * (1.0f / 64.0f);
        const float var = s2 * (1.0f / 64.0f) - mu * mu;
        s_nmu[tid] = -mu;
        s_rs[tid]  = rsqrtf(var + 1e-5f);
    }
    for (int i = tid; i < 4096; i += 256) {   // stage wfc1 (wproj reads done)
        const int o = i >> 6, k = i & 63;
        const float w = wfc1[i];
        *(float2*)&s_w2[k * WS2 + 2 * o] = make_float2(w, w);
    }
    __syncthreads();

    // ---- zn -> s_a (ya reads all done two syncs ago) ----
    {
        ulonglong2 nm = *(const ulonglong2*)(s_nmu + tg * 4);
        ulonglong2 rp = *(const ulonglong2*)(s_rs + tg * 4);
        #pragma unroll
        for (int o = 0; o < 8; o++) {
            const int row = og * 8 + o;
            const u64 gd = dup2(s_c[96 + row]);
            const u64 bd = dup2(s_c[160 + row]);
            ulonglong2 yy = *(const ulonglong2*)&s_y[row * 128 + tg * 4];
            u64 z0 = bd, z1 = bd;
            fma2(z0, mul2(add2(yy.x, nm.x), rp.x), gd);
            fma2(z1, mul2(add2(yy.y, nm.y), rp.y), gd);
            st4(&s_a[row * 128 + tg * 4], z0, z1);
        }
    }
    __syncthreads();

    // ---- P4: u = gelu(wfc1 @ zn + bfc1) -> s_a ----
    {
        u64 acc[8][2];
        #pragma unroll
        for (int o = 0; o < 8; o++) {
            const u64 bv = dup2(s_c[224 + og * 8 + o]);
            acc[o][0] = bv; acc[o][1] = bv;
        }
        mmD8<64>(s_w2, s_a, og, tg, acc);
        __syncthreads();   // all zn + wfc1 reads done

        #pragma unroll
        for (int o = 0; o < 8; o++) {
            float2 p0 = up2(acc[o][0]), p1 = up2(acc[o][1]);
            float4 u4 = make_float4(
                0.5f * p0.x * (1.0f + erff(p0.x * 0.7071067811865476f)),
                0.5f * p0.y * (1.0f + erff(p0.y * 0.7071067811865476f)),
                0.5f * p1.x * (1.0f + erff(p1.x * 0.7071067811865476f)),
                0.5f * p1.y * (1.0f + erff(p1.y * 0.7071067811865476f)));
            *(float4*)&s_a[(og * 8 + o) * 128 + tg * 4] = u4;
        }
        for (int i = tid; i < 4096; i += 256) {   // stage wfc2
            const int o = i >> 6, k = i & 63;
            const float w = wfc2[i];
            *(float2*)&s_w2[k * WS2 + 2 * o] = make_float2(w, w);
        }
    }
    __syncthreads();

    // ---- P5: out = y + wfc2 @ u + bfc2 ----
    {
        u64 acc[8][2];
        #pragma unroll
        for (int o = 0; o < 8; o++) {
            const u64 bv = dup2(s_c[288 + og * 8 + o]);
            acc[o][0] = bv; acc[o][1] = bv;
        }
        mmD8<64>(s_w2, s_a, og, tg, acc);

        float res[8][4];
        #pragma unroll
        for (int o = 0; o < 8; o++) {
            ulonglong2 yy = *(const ulonglong2*)&s_y[(og * 8 + o) * 128 + tg * 4];
            float2 p0 = up2(add2(acc[o][0], yy.x));
            float2 p1 = up2(add2(acc[o][1], yy.y));
            res[o][0] = p0.x; res[o][1] = p0.y; res[o][2] = p1.x; res[o][3] = p1.y;
        }
        #pragma unroll
        for (int j = 0; j < 4; j++) {
            float* op = out + (size_t)(n0 + tg * 4 + j) * 64 + og * 8;
            *(float4*)op       = make_float4(res[0][j], res[1][j], res[2][j], res[3][j]);
            *(float4*)(op + 4) = make_float4(res[4][j], res[5][j], res[6][j], res[7][j]);
        }
    }
}

// ============================================================================
extern "C" void kernel_launch(void* const* d_in, const int* in_sizes, int n_in,
                              void* d_out, int out_size)
{
    const float* x     = (const float*)d_in[0];
    const float* ln1g  = (const float*)d_in[1];
    const float* ln1b  = (const float*)d_in[2];
    const float* wkqv  = (const float*)d_in[3];
    const float* bkqv  = (const float*)d_in[4];
    const float* wproj = (const float*)d_in[5];
    const float* bproj = (const float*)d_in[6];
    const float* ln2g  = (const float*)d_in[7];
    const float* ln2b  = (const float*)d_in[8];
    const float* wfc1  = (const float*)d_in[9];
    const float* bfc1  = (const float*)d_in[10];
    const float* wfc2  = (const float*)d_in[11];
    const float* bfc2  = (const float*)d_in[12];
    const float* wrf   = (const float*)d_in[13];

    cudaFuncSetAttribute(pass1_kernel, cudaFuncAttributeMaxDynamicSharedMemorySize, P1_SMEMB);
    cudaFuncSetAttribute(pass2_kernel, cudaFuncAttributeMaxDynamicSharedMemorySize, P2_SMEMB);

    pass1_kernel<<<NBLK, 256, P1_SMEMB>>>(x, ln1g, ln1b, wkqv, bkqv, wrf);
    reduce1_kernel<<<dim3(NCH, BATCH), 256>>>();
    reduce2_kernel<<<BATCH, 256>>>();
    pass2_kernel<<<NBLK, 256, P2_SMEMB>>>(wproj, bproj, ln2g, ln2b,
                                          wfc1, bfc1, wfc2, bfc2, (float*)d_out);
}

// round 9
// speedup vs baseline: 1.3132x; 1.1992x over previous
#include <cuda_runtime.h>
#include <cuda_bf16.h>
#include <stdint.h>
#include <math.h>

#define BATCH 4
#define S 96
#define DP 48
#define L (DP*DP*DP)            // 110592
#define NTOK (BATCH*L)          // 442368
#define MRF 32
#define NCH 108
#define TILE 128
#define NBLK (NTOK/TILE)        // 3456

typedef unsigned int u32;

// ---------------- scratch ----------------
__device__ float g_kp[(size_t)NTOK * MRF];        // [m][tok]
__device__ float g_qp[(size_t)NTOK * MRF];        // token-major [tok][m]
__device__ float g_v [(size_t)NTOK * 64];         // [e][tok]
__device__ float g_part_kptv[BATCH * NCH * 64 * MRF];
__device__ float g_part_ksum[BATCH * NCH * MRF];
__device__ float g_kptv[BATCH * 64 * MRF];
__device__ float g_ksum[BATCH * MRF];

// ============================================================================
// mma.sync m16n8k16 bf16 GEMM core (sm_80+ path; tcgen05 unavailable at sm_100)
// A tiles: [rows][72] bf16 (144-B row stride), row-major, no swizzle.
// B tiles: weights [outs][72] bf16, K contiguous per out row (col-major k x n).
// ============================================================================
__device__ __forceinline__ void mma16816(float* c, const u32* a, u32 b0, u32 b1) {
    asm volatile(
        "mma.sync.aligned.m16n8k16.row.col.f32.bf16.bf16.f32 "
        "{%0,%1,%2,%3}, {%4,%5,%6,%7}, {%8,%9}, {%0,%1,%2,%3};"
        : "+f"(c[0]), "+f"(c[1]), "+f"(c[2]), "+f"(c[3])
        : "r"(a[0]), "r"(a[1]), "r"(a[2]), "r"(a[3]), "r"(b0), "r"(b1));
}

// Warp computes C[32 tokens x NT*8 outs] for its token block (w*32..w*32+31).
// 3-term split: Ahi*Bhi + Alo*Bhi + Ahi*Blo.
template<int KSTEPS, int NT>
__device__ __forceinline__ void mma_tile(
    const char* ah, const char* al,
    const char* bh, const char* bl,
    float (&acc)[2][NT][4], int w, int lane)
{
    const int g = lane >> 2;
    const int tig = lane & 3;
    #pragma unroll
    for (int ks = 0; ks < KSTEPS; ks++) {
        const int coff = ks * 32 + tig * 4;
        u32 Ah[2][4], Al[2][4];
        #pragma unroll
        for (int mt = 0; mt < 2; mt++) {
            const int r0 = (w * 32 + mt * 16 + g) * 144 + coff;
            const int r8 = r0 + 8 * 144;
            Ah[mt][0] = *(const u32*)(ah + r0);
            Ah[mt][1] = *(const u32*)(ah + r8);
            Ah[mt][2] = *(const u32*)(ah + r0 + 16);
            Ah[mt][3] = *(const u32*)(ah + r8 + 16);
            Al[mt][0] = *(const u32*)(al + r0);
            Al[mt][1] = *(const u32*)(al + r8);
            Al[mt][2] = *(const u32*)(al + r0 + 16);
            Al[mt][3] = *(const u32*)(al + r8 + 16);
        }
        #pragma unroll
        for (int nt = 0; nt < NT; nt++) {
            const int bo = (nt * 8 + g) * 144 + coff;
            const u32 Bh0 = *(const u32*)(bh + bo);
            const u32 Bh1 = *(const u32*)(bh + bo + 16);
            const u32 Bl0 = *(const u32*)(bl + bo);
            const u32 Bl1 = *(const u32*)(bl + bo + 16);
            #pragma unroll
            for (int mt = 0; mt < 2; mt++) {
                mma16816(acc[mt][nt], Ah[mt], Bh0, Bh1);
                mma16816(acc[mt][nt], Al[mt], Bh0, Bh1);
                mma16816(acc[mt][nt], Ah[mt], Bl0, Bl1);
            }
        }
    }
}

// C fragments -> fp32 smem tile [128][66]
template<int NT>
__device__ __forceinline__ void store_ct(float* ct, const float (&acc)[2][NT][4],
                                         int w, int lane)
{
    const int g = lane >> 2;
    const int tig = lane & 3;
    #pragma unroll
    for (int mt = 0; mt < 2; mt++) {
        const int t0 = w * 32 + mt * 16 + g;
        #pragma unroll
        for (int nt = 0; nt < NT; nt++) {
            const int col = nt * 8 + 2 * tig;
            *(float2*)&ct[t0 * 66 + col] =
                make_float2(acc[mt][nt][0], acc[mt][nt][1]);
            *(float2*)&ct[(t0 + 8) * 66 + col] =
                make_float2(acc[mt][nt][2], acc[mt][nt][3]);
        }
    }
}

// -------- bf16 hi/lo split + packing --------
__device__ __forceinline__ void split_pair(float x0, float x1, u32& hi, u32& lo) {
    __nv_bfloat16 h0 = __float2bfloat16_rn(x0);
    __nv_bfloat16 h1 = __float2bfloat16_rn(x1);
    float r0 = x0 - __bfloat162float(h0);
    float r1 = x1 - __bfloat162float(h1);
    __nv_bfloat16 l0 = __float2bfloat16_rn(r0);
    __nv_bfloat16 l1 = __float2bfloat16_rn(r1);
    __nv_bfloat162 hh = __halves2bfloat162(h0, h1);
    __nv_bfloat162 ll = __halves2bfloat162(l0, l1);
    hi = *(u32*)&hh;
    lo = *(u32*)&ll;
}

// store NE floats of activation row `row` into hi/lo A tiles (144-B stride)
template<int NE>
__device__ __forceinline__ void store_row(char* ahi, char* alo, int row,
                                          const float* v) {
    #pragma unroll
    for (int ch = 0; ch < NE / 8; ch++) {
        u32 h0, l0, h1, l1, h2, l2, h3, l3;
        split_pair(v[ch*8+0], v[ch*8+1], h0, l0);
        split_pair(v[ch*8+2], v[ch*8+3], h1, l1);
        split_pair(v[ch*8+4], v[ch*8+5], h2, l2);
        split_pair(v[ch*8+6], v[ch*8+7], h3, l3);
        const int off = row * 144 + ch * 16;
        *(uint4*)(ahi + off) = make_uint4(h0, h1, h2, h3);
        *(uint4*)(alo + off) = make_uint4(l0, l1, l2, l3);
    }
}

// stage weight [rows][COLS] fp32 row-major -> split bf16 tiles (144-B rows)
template<int COLS>
__device__ __forceinline__ void stage_w(char* bhi, char* blo,
                                        const float* __restrict__ g,
                                        int rows, int tid) {
    const int PPR = COLS / 2;
    for (int p = tid; p < rows * PPR; p += 128) {
        const int o = p / PPR;
        const int kp = p % PPR;
        const float2 w = *(const float2*)(g + o * COLS + kp * 2);
        u32 hi, lo;
        split_pair(w.x, w.y, hi, lo);
        const int off = o * 144 + kp * 4;
        *(u32*)(bhi + off) = hi;
        *(u32*)(blo + off) = lo;
    }
}

// ============================================================================
// Pass 1: unfold + LN1 + kqv (split-bf16 mma) + prm_exp; writes kp, qp, v
// smem byte offsets (within 1024-aligned base):
//   cst 0..2047 (floats: lng@16, lnb@80, bkqv@144)
//   Ah(h) 2048, Al 20480          (each 18432)
//   A2h 38912, A2l 57344          (each 18432)  [CT aliases 38912..72703]
//   Bh 75776, Bl 84992            (each 9216)
//   B2h 94208, B2l 98816          (each 4608, 32 rows)
// ============================================================================
#define Q1_AH  2048
#define Q1_AL  20480
#define Q1_A2H 38912
#define Q1_A2L 57344
#define Q1_CT  38912
#define Q1_BH  75776
#define Q1_BL  84992
#define Q1_B2H 94208
#define Q1_B2L 98816
#define P1_BYTES (103424 + 1024)

__global__ __launch_bounds__(128) void pass1_kernel(
    const float* __restrict__ x,
    const float* __restrict__ ln1g, const float* __restrict__ ln1b,
    const float* __restrict__ wkqv, const float* __restrict__ bkqv,
    const float* __restrict__ wrf)
{
    extern __shared__ char smem_raw[];
    char* smem = (char*)(((size_t)smem_raw + 1023) & ~(size_t)1023);
    float* cst = (float*)smem;

    const int tid  = threadIdx.x;
    const int w    = tid >> 5;
    const int lane = tid & 31;
    const int n0   = blockIdx.x * TILE;
    const int b    = n0 / L;
    const int l0   = n0 % L;

    if (tid < 64) {
        cst[16 + tid] = ln1g[tid];
        cst[80 + tid] = ln1b[tid];
    }
    for (int i = tid; i < 192; i += 128) {
        cst[144 + i] = bkqv[i];
    }
    stage_w<64>(smem + Q1_B2H, smem + Q1_B2L, wrf, 32, tid);   // wrf once

    // ---- gather token (thread = token) + LN1 ----
    const int l  = l0 + tid;
    const int dz = l / (DP * DP);
    const int hy = (l / DP) % DP;
    const int wx = l % DP;
    const float* xb = x + (size_t)b * S * S * S;
    float h[64];
    float sum = 0.0f, sq = 0.0f;
    #pragma unroll
    for (int kd = 0; kd < 4; kd++) {
        const int iz = 2 * dz - 1 + kd;
        const bool zok = (unsigned)iz < (unsigned)S;
        #pragma unroll
        for (int kh = 0; kh < 4; kh++) {
            const int iy = 2 * hy - 1 + kh;
            const bool yok = zok && ((unsigned)iy < (unsigned)S);
            #pragma unroll
            for (int kw = 0; kw < 4; kw++) {
                const int ix = 2 * wx - 1 + kw;
                const float v = (yok && (unsigned)ix < (unsigned)S)
                              ? xb[((size_t)iz * S + iy) * S + ix] : 0.0f;
                h[kd * 16 + kh * 4 + kw] = v;
                sum += v;
                sq += v * v;
            }
        }
    }
    const float mu  = sum * (1.0f / 64.0f);
    const float var = sq * (1.0f / 64.0f) - mu * mu;
    const float rs  = rsqrtf(var + 1e-5f);

    __syncthreads();   // consts visible
    #pragma unroll
    for (int f = 0; f < 64; f++) {
        h[f] = (h[f] - mu) * rs * cst[16 + f] + cst[80 + f];
    }
    store_row<64>(smem + Q1_AH, smem + Q1_AL, tid, h);

    float* ct = (float*)(smem + Q1_CT);
    const float rfscale = 0.1767766952966369f;   // 1/sqrt(32)

    for (int c = 0; c < 3; c++) {
        __syncthreads();   // prior B readers + h stores done
        stage_w<64>(smem + Q1_BH, smem + Q1_BL, wkqv + c * 4096, 64, tid);
        __syncthreads();

        float acc[2][8][4];
        #pragma unroll
        for (int mt = 0; mt < 2; mt++)
            #pragma unroll
            for (int nt = 0; nt < 8; nt++)
                #pragma unroll
                for (int i = 0; i < 4; i++) acc[mt][nt][i] = 0.0f;
        mma_tile<4, 8>(smem + Q1_AH, smem + Q1_AL, smem + Q1_BH, smem + Q1_BL,
                       acc, w, lane);
        __syncthreads();   // all mma reads done (A2/CT region free)
        store_ct<8>(ct, acc, w, lane);
        __syncthreads();

        float kq[64];
        #pragma unroll
        for (int j = 0; j < 32; j++) {
            const float2 p = *(const float2*)&ct[tid * 66 + 2 * j];
            kq[2*j]   = p.x + cst[144 + c * 64 + 2*j];
            kq[2*j+1] = p.y + cst[144 + c * 64 + 2*j + 1];
        }

        if (c < 2) {
            float xd = 0.0f;
            #pragma unroll
            for (int o = 0; o < 64; o++) xd += kq[o] * kq[o];
            xd *= 0.5f;

            __syncthreads();   // CT reads done
            store_row<64>(smem + Q1_A2H, smem + Q1_A2L, tid, kq);
            __syncthreads();

            float ac2[2][4][4];
            #pragma unroll
            for (int mt = 0; mt < 2; mt++)
                #pragma unroll
                for (int nt = 0; nt < 4; nt++)
                    #pragma unroll
                    for (int i = 0; i < 4; i++) ac2[mt][nt][i] = 0.0f;
            mma_tile<4, 4>(smem + Q1_A2H, smem + Q1_A2L,
                           smem + Q1_B2H, smem + Q1_B2L, ac2, w, lane);
            __syncthreads();   // all A2 reads done
            store_ct<4>(ct, ac2, w, lane);
            __syncthreads();

            if (c == 0) {
                #pragma unroll
                for (int j = 0; j < 16; j++) {
                    const float2 p = *(const float2*)&ct[tid * 66 + 2 * j];
                    g_kp[(size_t)(2*j)   * NTOK + n0 + tid] = __expf(p.x - xd) * rfscale;
                    g_kp[(size_t)(2*j+1) * NTOK + n0 + tid] = __expf(p.y - xd) * rfscale;
                }
            } else {
                float q[32];
                #pragma unroll
                for (int j = 0; j < 16; j++) {
                    const float2 p = *(const float2*)&ct[tid * 66 + 2 * j];
                    q[2*j]   = __expf(p.x - xd) * rfscale;
                    q[2*j+1] = __expf(p.y - xd) * rfscale;
                }
                float4* qp4 = (float4*)&g_qp[(size_t)(n0 + tid) * 32];
                #pragma unroll
                for (int j = 0; j < 8; j++) {
                    qp4[j] = make_float4(q[4*j], q[4*j+1], q[4*j+2], q[4*j+3]);
                }
            }
        } else {
            #pragma unroll
            for (int o = 0; o < 64; o++) {
                g_v[(size_t)o * NTOK + n0 + tid] = kq[o];
            }
        }
    }
}

// ============================================================================
// Reduce 1 & 2 (unchanged, deterministic)
// ============================================================================
__global__ __launch_bounds__(256) void reduce1_kernel()
{
    __shared__ float sv[64 * 65];
    __shared__ float sk[MRF * 65];

    const int b = blockIdx.y;
    const int c = blockIdx.x;
    const int t = threadIdx.x;
    const int n0 = b * L + c * 1024;

    const int e  = t >> 2;
    const int mb = (t & 3) * 8;

    float acc[8];
    #pragma unroll
    for (int i = 0; i < 8; i++) acc[i] = 0.0f;
    float ksum = 0.0f;

    for (int tile = 0; tile < 16; tile++) {
        const int base = n0 + tile * 64;
        __syncthreads();
        for (int idx = t; idx < 64 * 64; idx += 256) {
            const int ee = idx >> 6;
            const int tt = idx & 63;
            sv[ee * 65 + tt] = g_v[(size_t)ee * NTOK + base + tt];
        }
        for (int idx = t; idx < MRF * 64; idx += 256) {
            const int mm = idx >> 6;
            const int tt = idx & 63;
            sk[mm * 65 + tt] = g_kp[(size_t)mm * NTOK + base + tt];
        }
        __syncthreads();

        for (int tt = 0; tt < 64; tt++) {
            const float ve = sv[e * 65 + tt];
            #pragma unroll
            for (int i = 0; i < 8; i++) acc[i] += ve * sk[(mb + i) * 65 + tt];
        }
        if (t < MRF) {
            for (int tt = 0; tt < 64; tt++) ksum += sk[t * 65 + tt];
        }
    }

    const int slot = b * NCH + c;
    #pragma unroll
    for (int i = 0; i < 8; i++)
        g_part_kptv[slot * (64 * MRF) + e * MRF + mb + i] = acc[i];
    if (t < MRF) g_part_ksum[slot * MRF + t] = ksum;
}

__global__ __launch_bounds__(256) void reduce2_kernel()
{
    const int b = blockIdx.x;
    const int t = threadIdx.x;

    float acc[8];
    #pragma unroll
    for (int i = 0; i < 8; i++) acc[i] = 0.0f;
    for (int c = 0; c < NCH; c++) {
        const float* p = &g_part_kptv[(b * NCH + c) * (64 * MRF)];
        #pragma unroll
        for (int i = 0; i < 8; i++) acc[i] += p[t * 8 + i];
    }
    #pragma unroll
    for (int i = 0; i < 8; i++) g_kptv[b * (64 * MRF) + t * 8 + i] = acc[i];

    if (t < MRF) {
        float s = 0.0f;
        for (int c = 0; c < NCH; c++) s += g_part_ksum[(b * NCH + c) * MRF + t];
        g_ksum[b * MRF + t] = s;
    }
}

// ============================================================================
// Pass 2: ya (invD folded) + proj + skip + LN2 + MLP, thread-local epilogues
// smem: cst 0..2047; Ah 2048, Al 20480 (CT aliases 2048..35839);
//       Bh 38912, Bl 48128
// consts (float idx): bproj@16, ln2g@80, ln2b@144, bfc1@208, bfc2@272, ksum@336
// ============================================================================
#define Q2_AH 2048
#define Q2_AL 20480
#define Q2_CT 2048
#define Q2_BH 38912
#define Q2_BL 48128
#define P2_BYTES (57344 + 1024)

__global__ __launch_bounds__(128) void pass2_kernel(
    const float* __restrict__ wproj, const float* __restrict__ bproj,
    const float* __restrict__ ln2g,  const float* __restrict__ ln2b,
    const float* __restrict__ wfc1,  const float* __restrict__ bfc1,
    const float* __restrict__ wfc2,  const float* __restrict__ bfc2,
    float* __restrict__ out)
{
    extern __shared__ char smem_raw[];
    char* smem = (char*)(((size_t)smem_raw + 1023) & ~(size_t)1023);
    float* cst = (float*)smem;
    float* ct  = (float*)(smem + Q2_CT);

    const int tid  = threadIdx.x;
    const int w    = tid >> 5;
    const int lane = tid & 31;
    const int n0   = blockIdx.x * TILE;
    const int b    = n0 / L;
    const int n    = n0 + tid;

    if (tid < 64) {
        cst[16 + tid]  = bproj[tid];
        cst[80 + tid]  = ln2g[tid];
        cst[144 + tid] = ln2b[tid];
        cst[208 + tid] = bfc1[tid];
        cst[272 + tid] = bfc2[tid];
    }
    if (tid < 32) {
        cst[336 + tid] = g_ksum[b * 32 + tid];
    }
    stage_w<32>(smem + Q2_BH, smem + Q2_BL, g_kptv + b * 2048, 64, tid);

    // qp (token-major)
    float qp[32];
    {
        const float4* q4 = (const float4*)&g_qp[(size_t)n * 32];
        #pragma unroll
        for (int j = 0; j < 8; j++) {
            const float4 v = q4[j];
            qp[4*j]   = v.x;
            qp[4*j+1] = v.y;
            qp[4*j+2] = v.z;
            qp[4*j+3] = v.w;
        }
    }
    __syncthreads();   // consts visible

    {
        float D = 0.0f;
        #pragma unroll
        for (int m = 0; m < 32; m++) D += qp[m] * cst[336 + m];
        const float invD = 1.0f / (D + 1e-8f);
        #pragma unroll
        for (int m = 0; m < 32; m++) qp[m] *= invD;
    }
    store_row<32>(smem + Q2_AH, smem + Q2_AL, tid, qp);
    __syncthreads();

    // ---- GEMM 1: ya = qp' @ kptv^T  (K=32) ----
    float ya[64];
    {
        float acc[2][8][4];
        #pragma unroll
        for (int mt = 0; mt < 2; mt++)
            #pragma unroll
            for (int nt = 0; nt < 8; nt++)
                #pragma unroll
                for (int i = 0; i < 4; i++) acc[mt][nt][i] = 0.0f;
        mma_tile<2, 8>(smem + Q2_AH, smem + Q2_AL, smem + Q2_BH, smem + Q2_BL,
                       acc, w, lane);
        __syncthreads();
        store_ct<8>(ct, acc, w, lane);
        __syncthreads();
        #pragma unroll
        for (int j = 0; j < 32; j++) {
            const float2 p = *(const float2*)&ct[tid * 66 + 2 * j];
            ya[2*j]   = p.x;
            ya[2*j+1] = p.y;
        }
        __syncthreads();
    }

    // ---- GEMM 2: y = v + wproj @ ya + bproj ----
    store_row<64>(smem + Q2_AH, smem + Q2_AL, tid, ya);
    stage_w<64>(smem + Q2_BH, smem + Q2_BL, wproj, 64, tid);
    __syncthreads();
    float y[64];
    {
        float acc[2][8][4];
        #pragma unroll
        for (int mt = 0; mt < 2; mt++)
            #pragma unroll
            for (int nt = 0; nt < 8; nt++)
                #pragma unroll
                for (int i = 0; i < 4; i++) acc[mt][nt][i] = 0.0f;
        mma_tile<4, 8>(smem + Q2_AH, smem + Q2_AL, smem + Q2_BH, smem + Q2_BL,
                       acc, w, lane);
        __syncthreads();
        store_ct<8>(ct, acc, w, lane);
        __syncthreads();
        #pragma unroll
        for (int j = 0; j < 32; j++) {
            const float2 p = *(const float2*)&ct[tid * 66 + 2 * j];
            y[2*j]   = p.x + cst[16 + 2*j]   + g_v[(size_t)(2*j)   * NTOK + n];
            y[2*j+1] = p.y + cst[16 + 2*j+1] + g_v[(size_t)(2*j+1) * NTOK + n];
        }
        __syncthreads();
    }

    // ---- LN2 (thread-local) -> zn ----
    float zn[64];
    {
        float s1 = 0.0f, s2 = 0.0f;
        #pragma unroll
        for (int o = 0; o < 64; o++) {
            s1 += y[o];
            s2 += y[o] * y[o];
        }
        const float muv = s1 * (1.0f / 64.0f);
        const float var = s2 * (1.0f / 64.0f) - muv * muv;
        const float rsg = rsqrtf(var + 1e-5f);
        #pragma unroll
        for (int o = 0; o < 64; o++) {
            zn[o] = (y[o] - muv) * rsg * cst[80 + o] + cst[144 + o];
        }
    }

    // ---- GEMM 3: u = gelu(wfc1 @ zn + bfc1) ----
    store_row<64>(smem + Q2_AH, smem + Q2_AL, tid, zn);
    stage_w<64>(smem + Q2_BH, smem + Q2_BL, wfc1, 64, tid);
    __syncthreads();
    float u[64];
    {
        float acc[2][8][4];
        #pragma unroll
        for (int mt = 0; mt < 2; mt++)
            #pragma unroll
            for (int nt = 0; nt < 8; nt++)
                #pragma unroll
                for (int i = 0; i < 4; i++) acc[mt][nt][i] = 0.0f;
        mma_tile<4, 8>(smem + Q2_AH, smem + Q2_AL, smem + Q2_BH, smem + Q2_BL,
                       acc, w, lane);
        __syncthreads();
        store_ct<8>(ct, acc, w, lane);
        __syncthreads();
        #pragma unroll
        for (int j = 0; j < 32; j++) {
            const float2 p = *(const float2*)&ct[tid * 66 + 2 * j];
            const float v0 = p.x + cst[208 + 2*j];
            const float v1 = p.y + cst[208 + 2*j + 1];
            u[2*j]   = 0.5f * v0 * (1.0f + erff(v0 * 0.7071067811865476f));
            u[2*j+1] = 0.5f * v1 * (1.0f + erff(v1 * 0.7071067811865476f));
        }
        __syncthreads();
    }

    // ---- GEMM 4: out = y + wfc2 @ u + bfc2 ----
    store_row<64>(smem + Q2_AH, smem + Q2_AL, tid, u);
    stage_w<64>(smem + Q2_BH, smem + Q2_BL, wfc2, 64, tid);
    __syncthreads();
    {
        float acc[2][8][4];
        #pragma unroll
        for (int mt = 0; mt < 2; mt++)
            #pragma unroll
            for (int nt = 0; nt < 8; nt++)
                #pragma unroll
                for (int i = 0; i < 4; i++) acc[mt][nt][i] = 0.0f;
        mma_tile<4, 8>(smem + Q2_AH, smem + Q2_AL, smem + Q2_BH, smem + Q2_BL,
                       acc, w, lane);
        __syncthreads();
        store_ct<8>(ct, acc, w, lane);
        __syncthreads();
        float res[64];
        #pragma unroll
        for (int j = 0; j < 32; j++) {
            const float2 p = *(const float2*)&ct[tid * 66 + 2 * j];
            res[2*j]   = y[2*j]   + p.x + cst[272 + 2*j];
            res[2*j+1] = y[2*j+1] + p.y + cst[272 + 2*j + 1];
        }
        float4* op = (float4*)(out + (size_t)n * 64);
        #pragma unroll
        for (int j = 0; j < 16; j++) {
            op[j] = make_float4(res[4*j], res[4*j+1], res[4*j+2], res[4*j+3]);
        }
    }
}

// ============================================================================
extern "C" void kernel_launch(void* const* d_in, const int* in_sizes, int n_in,
                              void* d_out, int out_size)
{
    const float* x     = (const float*)d_in[0];
    const float* ln1g  = (const float*)d_in[1];
    const float* ln1b  = (const float*)d_in[2];
    const float* wkqv  = (const float*)d_in[3];
    const float* bkqv  = (const float*)d_in[4];
    const float* wproj = (const float*)d_in[5];
    const float* bproj = (const float*)d_in[6];
    const float* ln2g  = (const float*)d_in[7];
    const float* ln2b  = (const float*)d_in[8];
    const float* wfc1  = (const float*)d_in[9];
    const float* bfc1  = (const float*)d_in[10];
    const float* wfc2  = (const float*)d_in[11];
    const float* bfc2  = (const float*)d_in[12];
    const float* wrf   = (const float*)d_in[13];

    cudaFuncSetAttribute(pass1_kernel, cudaFuncAttributeMaxDynamicSharedMemorySize, P1_BYTES);
    cudaFuncSetAttribute(pass2_kernel, cudaFuncAttributeMaxDynamicSharedMemorySize, P2_BYTES);

    pass1_kernel<<<NBLK, 128, P1_BYTES>>>(x, ln1g, ln1b, wkqv, bkqv, wrf);
    reduce1_kernel<<<dim3(NCH, BATCH), 256>>>();
    reduce2_kernel<<<BATCH, 256>>>();
    pass2_kernel<<<NBLK, 128, P2_BYTES>>>(wproj, bproj, ln2g, ln2b,
                                          wfc1, bfc1, wfc2, bfc2, (float*)d_out);
}

// round 10
// speedup vs baseline: 1.6903x; 1.2872x over previous
#include <cuda_runtime.h>
#include <cuda_bf16.h>
#include <stdint.h>
#include <math.h>

#define BATCH 4
#define S 96
#define DP 48
#define L (DP*DP*DP)            // 110592
#define NTOK (BATCH*L)          // 442368
#define MRF 32
#define NCH 108
#define TILE 128
#define NBLK (NTOK/TILE)        // 3456

typedef unsigned int u32;

// ---------------- scratch (ALL token-major now) ----------------
__device__ float g_kp[(size_t)NTOK * MRF];        // [tok][m]
__device__ float g_qp[(size_t)NTOK * MRF];        // [tok][m]
__device__ float g_v [(size_t)NTOK * 64];         // [tok][e]
__device__ float g_part_kptv[BATCH * NCH * 64 * MRF];
__device__ float g_part_ksum[BATCH * NCH * MRF];
__device__ float g_kptv[BATCH * 64 * MRF];
__device__ float g_ksum[BATCH * MRF];

// ============================================================================
// mma.sync m16n8k16 bf16 core. A tiles [128][72] bf16, 144-B rows, no swizzle.
// ============================================================================
__device__ __forceinline__ void mma16816(float* c, const u32* a, u32 b0, u32 b1) {
    asm volatile(
        "mma.sync.aligned.m16n8k16.row.col.f32.bf16.bf16.f32 "
        "{%0,%1,%2,%3}, {%4,%5,%6,%7}, {%8,%9}, {%0,%1,%2,%3};"
        : "+f"(c[0]), "+f"(c[1]), "+f"(c[2]), "+f"(c[3])
        : "r"(a[0]), "r"(a[1]), "r"(a[2]), "r"(a[3]), "r"(b0), "r"(b1));
}

// 3-term split: Ahi*Bhi + Alo*Bhi + Ahi*Blo.
template<int KSTEPS, int NT>
__device__ __forceinline__ void mma_tile(
    const char* ah, const char* al,
    const char* bh, const char* bl,
    float (&acc)[2][NT][4], int w, int lane)
{
    const int g = lane >> 2;
    const int tig = lane & 3;
    #pragma unroll
    for (int ks = 0; ks < KSTEPS; ks++) {
        const int coff = ks * 32 + tig * 4;
        u32 Ah[2][4], Al[2][4];
        #pragma unroll
        for (int mt = 0; mt < 2; mt++) {
            const int r0 = (w * 32 + mt * 16 + g) * 144 + coff;
            const int r8 = r0 + 8 * 144;
            Ah[mt][0] = *(const u32*)(ah + r0);
            Ah[mt][1] = *(const u32*)(ah + r8);
            Ah[mt][2] = *(const u32*)(ah + r0 + 16);
            Ah[mt][3] = *(const u32*)(ah + r8 + 16);
            Al[mt][0] = *(const u32*)(al + r0);
            Al[mt][1] = *(const u32*)(al + r8);
            Al[mt][2] = *(const u32*)(al + r0 + 16);
            Al[mt][3] = *(const u32*)(al + r8 + 16);
        }
        #pragma unroll
        for (int nt = 0; nt < NT; nt++) {
            const int bo = (nt * 8 + g) * 144 + coff;
            const u32 Bh0 = *(const u32*)(bh + bo);
            const u32 Bh1 = *(const u32*)(bh + bo + 16);
            const u32 Bl0 = *(const u32*)(bl + bo);
            const u32 Bl1 = *(const u32*)(bl + bo + 16);
            #pragma unroll
            for (int mt = 0; mt < 2; mt++) {
                mma16816(acc[mt][nt], Ah[mt], Bh0, Bh1);
                mma16816(acc[mt][nt], Al[mt], Bh0, Bh1);
                mma16816(acc[mt][nt], Ah[mt], Bl0, Bl1);
            }
        }
    }
}

// quad reduction (token's 64 cols live in one lane-quad)
__device__ __forceinline__ float qsum(float v) {
    v += __shfl_xor_sync(0xffffffffu, v, 1);
    v += __shfl_xor_sync(0xffffffffu, v, 2);
    return v;
}

// -------- bf16 hi/lo split --------
__device__ __forceinline__ void split_pair(float x0, float x1, u32& hi, u32& lo) {
    __nv_bfloat16 h0 = __float2bfloat16_rn(x0);
    __nv_bfloat16 h1 = __float2bfloat16_rn(x1);
    float r0 = x0 - __bfloat162float(h0);
    float r1 = x1 - __bfloat162float(h1);
    __nv_bfloat16 l0 = __float2bfloat16_rn(r0);
    __nv_bfloat16 l1 = __float2bfloat16_rn(r1);
    __nv_bfloat162 hh = __halves2bfloat162(h0, h1);
    __nv_bfloat162 ll = __halves2bfloat162(l0, l1);
    hi = *(u32*)&hh;
    lo = *(u32*)&ll;
}

// fragment -> split A tiles (conflict-free: word addr = 36t + 4nt + tig)
template<int NT>
__device__ __forceinline__ void frag_to_A(char* ah, char* al,
                                          const float (&acc)[2][NT][4],
                                          int w, int lane) {
    const int g = lane >> 2, tig = lane & 3;
    #pragma unroll
    for (int mt = 0; mt < 2; mt++) {
        const int t0 = w * 32 + mt * 16 + g;
        #pragma unroll
        for (int nt = 0; nt < NT; nt++) {
            const int co = (nt * 8 + 2 * tig) * 2;
            u32 hi, lo;
            split_pair(acc[mt][nt][0], acc[mt][nt][1], hi, lo);
            *(u32*)(ah + t0 * 144 + co) = hi;
            *(u32*)(al + t0 * 144 + co) = lo;
            split_pair(acc[mt][nt][2], acc[mt][nt][3], hi, lo);
            *(u32*)(ah + (t0 + 8) * 144 + co) = hi;
            *(u32*)(al + (t0 + 8) * 144 + co) = lo;
        }
    }
}

// fragment -> token-major gmem (float2 per col pair)
template<int NT>
__device__ __forceinline__ void frag_to_gmem(float* dst, int C,
                                             const float (&acc)[2][NT][4],
                                             int w, int lane, int n0) {
    const int g = lane >> 2, tig = lane & 3;
    #pragma unroll
    for (int mt = 0; mt < 2; mt++) {
        const int t0 = w * 32 + mt * 16 + g;
        #pragma unroll
        for (int nt = 0; nt < NT; nt++) {
            const int col = nt * 8 + 2 * tig;
            *(float2*)&dst[(size_t)(n0 + t0) * C + col] =
                make_float2(acc[mt][nt][0], acc[mt][nt][1]);
            *(float2*)&dst[(size_t)(n0 + t0 + 8) * C + col] =
                make_float2(acc[mt][nt][2], acc[mt][nt][3]);
        }
    }
}

// add col-indexed bias (from smem) to fragments
template<int NT>
__device__ __forceinline__ void add_bias(float (&acc)[2][NT][4],
                                         const float* bias, int lane) {
    const int tig = lane & 3;
    #pragma unroll
    for (int nt = 0; nt < NT; nt++) {
        const float2 bb = *(const float2*)&bias[nt * 8 + 2 * tig];
        #pragma unroll
        for (int mt = 0; mt < 2; mt++) {
            acc[mt][nt][0] += bb.x;
            acc[mt][nt][1] += bb.y;
            acc[mt][nt][2] += bb.x;
            acc[mt][nt][3] += bb.y;
        }
    }
}

// thread=token activation store (for the gathered input h)
template<int NE>
__device__ __forceinline__ void store_row(char* ahi, char* alo, int row,
                                          const float* v) {
    #pragma unroll
    for (int ch = 0; ch < NE / 8; ch++) {
        u32 h0, l0, h1, l1, h2, l2, h3, l3;
        split_pair(v[ch*8+0], v[ch*8+1], h0, l0);
        split_pair(v[ch*8+2], v[ch*8+3], h1, l1);
        split_pair(v[ch*8+4], v[ch*8+5], h2, l2);
        split_pair(v[ch*8+6], v[ch*8+7], h3, l3);
        const int off = row * 144 + ch * 16;
        *(uint4*)(ahi + off) = make_uint4(h0, h1, h2, h3);
        *(uint4*)(alo + off) = make_uint4(l0, l1, l2, l3);
    }
}

// stage weight [rows][COLS] fp32 row-major -> split bf16 tiles (144-B rows)
template<int COLS>
__device__ __forceinline__ void stage_w(char* bhi, char* blo,
                                        const float* __restrict__ g,
                                        int rows, int tid) {
    const int PPR = COLS / 2;
    for (int p = tid; p < rows * PPR; p += 128) {
        const int o = p / PPR;
        const int kp = p % PPR;
        const float2 w = *(const float2*)(g + o * COLS + kp * 2);
        u32 hi, lo;
        split_pair(w.x, w.y, hi, lo);
        const int off = o * 144 + kp * 4;
        *(u32*)(bhi + off) = hi;
        *(u32*)(blo + off) = lo;
    }
}

// ============================================================================
// Pass 1
// ============================================================================
#define Q1_AH  2048
#define Q1_AL  20480
#define Q1_A2H 38912
#define Q1_A2L 57344
#define Q1_BH  75776
#define Q1_BL  84992
#define Q1_B2H 94208
#define Q1_B2L 98816
#define P1_BYTES (103424 + 1024)

__global__ __launch_bounds__(128, 2) void pass1_kernel(
    const float* __restrict__ x,
    const float* __restrict__ ln1g, const float* __restrict__ ln1b,
    const float* __restrict__ wkqv, const float* __restrict__ bkqv,
    const float* __restrict__ wrf)
{
    extern __shared__ char smem_raw[];
    char* smem = (char*)(((size_t)smem_raw + 1023) & ~(size_t)1023);
    float* cst = (float*)smem;   // lng@16 lnb@80 bkqv@144

    const int tid  = threadIdx.x;
    const int w    = tid >> 5;
    const int lane = tid & 31;
    const int g    = lane >> 2;
    const int tig  = lane & 3;
    const int n0   = blockIdx.x * TILE;
    const int b    = n0 / L;
    const int l0   = n0 % L;

    if (tid < 64) {
        cst[16 + tid] = ln1g[tid];
        cst[80 + tid] = ln1b[tid];
    }
    for (int i = tid; i < 192; i += 128) cst[144 + i] = bkqv[i];
    stage_w<64>(smem + Q1_B2H, smem + Q1_B2L, wrf, 32, tid);   // wrf once

    // ---- gather (thread = token) + LN1 ----
    const int l  = l0 + tid;
    const int dz = l / (DP * DP);
    const int hy = (l / DP) % DP;
    const int wx = l % DP;
    const float* xb = x + (size_t)b * S * S * S;
    float h[64];
    float sum = 0.0f, sq = 0.0f;
    #pragma unroll
    for (int kd = 0; kd < 4; kd++) {
        const int iz = 2 * dz - 1 + kd;
        const bool zok = (unsigned)iz < (unsigned)S;
        #pragma unroll
        for (int kh = 0; kh < 4; kh++) {
            const int iy = 2 * hy - 1 + kh;
            const bool yok = zok && ((unsigned)iy < (unsigned)S);
            #pragma unroll
            for (int kw = 0; kw < 4; kw++) {
                const int ix = 2 * wx - 1 + kw;
                const float v = (yok && (unsigned)ix < (unsigned)S)
                              ? xb[((size_t)iz * S + iy) * S + ix] : 0.0f;
                h[kd * 16 + kh * 4 + kw] = v;
                sum += v;
                sq += v * v;
            }
        }
    }
    const float mu  = sum * (1.0f / 64.0f);
    const float var = sq * (1.0f / 64.0f) - mu * mu;
    const float rs  = rsqrtf(var + 1e-5f);

    __syncthreads();   // cst visible
    #pragma unroll
    for (int f = 0; f < 64; f++)
        h[f] = (h[f] - mu) * rs * cst[16 + f] + cst[80 + f];
    store_row<64>(smem + Q1_AH, smem + Q1_AL, tid, h);

    const float rfscale = 0.1767766952966369f;   // 1/sqrt(32)

    for (int c = 0; c < 3; c++) {
        __syncthreads();   // h/A2 writes visible; prev iter mma reads of B/A2 done
        stage_w<64>(smem + Q1_BH, smem + Q1_BL, wkqv + c * 4096, 64, tid);
        __syncthreads();

        float acc[2][8][4];
        #pragma unroll
        for (int mt = 0; mt < 2; mt++)
            #pragma unroll
            for (int nt = 0; nt < 8; nt++)
                #pragma unroll
                for (int i = 0; i < 4; i++) acc[mt][nt][i] = 0.0f;
        mma_tile<4, 8>(smem + Q1_AH, smem + Q1_AL, smem + Q1_BH, smem + Q1_BL,
                       acc, w, lane);
        add_bias<8>(acc, &cst[144 + c * 64], lane);

        if (c < 2) {
            // xd per token (quad reduction)
            float xd[2][2];
            #pragma unroll
            for (int mt = 0; mt < 2; mt++)
                #pragma unroll
                for (int hf = 0; hf < 2; hf++) {
                    float p = 0.0f;
                    #pragma unroll
                    for (int nt = 0; nt < 8; nt++) {
                        const float v0 = acc[mt][nt][2*hf];
                        const float v1 = acc[mt][nt][2*hf + 1];
                        p += v0 * v0 + v1 * v1;
                    }
                    xd[mt][hf] = 0.5f * qsum(p);
                }

            frag_to_A<8>(smem + Q1_A2H, smem + Q1_A2L, acc, w, lane);
            __syncthreads();

            float ac2[2][4][4];
            #pragma unroll
            for (int mt = 0; mt < 2; mt++)
                #pragma unroll
                for (int nt = 0; nt < 4; nt++)
                    #pragma unroll
                    for (int i = 0; i < 4; i++) ac2[mt][nt][i] = 0.0f;
            mma_tile<4, 4>(smem + Q1_A2H, smem + Q1_A2L,
                           smem + Q1_B2H, smem + Q1_B2L, ac2, w, lane);

            float* dst = (c == 0) ? g_kp : g_qp;
            #pragma unroll
            for (int mt = 0; mt < 2; mt++) {
                const int t0 = w * 32 + mt * 16 + g;
                #pragma unroll
                for (int nt = 0; nt < 4; nt++) {
                    const int col = nt * 8 + 2 * tig;
                    *(float2*)&dst[(size_t)(n0 + t0) * 32 + col] = make_float2(
                        __expf(ac2[mt][nt][0] - xd[mt][0]) * rfscale,
                        __expf(ac2[mt][nt][1] - xd[mt][0]) * rfscale);
                    *(float2*)&dst[(size_t)(n0 + t0 + 8) * 32 + col] = make_float2(
                        __expf(ac2[mt][nt][2] - xd[mt][1]) * rfscale,
                        __expf(ac2[mt][nt][3] - xd[mt][1]) * rfscale);
                }
            }
        } else {
            frag_to_gmem<8>(g_v, 64, acc, w, lane, n0);
        }
    }
}

// ============================================================================
// Reduce 1 & 2 (token-major loads, same math)
// ============================================================================
__global__ __launch_bounds__(256) void reduce1_kernel()
{
    __shared__ float sv[64 * 65];
    __shared__ float sk[MRF * 65];

    const int b = blockIdx.y;
    const int c = blockIdx.x;
    const int t = threadIdx.x;
    const int n0 = b * L + c * 1024;

    const int e  = t >> 2;
    const int mb = (t & 3) * 8;

    float acc[8];
    #pragma unroll
    for (int i = 0; i < 8; i++) acc[i] = 0.0f;
    float ksum = 0.0f;

    for (int tile = 0; tile < 16; tile++) {
        const int base = n0 + tile * 64;
        __syncthreads();
        for (int idx = t; idx < 1024; idx += 256) {
            const int tt = idx >> 4;
            const int eq = (idx & 15) * 4;
            const float4 vv = *(const float4*)&g_v[(size_t)(base + tt) * 64 + eq];
            sv[(eq+0)*65+tt] = vv.x;
            sv[(eq+1)*65+tt] = vv.y;
            sv[(eq+2)*65+tt] = vv.z;
            sv[(eq+3)*65+tt] = vv.w;
        }
        for (int idx = t; idx < 512; idx += 256) {
            const int tt = idx >> 3;
            const int mq = (idx & 7) * 4;
            const float4 kk = *(const float4*)&g_kp[(size_t)(base + tt) * 32 + mq];
            sk[(mq+0)*65+tt] = kk.x;
            sk[(mq+1)*65+tt] = kk.y;
            sk[(mq+2)*65+tt] = kk.z;
            sk[(mq+3)*65+tt] = kk.w;
        }
        __syncthreads();

        for (int tt = 0; tt < 64; tt++) {
            const float ve = sv[e * 65 + tt];
            #pragma unroll
            for (int i = 0; i < 8; i++) acc[i] += ve * sk[(mb + i) * 65 + tt];
        }
        if (t < MRF) {
            for (int tt = 0; tt < 64; tt++) ksum += sk[t * 65 + tt];
        }
    }

    const int slot = b * NCH + c;
    #pragma unroll
    for (int i = 0; i < 8; i++)
        g_part_kptv[slot * (64 * MRF) + e * MRF + mb + i] = acc[i];
    if (t < MRF) g_part_ksum[slot * MRF + t] = ksum;
}

__global__ __launch_bounds__(256) void reduce2_kernel()
{
    const int b = blockIdx.x;
    const int t = threadIdx.x;

    float acc[8];
    #pragma unroll
    for (int i = 0; i < 8; i++) acc[i] = 0.0f;
    for (int c = 0; c < NCH; c++) {
        const float* p = &g_part_kptv[(b * NCH + c) * (64 * MRF)];
        #pragma unroll
        for (int i = 0; i < 8; i++) acc[i] += p[t * 8 + i];
    }
    #pragma unroll
    for (int i = 0; i < 8; i++) g_kptv[b * (64 * MRF) + t * 8 + i] = acc[i];

    if (t < MRF) {
        float s = 0.0f;
        for (int c = 0; c < NCH; c++) s += g_part_ksum[(b * NCH + c) * MRF + t];
        g_ksum[b * MRF + t] = s;
    }
}

// ============================================================================
// Pass 2 — fully fragment-resident epilogues
// ============================================================================
#define Q2_AH 2048
#define Q2_AL 20480
#define Q2_BH 38912
#define Q2_BL 48128
#define P2_BYTES (57344 + 1024)
// cst floats: bproj@16, ln2g@80, ln2b@144, bfc1@208, bfc2@272, ksum@336

__global__ __launch_bounds__(128, 3) void pass2_kernel(
    const float* __restrict__ wproj, const float* __restrict__ bproj,
    const float* __restrict__ ln2g,  const float* __restrict__ ln2b,
    const float* __restrict__ wfc1,  const float* __restrict__ bfc1,
    const float* __restrict__ wfc2,  const float* __restrict__ bfc2,
    float* __restrict__ out)
{
    extern __shared__ char smem_raw[];
    char* smem = (char*)(((size_t)smem_raw + 1023) & ~(size_t)1023);
    float* cst = (float*)smem;

    const int tid  = threadIdx.x;
    const int w    = tid >> 5;
    const int lane = tid & 31;
    const int g    = lane >> 2;
    const int tig  = lane & 3;
    const int n0   = blockIdx.x * TILE;
    const int b    = n0 / L;

    if (tid < 64) {
        cst[16 + tid]  = bproj[tid];
        cst[80 + tid]  = ln2g[tid];
        cst[144 + tid] = ln2b[tid];
        cst[208 + tid] = bfc1[tid];
        cst[272 + tid] = bfc2[tid];
    }
    if (tid < 32) cst[336 + tid] = g_ksum[b * 32 + tid];
    stage_w<32>(smem + Q2_BH, smem + Q2_BL, g_kptv + b * 2048, 64, tid);

    // qp fragments (token-major gmem)
    float qf[2][4][4];
    #pragma unroll
    for (int mt = 0; mt < 2; mt++) {
        const int t0 = w * 32 + mt * 16 + g;
        #pragma unroll
        for (int nt = 0; nt < 4; nt++) {
            const int col = nt * 8 + 2 * tig;
            const float2 a = *(const float2*)&g_qp[(size_t)(n0 + t0) * 32 + col];
            const float2 bb = *(const float2*)&g_qp[(size_t)(n0 + t0 + 8) * 32 + col];
            qf[mt][nt][0] = a.x;  qf[mt][nt][1] = a.y;
            qf[mt][nt][2] = bb.x; qf[mt][nt][3] = bb.y;
        }
    }
    __syncthreads();   // cst + B(kptv) visible

    // D per token; fold invD into qp
    #pragma unroll
    for (int mt = 0; mt < 2; mt++)
        #pragma unroll
        for (int hf = 0; hf < 2; hf++) {
            float p = 0.0f;
            #pragma unroll
            for (int nt = 0; nt < 4; nt++) {
                const int col = nt * 8 + 2 * tig;
                p += qf[mt][nt][2*hf]     * cst[336 + col]
                   + qf[mt][nt][2*hf + 1] * cst[336 + col + 1];
            }
            const float invD = 1.0f / (qsum(p) + 1e-8f);
            #pragma unroll
            for (int nt = 0; nt < 4; nt++) {
                qf[mt][nt][2*hf]     *= invD;
                qf[mt][nt][2*hf + 1] *= invD;
            }
        }
    frag_to_A<4>(smem + Q2_AH, smem + Q2_AL, qf, w, lane);
    __syncthreads();

    // ---- GEMM 1: ya = qp' @ kptv^T (K=32) ----
    float acc[2][8][4];
    #pragma unroll
    for (int mt = 0; mt < 2; mt++)
        #pragma unroll
        for (int nt = 0; nt < 8; nt++)
            #pragma unroll
            for (int i = 0; i < 4; i++) acc[mt][nt][i] = 0.0f;
    mma_tile<2, 8>(smem + Q2_AH, smem + Q2_AL, smem + Q2_BH, smem + Q2_BL,
                   acc, w, lane);
    __syncthreads();   // mma reads done
    stage_w<64>(smem + Q2_BH, smem + Q2_BL, wproj, 64, tid);
    frag_to_A<8>(smem + Q2_AH, smem + Q2_AL, acc, w, lane);
    __syncthreads();

    // ---- GEMM 2: y = v + wproj @ ya + bproj ----
    float y[2][8][4];
    #pragma unroll
    for (int mt = 0; mt < 2; mt++)
        #pragma unroll
        for (int nt = 0; nt < 8; nt++)
            #pragma unroll
            for (int i = 0; i < 4; i++) acc[mt][nt][i] = 0.0f;
    mma_tile<4, 8>(smem + Q2_AH, smem + Q2_AL, smem + Q2_BH, smem + Q2_BL,
                   acc, w, lane);
    add_bias<8>(acc, &cst[16], lane);
    #pragma unroll
    for (int mt = 0; mt < 2; mt++) {
        const int t0 = w * 32 + mt * 16 + g;
        #pragma unroll
        for (int nt = 0; nt < 8; nt++) {
            const int col = nt * 8 + 2 * tig;
            const float2 va = *(const float2*)&g_v[(size_t)(n0 + t0) * 64 + col];
            const float2 vb = *(const float2*)&g_v[(size_t)(n0 + t0 + 8) * 64 + col];
            y[mt][nt][0] = acc[mt][nt][0] + va.x;
            y[mt][nt][1] = acc[mt][nt][1] + va.y;
            y[mt][nt][2] = acc[mt][nt][2] + vb.x;
            y[mt][nt][3] = acc[mt][nt][3] + vb.y;
        }
    }

    // ---- LN2 stats (quad reductions) ----
    float nmu[2][2], rsg[2][2];
    #pragma unroll
    for (int mt = 0; mt < 2; mt++)
        #pragma unroll
        for (int hf = 0; hf < 2; hf++) {
            float p1 = 0.0f, p2 = 0.0f;
            #pragma unroll
            for (int nt = 0; nt < 8; nt++) {
                const float v0 = y[mt][nt][2*hf];
                const float v1 = y[mt][nt][2*hf + 1];
                p1 += v0 + v1;
                p2 += v0 * v0 + v1 * v1;
            }
            const float s1 = qsum(p1);
            const float s2 = qsum(p2);
            const float muv = s1 * (1.0f / 64.0f);
            const float var = s2 * (1.0f / 64.0f) - muv * muv;
            nmu[mt][hf] = -muv;
            rsg[mt][hf] = rsqrtf(var + 1e-5f);
        }

    __syncthreads();   // GEMM2 reads done
    stage_w<64>(smem + Q2_BH, smem + Q2_BL, wfc1, 64, tid);
    // zn -> A
    #pragma unroll
    for (int mt = 0; mt < 2; mt++) {
        const int t0 = w * 32 + mt * 16 + g;
        #pragma unroll
        for (int nt = 0; nt < 8; nt++) {
            const int col = nt * 8 + 2 * tig;
            const float2 gg = *(const float2*)&cst[80 + col];
            const float2 bb = *(const float2*)&cst[144 + col];
            const float z0 = (y[mt][nt][0] + nmu[mt][0]) * rsg[mt][0] * gg.x + bb.x;
            const float z1 = (y[mt][nt][1] + nmu[mt][0]) * rsg[mt][0] * gg.y + bb.y;
            const float z2 = (y[mt][nt][2] + nmu[mt][1]) * rsg[mt][1] * gg.x + bb.x;
            const float z3 = (y[mt][nt][3] + nmu[mt][1]) * rsg[mt][1] * gg.y + bb.y;
            u32 hi, lo;
            const int co = col * 2;
            split_pair(z0, z1, hi, lo);
            *(u32*)(smem + Q2_AH + t0 * 144 + co) = hi;
            *(u32*)(smem + Q2_AL + t0 * 144 + co) = lo;
            split_pair(z2, z3, hi, lo);
            *(u32*)(smem + Q2_AH + (t0 + 8) * 144 + co) = hi;
            *(u32*)(smem + Q2_AL + (t0 + 8) * 144 + co) = lo;
        }
    }
    __syncthreads();

    // ---- GEMM 3: u = gelu(wfc1 @ zn + bfc1) ----
    #pragma unroll
    for (int mt = 0; mt < 2; mt++)
        #pragma unroll
        for (int nt = 0; nt < 8; nt++)
            #pragma unroll
            for (int i = 0; i < 4; i++) acc[mt][nt][i] = 0.0f;
    mma_tile<4, 8>(smem + Q2_AH, smem + Q2_AL, smem + Q2_BH, smem + Q2_BL,
                   acc, w, lane);
    add_bias<8>(acc, &cst[208], lane);
    #pragma unroll
    for (int mt = 0; mt < 2; mt++)
        #pragma unroll
        for (int nt = 0; nt < 8; nt++)
            #pragma unroll
            for (int i = 0; i < 4; i++) {
                const float v = acc[mt][nt][i];
                acc[mt][nt][i] = 0.5f * v * (1.0f + erff(v * 0.7071067811865476f));
            }
    __syncthreads();   // GEMM3 reads done
    stage_w<64>(smem + Q2_BH, smem + Q2_BL, wfc2, 64, tid);
    frag_to_A<8>(smem + Q2_AH, smem + Q2_AL, acc, w, lane);
    __syncthreads();

    // ---- GEMM 4: out = y + wfc2 @ u + bfc2 ----
    #pragma unroll
    for (int mt = 0; mt < 2; mt++)
        #pragma unroll
        for (int nt = 0; nt < 8; nt++)
            #pragma unroll
            for (int i = 0; i < 4; i++) acc[mt][nt][i] = 0.0f;
    mma_tile<4, 8>(smem + Q2_AH, smem + Q2_AL, smem + Q2_BH, smem + Q2_BL,
                   acc, w, lane);
    add_bias<8>(acc, &cst[272], lane);
    #pragma unroll
    for (int mt = 0; mt < 2; mt++) {
        const int t0 = w * 32 + mt * 16 + g;
        #pragma unroll
        for (int nt = 0; nt < 8; nt++) {
            const int col = nt * 8 + 2 * tig;
            *(float2*)&out[(size_t)(n0 + t0) * 64 + col] = make_float2(
                acc[mt][nt][0] + y[mt][nt][0], acc[mt][nt][1] + y[mt][nt][1]);
            *(float2*)&out[(size_t)(n0 + t0 + 8) * 64 + col] = make_float2(
                acc[mt][nt][2] + y[mt][nt][2], acc[mt][nt][3] + y[mt][nt][3]);
        }
    }
}

// ============================================================================
extern "C" void kernel_launch(void* const* d_in, const int* in_sizes, int n_in,
                              void* d_out, int out_size)
{
    const float* x     = (const float*)d_in[0];
    const float* ln1g  = (const float*)d_in[1];
    const float* ln1b  = (const float*)d_in[2];
    const float* wkqv  = (const float*)d_in[3];
    const float* bkqv  = (const float*)d_in[4];
    const float* wproj = (const float*)d_in[5];
    const float* bproj = (const float*)d_in[6];
    const float* ln2g  = (const float*)d_in[7];
    const float* ln2b  = (const float*)d_in[8];
    const float* wfc1  = (const float*)d_in[9];
    const float* bfc1  = (const float*)d_in[10];
    const float* wfc2  = (const float*)d_in[11];
    const float* bfc2  = (const float*)d_in[12];
    const float* wrf   = (const float*)d_in[13];

    cudaFuncSetAttribute(pass1_kernel, cudaFuncAttributeMaxDynamicSharedMemorySize, P1_BYTES);
    cudaFuncSetAttribute(pass2_kernel, cudaFuncAttributeMaxDynamicSharedMemorySize, P2_BYTES);

    pass1_kernel<<<NBLK, 128, P1_BYTES>>>(x, ln1g, ln1b, wkqv, bkqv, wrf);
    reduce1_kernel<<<dim3(NCH, BATCH), 256>>>();
    reduce2_kernel<<<BATCH, 256>>>();
    pass2_kernel<<<NBLK, 128, P2_BYTES>>>(wproj, bproj, ln2g, ln2b,
                                          wfc1, bfc1, wfc2, bfc2, (float*)d_out);
}

// round 11
// speedup vs baseline: 1.7921x; 1.0602x over previous
#include <cuda_runtime.h>
#include <cuda_bf16.h>
#include <stdint.h>
#include <math.h>

#define BATCH 4
#define S 96
#define DP 48
#define L (DP*DP*DP)            // 110592
#define NTOK (BATCH*L)          // 442368
#define MRF 32
#define NCH 108
#define TILE 128
#define NBLK (NTOK/TILE)        // 3456

typedef unsigned int u32;

// ---------------- scratch (token-major) ----------------
__device__ float g_kp[(size_t)NTOK * MRF];        // [tok][m]
__device__ float g_qp[(size_t)NTOK * MRF];        // [tok][m]
__device__ float g_v [(size_t)NTOK * 64];         // [tok][e]
__device__ float g_part_kptv[BATCH * NCH * 64 * MRF];
__device__ float g_part_ksum[BATCH * NCH * MRF];
__device__ float g_ksum[BATCH * MRF];
__device__ float g_wc[2 * 32 * 64];               // fused wrf@W{k,q}  [c][m][e]
__device__ float g_bc[2 * 32];                    // fused wrf@b{k,q}
__device__ float g_wc2[BATCH * 64 * 32];          // fused wproj@kptv^T [b][j][m]

// ============================================================================
// mma.sync m16n8k16 bf16 core. A tiles [128][72] bf16, 144-B rows, no swizzle.
// ============================================================================
__device__ __forceinline__ void mma16816(float* c, const u32* a, u32 b0, u32 b1) {
    asm volatile(
        "mma.sync.aligned.m16n8k16.row.col.f32.bf16.bf16.f32 "
        "{%0,%1,%2,%3}, {%4,%5,%6,%7}, {%8,%9}, {%0,%1,%2,%3};"
        : "+f"(c[0]), "+f"(c[1]), "+f"(c[2]), "+f"(c[3])
        : "r"(a[0]), "r"(a[1]), "r"(a[2]), "r"(a[3]), "r"(b0), "r"(b1));
}

// 3-term split: Ahi*Bhi + Alo*Bhi + Ahi*Blo.
template<int KSTEPS, int NT>
__device__ __forceinline__ void mma_tile(
    const char* ah, const char* al,
    const char* bh, const char* bl,
    float (&acc)[2][NT][4], int w, int lane)
{
    const int g = lane >> 2;
    const int tig = lane & 3;
    #pragma unroll
    for (int ks = 0; ks < KSTEPS; ks++) {
        const int coff = ks * 32 + tig * 4;
        u32 Ah[2][4], Al[2][4];
        #pragma unroll
        for (int mt = 0; mt < 2; mt++) {
            const int r0 = (w * 32 + mt * 16 + g) * 144 + coff;
            const int r8 = r0 + 8 * 144;
            Ah[mt][0] = *(const u32*)(ah + r0);
            Ah[mt][1] = *(const u32*)(ah + r8);
            Ah[mt][2] = *(const u32*)(ah + r0 + 16);
            Ah[mt][3] = *(const u32*)(ah + r8 + 16);
            Al[mt][0] = *(const u32*)(al + r0);
            Al[mt][1] = *(const u32*)(al + r8);
            Al[mt][2] = *(const u32*)(al + r0 + 16);
            Al[mt][3] = *(const u32*)(al + r8 + 16);
        }
        #pragma unroll
        for (int nt = 0; nt < NT; nt++) {
            const int bo = (nt * 8 + g) * 144 + coff;
            const u32 Bh0 = *(const u32*)(bh + bo);
            const u32 Bh1 = *(const u32*)(bh + bo + 16);
            const u32 Bl0 = *(const u32*)(bl + bo);
            const u32 Bl1 = *(const u32*)(bl + bo + 16);
            #pragma unroll
            for (int mt = 0; mt < 2; mt++) {
                mma16816(acc[mt][nt], Ah[mt], Bh0, Bh1);
                mma16816(acc[mt][nt], Al[mt], Bh0, Bh1);
                mma16816(acc[mt][nt], Ah[mt], Bl0, Bl1);
            }
        }
    }
}

__device__ __forceinline__ float qsum(float v) {
    v += __shfl_xor_sync(0xffffffffu, v, 1);
    v += __shfl_xor_sync(0xffffffffu, v, 2);
    return v;
}

__device__ __forceinline__ void split_pair(float x0, float x1, u32& hi, u32& lo) {
    __nv_bfloat16 h0 = __float2bfloat16_rn(x0);
    __nv_bfloat16 h1 = __float2bfloat16_rn(x1);
    float r0 = x0 - __bfloat162float(h0);
    float r1 = x1 - __bfloat162float(h1);
    __nv_bfloat16 l0 = __float2bfloat16_rn(r0);
    __nv_bfloat16 l1 = __float2bfloat16_rn(r1);
    __nv_bfloat162 hh = __halves2bfloat162(h0, h1);
    __nv_bfloat162 ll = __halves2bfloat162(l0, l1);
    hi = *(u32*)&hh;
    lo = *(u32*)&ll;
}

template<int NT>
__device__ __forceinline__ void frag_to_A(char* ah, char* al,
                                          const float (&acc)[2][NT][4],
                                          int w, int lane) {
    const int g = lane >> 2, tig = lane & 3;
    #pragma unroll
    for (int mt = 0; mt < 2; mt++) {
        const int t0 = w * 32 + mt * 16 + g;
        #pragma unroll
        for (int nt = 0; nt < NT; nt++) {
            const int co = (nt * 8 + 2 * tig) * 2;
            u32 hi, lo;
            split_pair(acc[mt][nt][0], acc[mt][nt][1], hi, lo);
            *(u32*)(ah + t0 * 144 + co) = hi;
            *(u32*)(al + t0 * 144 + co) = lo;
            split_pair(acc[mt][nt][2], acc[mt][nt][3], hi, lo);
            *(u32*)(ah + (t0 + 8) * 144 + co) = hi;
            *(u32*)(al + (t0 + 8) * 144 + co) = lo;
        }
    }
}

template<int NT>
__device__ __forceinline__ void frag_to_gmem(float* dst, int C,
                                             const float (&acc)[2][NT][4],
                                             int w, int lane, int n0) {
    const int g = lane >> 2, tig = lane & 3;
    #pragma unroll
    for (int mt = 0; mt < 2; mt++) {
        const int t0 = w * 32 + mt * 16 + g;
        #pragma unroll
        for (int nt = 0; nt < NT; nt++) {
            const int col = nt * 8 + 2 * tig;
            *(float2*)&dst[(size_t)(n0 + t0) * C + col] =
                make_float2(acc[mt][nt][0], acc[mt][nt][1]);
            *(float2*)&dst[(size_t)(n0 + t0 + 8) * C + col] =
                make_float2(acc[mt][nt][2], acc[mt][nt][3]);
        }
    }
}

template<int NT>
__device__ __forceinline__ void add_bias(float (&acc)[2][NT][4],
                                         const float* bias, int lane) {
    const int tig = lane & 3;
    #pragma unroll
    for (int nt = 0; nt < NT; nt++) {
        const float2 bb = *(const float2*)&bias[nt * 8 + 2 * tig];
        #pragma unroll
        for (int mt = 0; mt < 2; mt++) {
            acc[mt][nt][0] += bb.x;
            acc[mt][nt][1] += bb.y;
            acc[mt][nt][2] += bb.x;
            acc[mt][nt][3] += bb.y;
        }
    }
}

template<int NE>
__device__ __forceinline__ void store_row(char* ahi, char* alo, int row,
                                          const float* v) {
    #pragma unroll
    for (int ch = 0; ch < NE / 8; ch++) {
        u32 h0, l0, h1, l1, h2, l2, h3, l3;
        split_pair(v[ch*8+0], v[ch*8+1], h0, l0);
        split_pair(v[ch*8+2], v[ch*8+3], h1, l1);
        split_pair(v[ch*8+4], v[ch*8+5], h2, l2);
        split_pair(v[ch*8+6], v[ch*8+7], h3, l3);
        const int off = row * 144 + ch * 16;
        *(uint4*)(ahi + off) = make_uint4(h0, h1, h2, h3);
        *(uint4*)(alo + off) = make_uint4(l0, l1, l2, l3);
    }
}

template<int COLS>
__device__ __forceinline__ void stage_w(char* bhi, char* blo,
                                        const float* __restrict__ g,
                                        int rows, int tid) {
    const int PPR = COLS / 2;
    for (int p = tid; p < rows * PPR; p += 128) {
        const int o = p / PPR;
        const int kp = p % PPR;
        const float2 w = *(const float2*)(g + o * COLS + kp * 2);
        u32 hi, lo;
        split_pair(w.x, w.y, hi, lo);
        const int off = o * 144 + kp * 4;
        *(u32*)(bhi + off) = hi;
        *(u32*)(blo + off) = lo;
    }
}

// ============================================================================
// Setup: fused RF weights Wc = wrf @ W{k,q}, bc = wrf @ b{k,q}   (1 block)
// ============================================================================
__global__ __launch_bounds__(256) void setup_kernel(
    const float* __restrict__ wkqv, const float* __restrict__ bkqv,
    const float* __restrict__ wrf)
{
    const int t = threadIdx.x;
    for (int i = t; i < 4096; i += 256) {
        const int c = i >> 11;
        const int m = (i >> 6) & 31;
        const int e = i & 63;
        float s = 0.0f;
        for (int d = 0; d < 64; d++)
            s += wrf[m * 64 + d] * wkqv[c * 4096 + d * 64 + e];
        g_wc[i] = s;
    }
    if (t < 64) {
        const int c = t >> 5;
        const int m = t & 31;
        float s = 0.0f;
        for (int d = 0; d < 64; d++)
            s += wrf[m * 64 + d] * bkqv[c * 64 + d];
        g_bc[t] = s;
    }
}

// ============================================================================
// Pass 1: unfold + LN1 + {k,q,v} GEMMs + fused-RF GEMMs + exp
// smem: cst 2K | AH 2048 AL 20480 | BH 38912 BL 48128 | B2H 57344 B2L 61952
// cst floats: lng@16 lnb@80 bkqv@144 bc@336
// ============================================================================
#define Q1_AH  2048
#define Q1_AL  20480
#define Q1_BH  38912
#define Q1_BL  48128
#define Q1_B2H 57344
#define Q1_B2L 61952
#define P1_BYTES (66560 + 1024)

__global__ __launch_bounds__(128, 3) void pass1_kernel(
    const float* __restrict__ x,
    const float* __restrict__ ln1g, const float* __restrict__ ln1b,
    const float* __restrict__ wkqv, const float* __restrict__ bkqv)
{
    extern __shared__ char smem_raw[];
    char* smem = (char*)(((size_t)smem_raw + 1023) & ~(size_t)1023);
    float* cst = (float*)smem;

    const int tid  = threadIdx.x;
    const int w    = tid >> 5;
    const int lane = tid & 31;
    const int g    = lane >> 2;
    const int tig  = lane & 3;
    const int n0   = blockIdx.x * TILE;
    const int b    = n0 / L;
    const int l0   = n0 % L;

    if (tid < 64) {
        cst[16 + tid]  = ln1g[tid];
        cst[80 + tid]  = ln1b[tid];
        cst[336 + tid] = g_bc[tid];
    }
    for (int i = tid; i < 192; i += 128) cst[144 + i] = bkqv[i];

    // ---- gather (thread = token) + LN1 ----
    const int l  = l0 + tid;
    const int dz = l / (DP * DP);
    const int hy = (l / DP) % DP;
    const int wx = l % DP;
    const float* xb = x + (size_t)b * S * S * S;
    float h[64];
    float sum = 0.0f, sq = 0.0f;
    #pragma unroll
    for (int kd = 0; kd < 4; kd++) {
        const int iz = 2 * dz - 1 + kd;
        const bool zok = (unsigned)iz < (unsigned)S;
        #pragma unroll
        for (int kh = 0; kh < 4; kh++) {
            const int iy = 2 * hy - 1 + kh;
            const bool yok = zok && ((unsigned)iy < (unsigned)S);
            #pragma unroll
            for (int kw = 0; kw < 4; kw++) {
                const int ix = 2 * wx - 1 + kw;
                const float v = (yok && (unsigned)ix < (unsigned)S)
                              ? xb[((size_t)iz * S + iy) * S + ix] : 0.0f;
                h[kd * 16 + kh * 4 + kw] = v;
                sum += v;
                sq += v * v;
            }
        }
    }
    const float mu  = sum * (1.0f / 64.0f);
    const float var = sq * (1.0f / 64.0f) - mu * mu;
    const float rs  = rsqrtf(var + 1e-5f);

    __syncthreads();   // cst visible
    #pragma unroll
    for (int f = 0; f < 64; f++)
        h[f] = (h[f] - mu) * rs * cst[16 + f] + cst[80 + f];
    store_row<64>(smem + Q1_AH, smem + Q1_AL, tid, h);

    const float rfscale = 0.1767766952966369f;   // 1/sqrt(32)

    for (int c = 0; c < 3; c++) {
        __syncthreads();   // h stores visible / prev mma reads of B done
        stage_w<64>(smem + Q1_BH, smem + Q1_BL, wkqv + c * 4096, 64, tid);
        if (c < 2)
            stage_w<64>(smem + Q1_B2H, smem + Q1_B2L, g_wc + c * 2048, 32, tid);
        __syncthreads();

        float acc[2][8][4];
        #pragma unroll
        for (int mt = 0; mt < 2; mt++)
            #pragma unroll
            for (int nt = 0; nt < 8; nt++)
                #pragma unroll
                for (int i = 0; i < 4; i++) acc[mt][nt][i] = 0.0f;
        mma_tile<4, 8>(smem + Q1_AH, smem + Q1_AL, smem + Q1_BH, smem + Q1_BL,
                       acc, w, lane);
        add_bias<8>(acc, &cst[144 + c * 64], lane);

        if (c < 2) {
            // xd per token
            float xd[2][2];
            #pragma unroll
            for (int mt = 0; mt < 2; mt++)
                #pragma unroll
                for (int hf = 0; hf < 2; hf++) {
                    float p = 0.0f;
                    #pragma unroll
                    for (int nt = 0; nt < 8; nt++) {
                        const float v0 = acc[mt][nt][2*hf];
                        const float v1 = acc[mt][nt][2*hf + 1];
                        p += v0 * v0 + v1 * v1;
                    }
                    xd[mt][hf] = 0.5f * qsum(p);
                }

            // wtx = Wc @ h + bc   (A tile = h, already resident!)
            float ac2[2][4][4];
            #pragma unroll
            for (int mt = 0; mt < 2; mt++)
                #pragma unroll
                for (int nt = 0; nt < 4; nt++)
                    #pragma unroll
                    for (int i = 0; i < 4; i++) ac2[mt][nt][i] = 0.0f;
            mma_tile<4, 4>(smem + Q1_AH, smem + Q1_AL,
                           smem + Q1_B2H, smem + Q1_B2L, ac2, w, lane);
            add_bias<4>(ac2, &cst[336 + c * 32], lane);

            float* dst = (c == 0) ? g_kp : g_qp;
            #pragma unroll
            for (int mt = 0; mt < 2; mt++) {
                const int t0 = w * 32 + mt * 16 + g;
                #pragma unroll
                for (int nt = 0; nt < 4; nt++) {
                    const int col = nt * 8 + 2 * tig;
                    *(float2*)&dst[(size_t)(n0 + t0) * 32 + col] = make_float2(
                        __expf(ac2[mt][nt][0] - xd[mt][0]) * rfscale,
                        __expf(ac2[mt][nt][1] - xd[mt][0]) * rfscale);
                    *(float2*)&dst[(size_t)(n0 + t0 + 8) * 32 + col] = make_float2(
                        __expf(ac2[mt][nt][2] - xd[mt][1]) * rfscale,
                        __expf(ac2[mt][nt][3] - xd[mt][1]) * rfscale);
                }
            }
        } else {
            frag_to_gmem<8>(g_v, 64, acc, w, lane, n0);
        }
    }
}

// ============================================================================
// Reduce 1 (unchanged) & Reduce 2 (+ fused Wc2 = wproj @ kptv^T)
// ============================================================================
__global__ __launch_bounds__(256) void reduce1_kernel()
{
    __shared__ float sv[64 * 65];
    __shared__ float sk[MRF * 65];

    const int b = blockIdx.y;
    const int c = blockIdx.x;
    const int t = threadIdx.x;
    const int n0 = b * L + c * 1024;

    const int e  = t >> 2;
    const int mb = (t & 3) * 8;

    float acc[8];
    #pragma unroll
    for (int i = 0; i < 8; i++) acc[i] = 0.0f;
    float ksum = 0.0f;

    for (int tile = 0; tile < 16; tile++) {
        const int base = n0 + tile * 64;
        __syncthreads();
        for (int idx = t; idx < 1024; idx += 256) {
            const int tt = idx >> 4;
            const int eq = (idx & 15) * 4;
            const float4 vv = *(const float4*)&g_v[(size_t)(base + tt) * 64 + eq];
            sv[(eq+0)*65+tt] = vv.x;
            sv[(eq+1)*65+tt] = vv.y;
            sv[(eq+2)*65+tt] = vv.z;
            sv[(eq+3)*65+tt] = vv.w;
        }
        for (int idx = t; idx < 512; idx += 256) {
            const int tt = idx >> 3;
            const int mq = (idx & 7) * 4;
            const float4 kk = *(const float4*)&g_kp[(size_t)(base + tt) * 32 + mq];
            sk[(mq+0)*65+tt] = kk.x;
            sk[(mq+1)*65+tt] = kk.y;
            sk[(mq+2)*65+tt] = kk.z;
            sk[(mq+3)*65+tt] = kk.w;
        }
        __syncthreads();

        for (int tt = 0; tt < 64; tt++) {
            const float ve = sv[e * 65 + tt];
            #pragma unroll
            for (int i = 0; i < 8; i++) acc[i] += ve * sk[(mb + i) * 65 + tt];
        }
        if (t < MRF) {
            for (int tt = 0; tt < 64; tt++) ksum += sk[t * 65 + tt];
        }
    }

    const int slot = b * NCH + c;
    #pragma unroll
    for (int i = 0; i < 8; i++)
        g_part_kptv[slot * (64 * MRF) + e * MRF + mb + i] = acc[i];
    if (t < MRF) g_part_ksum[slot * MRF + t] = ksum;
}

__global__ __launch_bounds__(256) void reduce2_kernel(
    const float* __restrict__ wproj)
{
    __shared__ float sk[2048];   // kptv [e][m]
    const int b = blockIdx.x;
    const int t = threadIdx.x;

    float acc[8];
    #pragma unroll
    for (int i = 0; i < 8; i++) acc[i] = 0.0f;
    for (int c = 0; c < NCH; c++) {
        const float* p = &g_part_kptv[(b * NCH + c) * (64 * MRF)];
        #pragma unroll
        for (int i = 0; i < 8; i++) acc[i] += p[t * 8 + i];
    }
    #pragma unroll
    for (int i = 0; i < 8; i++) sk[t * 8 + i] = acc[i];

    if (t < MRF) {
        float s = 0.0f;
        for (int c = 0; c < NCH; c++) s += g_part_ksum[(b * NCH + c) * MRF + t];
        g_ksum[b * MRF + t] = s;
    }
    __syncthreads();

    // Wc2[j][m] = sum_e wproj[j][e] * kptv[e][m]
    #pragma unroll
    for (int i = 0; i < 8; i++) {
        const int idx = t * 8 + i;
        const int j = idx >> 5;
        const int m = idx & 31;
        float s = 0.0f;
        for (int e = 0; e < 64; e++) s += wproj[j * 64 + e] * sk[e * 32 + m];
        g_wc2[b * 2048 + idx] = s;
    }
}

// ============================================================================
// Pass 2: y = Wc2@qp' + bproj + v; LN2; MLP.  3 GEMMs.
// smem: cst 2K | AH 2048 AL 20480 | BH 38912 BL 48128
// cst floats: bproj@16, ln2g@80, ln2b@144, bfc1@208, bfc2@272, ksum@336
// ============================================================================
#define Q2_AH 2048
#define Q2_AL 20480
#define Q2_BH 38912
#define Q2_BL 48128
#define P2_BYTES (57344 + 1024)

__global__ __launch_bounds__(128, 3) void pass2_kernel(
    const float* __restrict__ bproj,
    const float* __restrict__ ln2g,  const float* __restrict__ ln2b,
    const float* __restrict__ wfc1,  const float* __restrict__ bfc1,
    const float* __restrict__ wfc2,  const float* __restrict__ bfc2,
    float* __restrict__ out)
{
    extern __shared__ char smem_raw[];
    char* smem = (char*)(((size_t)smem_raw + 1023) & ~(size_t)1023);
    float* cst = (float*)smem;

    const int tid  = threadIdx.x;
    const int w    = tid >> 5;
    const int lane = tid & 31;
    const int g    = lane >> 2;
    const int tig  = lane & 3;
    const int n0   = blockIdx.x * TILE;
    const int b    = n0 / L;

    if (tid < 64) {
        cst[16 + tid]  = bproj[tid];
        cst[80 + tid]  = ln2g[tid];
        cst[144 + tid] = ln2b[tid];
        cst[208 + tid] = bfc1[tid];
        cst[272 + tid] = bfc2[tid];
    }
    if (tid < 32) cst[336 + tid] = g_ksum[b * 32 + tid];
    stage_w<32>(smem + Q2_BH, smem + Q2_BL, g_wc2 + b * 2048, 64, tid);

    // qp fragments (token-major gmem)
    float qf[2][4][4];
    #pragma unroll
    for (int mt = 0; mt < 2; mt++) {
        const int t0 = w * 32 + mt * 16 + g;
        #pragma unroll
        for (int nt = 0; nt < 4; nt++) {
            const int col = nt * 8 + 2 * tig;
            const float2 a = *(const float2*)&g_qp[(size_t)(n0 + t0) * 32 + col];
            const float2 bb = *(const float2*)&g_qp[(size_t)(n0 + t0 + 8) * 32 + col];
            qf[mt][nt][0] = a.x;  qf[mt][nt][1] = a.y;
            qf[mt][nt][2] = bb.x; qf[mt][nt][3] = bb.y;
        }
    }
    __syncthreads();   // cst + B(Wc2) visible

    // D; fold invD into qp
    #pragma unroll
    for (int mt = 0; mt < 2; mt++)
        #pragma unroll
        for (int hf = 0; hf < 2; hf++) {
            float p = 0.0f;
            #pragma unroll
            for (int nt = 0; nt < 4; nt++) {
                const int col = nt * 8 + 2 * tig;
                p += qf[mt][nt][2*hf]     * cst[336 + col]
                   + qf[mt][nt][2*hf + 1] * cst[336 + col + 1];
            }
            const float invD = 1.0f / (qsum(p) + 1e-8f);
            #pragma unroll
            for (int nt = 0; nt < 4; nt++) {
                qf[mt][nt][2*hf]     *= invD;
                qf[mt][nt][2*hf + 1] *= invD;
            }
        }
    frag_to_A<4>(smem + Q2_AH, smem + Q2_AL, qf, w, lane);
    __syncthreads();

    // ---- GEMM 1 (fused): y = Wc2 @ qp' + bproj + v ----
    float acc[2][8][4];
    #pragma unroll
    for (int mt = 0; mt < 2; mt++)
        #pragma unroll
        for (int nt = 0; nt < 8; nt++)
            #pragma unroll
            for (int i = 0; i < 4; i++) acc[mt][nt][i] = 0.0f;
    mma_tile<2, 8>(smem + Q2_AH, smem + Q2_AL, smem + Q2_BH, smem + Q2_BL,
                   acc, w, lane);
    add_bias<8>(acc, &cst[16], lane);

    float y[2][8][4];
    #pragma unroll
    for (int mt = 0; mt < 2; mt++) {
        const int t0 = w * 32 + mt * 16 + g;
        #pragma unroll
        for (int nt = 0; nt < 8; nt++) {
            const int col = nt * 8 + 2 * tig;
            const float2 va = *(const float2*)&g_v[(size_t)(n0 + t0) * 64 + col];
            const float2 vb = *(const float2*)&g_v[(size_t)(n0 + t0 + 8) * 64 + col];
            y[mt][nt][0] = acc[mt][nt][0] + va.x;
            y[mt][nt][1] = acc[mt][nt][1] + va.y;
            y[mt][nt][2] = acc[mt][nt][2] + vb.x;
            y[mt][nt][3] = acc[mt][nt][3] + vb.y;
        }
    }

    // ---- LN2 stats ----
    float nmu[2][2], rsg[2][2];
    #pragma unroll
    for (int mt = 0; mt < 2; mt++)
        #pragma unroll
        for (int hf = 0; hf < 2; hf++) {
            float p1 = 0.0f, p2 = 0.0f;
            #pragma unroll
            for (int nt = 0; nt < 8; nt++) {
                const float v0 = y[mt][nt][2*hf];
                const float v1 = y[mt][nt][2*hf + 1];
                p1 += v0 + v1;
                p2 += v0 * v0 + v1 * v1;
            }
            const float s1 = qsum(p1);
            const float s2 = qsum(p2);
            const float muv = s1 * (1.0f / 64.0f);
            const float var = s2 * (1.0f / 64.0f) - muv * muv;
            nmu[mt][hf] = -muv;
            rsg[mt][hf] = rsqrtf(var + 1e-5f);
        }

    __syncthreads();   // GEMM1 reads done
    stage_w<64>(smem + Q2_BH, smem + Q2_BL, wfc1, 64, tid);
    // zn -> A
    #pragma unroll
    for (int mt = 0; mt < 2; mt++) {
        const int t0 = w * 32 + mt * 16 + g;
        #pragma unroll
        for (int nt = 0; nt < 8; nt++) {
            const int col = nt * 8 + 2 * tig;
            const float2 gg = *(const float2*)&cst[80 + col];
            const float2 bb = *(const float2*)&cst[144 + col];
            const float z0 = (y[mt][nt][0] + nmu[mt][0]) * rsg[mt][0] * gg.x + bb.x;
            const float z1 = (y[mt][nt][1] + nmu[mt][0]) * rsg[mt][0] * gg.y + bb.y;
            const float z2 = (y[mt][nt][2] + nmu[mt][1]) * rsg[mt][1] * gg.x + bb.x;
            const float z3 = (y[mt][nt][3] + nmu[mt][1]) * rsg[mt][1] * gg.y + bb.y;
            u32 hi, lo;
            const int co = col * 2;
            split_pair(z0, z1, hi, lo);
            *(u32*)(smem + Q2_AH + t0 * 144 + co) = hi;
            *(u32*)(smem + Q2_AL + t0 * 144 + co) = lo;
            split_pair(z2, z3, hi, lo);
            *(u32*)(smem + Q2_AH + (t0 + 8) * 144 + co) = hi;
            *(u32*)(smem + Q2_AL + (t0 + 8) * 144 + co) = lo;
        }
    }
    __syncthreads();

    // ---- GEMM 2: u = gelu(wfc1 @ zn + bfc1) ----
    #pragma unroll
    for (int mt = 0; mt < 2; mt++)
        #pragma unroll
        for (int nt = 0; nt < 8; nt++)
            #pragma unroll
            for (int i = 0; i < 4; i++) acc[mt][nt][i] = 0.0f;
    mma_tile<4, 8>(smem + Q2_AH, smem + Q2_AL, smem + Q2_BH, smem + Q2_BL,
                   acc, w, lane);
    add_bias<8>(acc, &cst[208], lane);
    #pragma unroll
    for (int mt = 0; mt < 2; mt++)
        #pragma unroll
        for (int nt = 0; nt < 8; nt++)
            #pragma unroll
            for (int i = 0; i < 4; i++) {
                const float v = acc[mt][nt][i];
                acc[mt][nt][i] = 0.5f * v * (1.0f + erff(v * 0.7071067811865476f));
            }
    __syncthreads();   // GEMM2 reads done
    stage_w<64>(smem + Q2_BH, smem + Q2_BL, wfc2, 64, tid);
    frag_to_A<8>(smem + Q2_AH, smem + Q2_AL, acc, w, lane);
    __syncthreads();

    // ---- GEMM 3: out = y + wfc2 @ u + bfc2 ----
    #pragma unroll
    for (int mt = 0; mt < 2; mt++)
        #pragma unroll
        for (int nt = 0; nt < 8; nt++)
            #pragma unroll
            for (int i = 0; i < 4; i++) acc[mt][nt][i] = 0.0f;
    mma_tile<4, 8>(smem + Q2_AH, smem + Q2_AL, smem + Q2_BH, smem + Q2_BL,
                   acc, w, lane);
    add_bias<8>(acc, &cst[272], lane);
    #pragma unroll
    for (int mt = 0; mt < 2; mt++) {
        const int t0 = w * 32 + mt * 16 + g;
        #pragma unroll
        for (int nt = 0; nt < 8; nt++) {
            const int col = nt * 8 + 2 * tig;
            *(float2*)&out[(size_t)(n0 + t0) * 64 + col] = make_float2(
                acc[mt][nt][0] + y[mt][nt][0], acc[mt][nt][1] + y[mt][nt][1]);
            *(float2*)&out[(size_t)(n0 + t0 + 8) * 64 + col] = make_float2(
                acc[mt][nt][2] + y[mt][nt][2], acc[mt][nt][3] + y[mt][nt][3]);
        }
    }
}

// ============================================================================
extern "C" void kernel_launch(void* const* d_in, const int* in_sizes, int n_in,
                              void* d_out, int out_size)
{
    const float* x     = (const float*)d_in[0];
    const float* ln1g  = (const float*)d_in[1];
    const float* ln1b  = (const float*)d_in[2];
    const float* wkqv  = (const float*)d_in[3];
    const float* bkqv  = (const float*)d_in[4];
    const float* wproj = (const float*)d_in[5];
    const float* bproj = (const float*)d_in[6];
    const float* ln2g  = (const float*)d_in[7];
    const float* ln2b  = (const float*)d_in[8];
    const float* wfc1  = (const float*)d_in[9];
    const float* bfc1  = (const float*)d_in[10];
    const float* wfc2  = (const float*)d_in[11];
    const float* bfc2  = (const float*)d_in[12];
    const float* wrf   = (const float*)d_in[13];

    cudaFuncSetAttribute(pass1_kernel, cudaFuncAttributeMaxDynamicSharedMemorySize, P1_BYTES);
    cudaFuncSetAttribute(pass2_kernel, cudaFuncAttributeMaxDynamicSharedMemorySize, P2_BYTES);

    setup_kernel<<<1, 256>>>(wkqv, bkqv, wrf);
    pass1_kernel<<<NBLK, 128, P1_BYTES>>>(x, ln1g, ln1b, wkqv, bkqv);
    reduce1_kernel<<<dim3(NCH, BATCH), 256>>>();
    reduce2_kernel<<<BATCH, 256>>>(wproj);
    pass2_kernel<<<NBLK, 128, P2_BYTES>>>(bproj, ln2g, ln2b,
                                          wfc1, bfc1, wfc2, bfc2, (float*)d_out);
}

// round 12
// speedup vs baseline: 1.9318x; 1.0779x over previous
#include <cuda_runtime.h>
#include <cuda_bf16.h>
#include <stdint.h>
#include <math.h>

#define BATCH 4
#define S 96
#define DP 48
#define L (DP*DP*DP)            // 110592
#define NTOK (BATCH*L)          // 442368
#define MRF 32
#define NCH 108
#define TILE 128
#define NBLK (NTOK/TILE)        // 3456

typedef unsigned int u32;

// ---------------- scratch (token-major) ----------------
__device__ float g_kp[(size_t)NTOK * MRF];        // [tok][m]
__device__ float g_qp[(size_t)NTOK * MRF];        // [tok][m]
__device__ float g_v [(size_t)NTOK * 64];         // [tok][e]
__device__ float g_part_kptv[BATCH * NCH * 64 * MRF];
__device__ float g_part_ksum[BATCH * NCH * MRF];
__device__ float g_kptv[BATCH * 64 * MRF];        // [b][e][m]
__device__ float g_ksum[BATCH * MRF];
__device__ float g_wc[2 * 32 * 64];               // fused wrf@W{k,q}  [c][m][e]
__device__ float g_bc[2 * 32];                    // fused wrf@b{k,q}
__device__ float g_wc2[BATCH * 64 * 32];          // fused wproj@kptv^T [b][j][m]

// ============================================================================
// mma.sync m16n8k16 bf16 core. A tiles [128][72] bf16, 144-B rows, no swizzle.
// ============================================================================
__device__ __forceinline__ void mma16816(float* c, const u32* a, u32 b0, u32 b1) {
    asm volatile(
        "mma.sync.aligned.m16n8k16.row.col.f32.bf16.bf16.f32 "
        "{%0,%1,%2,%3}, {%4,%5,%6,%7}, {%8,%9}, {%0,%1,%2,%3};"
        : "+f"(c[0]), "+f"(c[1]), "+f"(c[2]), "+f"(c[3])
        : "r"(a[0]), "r"(a[1]), "r"(a[2]), "r"(a[3]), "r"(b0), "r"(b1));
}

// 3-term split: Ahi*Bhi + Alo*Bhi + Ahi*Blo.
template<int KSTEPS, int NT>
__device__ __forceinline__ void mma_tile(
    const char* ah, const char* al,
    const char* bh, const char* bl,
    float (&acc)[2][NT][4], int w, int lane)
{
    const int g = lane >> 2;
    const int tig = lane & 3;
    #pragma unroll
    for (int ks = 0; ks < KSTEPS; ks++) {
        const int coff = ks * 32 + tig * 4;
        u32 Ah[2][4], Al[2][4];
        #pragma unroll
        for (int mt = 0; mt < 2; mt++) {
            const int r0 = (w * 32 + mt * 16 + g) * 144 + coff;
            const int r8 = r0 + 8 * 144;
            Ah[mt][0] = *(const u32*)(ah + r0);
            Ah[mt][1] = *(const u32*)(ah + r8);
            Ah[mt][2] = *(const u32*)(ah + r0 + 16);
            Ah[mt][3] = *(const u32*)(ah + r8 + 16);
            Al[mt][0] = *(const u32*)(al + r0);
            Al[mt][1] = *(const u32*)(al + r8);
            Al[mt][2] = *(const u32*)(al + r0 + 16);
            Al[mt][3] = *(const u32*)(al + r8 + 16);
        }
        #pragma unroll
        for (int nt = 0; nt < NT; nt++) {
            const int bo = (nt * 8 + g) * 144 + coff;
            const u32 Bh0 = *(const u32*)(bh + bo);
            const u32 Bh1 = *(const u32*)(bh + bo + 16);
            const u32 Bl0 = *(const u32*)(bl + bo);
            const u32 Bl1 = *(const u32*)(bl + bo + 16);
            #pragma unroll
            for (int mt = 0; mt < 2; mt++) {
                mma16816(acc[mt][nt], Ah[mt], Bh0, Bh1);
                mma16816(acc[mt][nt], Al[mt], Bh0, Bh1);
                mma16816(acc[mt][nt], Ah[mt], Bl0, Bl1);
            }
        }
    }
}

__device__ __forceinline__ float qsum(float v) {
    v += __shfl_xor_sync(0xffffffffu, v, 1);
    v += __shfl_xor_sync(0xffffffffu, v, 2);
    return v;
}

__device__ __forceinline__ void split_pair(float x0, float x1, u32& hi, u32& lo) {
    __nv_bfloat16 h0 = __float2bfloat16_rn(x0);
    __nv_bfloat16 h1 = __float2bfloat16_rn(x1);
    float r0 = x0 - __bfloat162float(h0);
    float r1 = x1 - __bfloat162float(h1);
    __nv_bfloat16 l0 = __float2bfloat16_rn(r0);
    __nv_bfloat16 l1 = __float2bfloat16_rn(r1);
    __nv_bfloat162 hh = __halves2bfloat162(h0, h1);
    __nv_bfloat162 ll = __halves2bfloat162(l0, l1);
    hi = *(u32*)&hh;
    lo = *(u32*)&ll;
}

template<int NT>
__device__ __forceinline__ void frag_to_A(char* ah, char* al,
                                          const float (&acc)[2][NT][4],
                                          int w, int lane) {
    const int g = lane >> 2, tig = lane & 3;
    #pragma unroll
    for (int mt = 0; mt < 2; mt++) {
        const int t0 = w * 32 + mt * 16 + g;
        #pragma unroll
        for (int nt = 0; nt < NT; nt++) {
            const int co = (nt * 8 + 2 * tig) * 2;
            u32 hi, lo;
            split_pair(acc[mt][nt][0], acc[mt][nt][1], hi, lo);
            *(u32*)(ah + t0 * 144 + co) = hi;
            *(u32*)(al + t0 * 144 + co) = lo;
            split_pair(acc[mt][nt][2], acc[mt][nt][3], hi, lo);
            *(u32*)(ah + (t0 + 8) * 144 + co) = hi;
            *(u32*)(al + (t0 + 8) * 144 + co) = lo;
        }
    }
}

template<int NT>
__device__ __forceinline__ void frag_to_gmem(float* dst, int C,
                                             const float (&acc)[2][NT][4],
                                             int w, int lane, int n0) {
    const int g = lane >> 2, tig = lane & 3;
    #pragma unroll
    for (int mt = 0; mt < 2; mt++) {
        const int t0 = w * 32 + mt * 16 + g;
        #pragma unroll
        for (int nt = 0; nt < NT; nt++) {
            const int col = nt * 8 + 2 * tig;
            *(float2*)&dst[(size_t)(n0 + t0) * C + col] =
                make_float2(acc[mt][nt][0], acc[mt][nt][1]);
            *(float2*)&dst[(size_t)(n0 + t0 + 8) * C + col] =
                make_float2(acc[mt][nt][2], acc[mt][nt][3]);
        }
    }
}

template<int NT>
__device__ __forceinline__ void add_bias(float (&acc)[2][NT][4],
                                         const float* bias, int lane) {
    const int tig = lane & 3;
    #pragma unroll
    for (int nt = 0; nt < NT; nt++) {
        const float2 bb = *(const float2*)&bias[nt * 8 + 2 * tig];
        #pragma unroll
        for (int mt = 0; mt < 2; mt++) {
            acc[mt][nt][0] += bb.x;
            acc[mt][nt][1] += bb.y;
            acc[mt][nt][2] += bb.x;
            acc[mt][nt][3] += bb.y;
        }
    }
}

template<int NE>
__device__ __forceinline__ void store_row(char* ahi, char* alo, int row,
                                          const float* v) {
    #pragma unroll
    for (int ch = 0; ch < NE / 8; ch++) {
        u32 h0, l0, h1, l1, h2, l2, h3, l3;
        split_pair(v[ch*8+0], v[ch*8+1], h0, l0);
        split_pair(v[ch*8+2], v[ch*8+3], h1, l1);
        split_pair(v[ch*8+4], v[ch*8+5], h2, l2);
        split_pair(v[ch*8+6], v[ch*8+7], h3, l3);
        const int off = row * 144 + ch * 16;
        *(uint4*)(ahi + off) = make_uint4(h0, h1, h2, h3);
        *(uint4*)(alo + off) = make_uint4(l0, l1, l2, l3);
    }
}

template<int COLS>
__device__ __forceinline__ void stage_w(char* bhi, char* blo,
                                        const float* __restrict__ g,
                                        int rows, int tid) {
    const int PPR = COLS / 2;
    for (int p = tid; p < rows * PPR; p += 128) {
        const int o = p / PPR;
        const int kp = p % PPR;
        const float2 w = *(const float2*)(g + o * COLS + kp * 2);
        u32 hi, lo;
        split_pair(w.x, w.y, hi, lo);
        const int off = o * 144 + kp * 4;
        *(u32*)(bhi + off) = hi;
        *(u32*)(blo + off) = lo;
    }
}

// ============================================================================
// Setup (grid 16): Wc = wrf @ W{k,q}, bc = wrf @ b{k,q}
// ============================================================================
__global__ __launch_bounds__(256) void setup_kernel(
    const float* __restrict__ wkqv, const float* __restrict__ bkqv,
    const float* __restrict__ wrf)
{
    const int i = blockIdx.x * 256 + threadIdx.x;   // 0..4095
    const int c = i >> 11;
    const int m = (i >> 6) & 31;
    const int e = i & 63;
    float s = 0.0f;
    #pragma unroll 8
    for (int d = 0; d < 64; d++)
        s += wrf[m * 64 + d] * wkqv[c * 4096 + d * 64 + e];
    g_wc[i] = s;

    if (blockIdx.x == 0 && threadIdx.x < 64) {
        const int cc = threadIdx.x >> 5;
        const int mm = threadIdx.x & 31;
        float sb = 0.0f;
        #pragma unroll 8
        for (int d = 0; d < 64; d++)
            sb += wrf[mm * 64 + d] * bkqv[cc * 64 + d];
        g_bc[threadIdx.x] = sb;
    }
}

// ============================================================================
// Pass 1 (unchanged from R10 winner)
// ============================================================================
#define Q1_AH  2048
#define Q1_AL  20480
#define Q1_BH  38912
#define Q1_BL  48128
#define Q1_B2H 57344
#define Q1_B2L 61952
#define P1_BYTES (66560 + 1024)

__global__ __launch_bounds__(128, 3) void pass1_kernel(
    const float* __restrict__ x,
    const float* __restrict__ ln1g, const float* __restrict__ ln1b,
    const float* __restrict__ wkqv, const float* __restrict__ bkqv)
{
    extern __shared__ char smem_raw[];
    char* smem = (char*)(((size_t)smem_raw + 1023) & ~(size_t)1023);
    float* cst = (float*)smem;

    const int tid  = threadIdx.x;
    const int w    = tid >> 5;
    const int lane = tid & 31;
    const int g    = lane >> 2;
    const int tig  = lane & 3;
    const int n0   = blockIdx.x * TILE;
    const int b    = n0 / L;
    const int l0   = n0 % L;

    if (tid < 64) {
        cst[16 + tid]  = ln1g[tid];
        cst[80 + tid]  = ln1b[tid];
        cst[336 + tid] = g_bc[tid];
    }
    for (int i = tid; i < 192; i += 128) cst[144 + i] = bkqv[i];

    const int l  = l0 + tid;
    const int dz = l / (DP * DP);
    const int hy = (l / DP) % DP;
    const int wx = l % DP;
    const float* xb = x + (size_t)b * S * S * S;
    float h[64];
    float sum = 0.0f, sq = 0.0f;
    #pragma unroll
    for (int kd = 0; kd < 4; kd++) {
        const int iz = 2 * dz - 1 + kd;
        const bool zok = (unsigned)iz < (unsigned)S;
        #pragma unroll
        for (int kh = 0; kh < 4; kh++) {
            const int iy = 2 * hy - 1 + kh;
            const bool yok = zok && ((unsigned)iy < (unsigned)S);
            #pragma unroll
            for (int kw = 0; kw < 4; kw++) {
                const int ix = 2 * wx - 1 + kw;
                const float v = (yok && (unsigned)ix < (unsigned)S)
                              ? xb[((size_t)iz * S + iy) * S + ix] : 0.0f;
                h[kd * 16 + kh * 4 + kw] = v;
                sum += v;
                sq += v * v;
            }
        }
    }
    const float mu  = sum * (1.0f / 64.0f);
    const float var = sq * (1.0f / 64.0f) - mu * mu;
    const float rs  = rsqrtf(var + 1e-5f);

    __syncthreads();
    #pragma unroll
    for (int f = 0; f < 64; f++)
        h[f] = (h[f] - mu) * rs * cst[16 + f] + cst[80 + f];
    store_row<64>(smem + Q1_AH, smem + Q1_AL, tid, h);

    const float rfscale = 0.1767766952966369f;

    for (int c = 0; c < 3; c++) {
        __syncthreads();
        stage_w<64>(smem + Q1_BH, smem + Q1_BL, wkqv + c * 4096, 64, tid);
        if (c < 2)
            stage_w<64>(smem + Q1_B2H, smem + Q1_B2L, g_wc + c * 2048, 32, tid);
        __syncthreads();

        float acc[2][8][4];
        #pragma unroll
        for (int mt = 0; mt < 2; mt++)
            #pragma unroll
            for (int nt = 0; nt < 8; nt++)
                #pragma unroll
                for (int i = 0; i < 4; i++) acc[mt][nt][i] = 0.0f;
        mma_tile<4, 8>(smem + Q1_AH, smem + Q1_AL, smem + Q1_BH, smem + Q1_BL,
                       acc, w, lane);
        add_bias<8>(acc, &cst[144 + c * 64], lane);

        if (c < 2) {
            float xd[2][2];
            #pragma unroll
            for (int mt = 0; mt < 2; mt++)
                #pragma unroll
                for (int hf = 0; hf < 2; hf++) {
                    float p = 0.0f;
                    #pragma unroll
                    for (int nt = 0; nt < 8; nt++) {
                        const float v0 = acc[mt][nt][2*hf];
                        const float v1 = acc[mt][nt][2*hf + 1];
                        p += v0 * v0 + v1 * v1;
                    }
                    xd[mt][hf] = 0.5f * qsum(p);
                }

            float ac2[2][4][4];
            #pragma unroll
            for (int mt = 0; mt < 2; mt++)
                #pragma unroll
                for (int nt = 0; nt < 4; nt++)
                    #pragma unroll
                    for (int i = 0; i < 4; i++) ac2[mt][nt][i] = 0.0f;
            mma_tile<4, 4>(smem + Q1_AH, smem + Q1_AL,
                           smem + Q1_B2H, smem + Q1_B2L, ac2, w, lane);
            add_bias<4>(ac2, &cst[336 + c * 32], lane);

            float* dst = (c == 0) ? g_kp : g_qp;
            #pragma unroll
            for (int mt = 0; mt < 2; mt++) {
                const int t0 = w * 32 + mt * 16 + g;
                #pragma unroll
                for (int nt = 0; nt < 4; nt++) {
                    const int col = nt * 8 + 2 * tig;
                    *(float2*)&dst[(size_t)(n0 + t0) * 32 + col] = make_float2(
                        __expf(ac2[mt][nt][0] - xd[mt][0]) * rfscale,
                        __expf(ac2[mt][nt][1] - xd[mt][0]) * rfscale);
                    *(float2*)&dst[(size_t)(n0 + t0 + 8) * 32 + col] = make_float2(
                        __expf(ac2[mt][nt][2] - xd[mt][1]) * rfscale,
                        __expf(ac2[mt][nt][3] - xd[mt][1]) * rfscale);
                }
            }
        } else {
            frag_to_gmem<8>(g_v, 64, acc, w, lane, n0);
        }
    }
}

// ============================================================================
// Reduce 1 (unchanged)
// ============================================================================
__global__ __launch_bounds__(256) void reduce1_kernel()
{
    __shared__ float sv[64 * 65];
    __shared__ float sk[MRF * 65];

    const int b = blockIdx.y;
    const int c = blockIdx.x;
    const int t = threadIdx.x;
    const int n0 = b * L + c * 1024;

    const int e  = t >> 2;
    const int mb = (t & 3) * 8;

    float acc[8];
    #pragma unroll
    for (int i = 0; i < 8; i++) acc[i] = 0.0f;
    float ksum = 0.0f;

    for (int tile = 0; tile < 16; tile++) {
        const int base = n0 + tile * 64;
        __syncthreads();
        for (int idx = t; idx < 1024; idx += 256) {
            const int tt = idx >> 4;
            const int eq = (idx & 15) * 4;
            const float4 vv = *(const float4*)&g_v[(size_t)(base + tt) * 64 + eq];
            sv[(eq+0)*65+tt] = vv.x;
            sv[(eq+1)*65+tt] = vv.y;
            sv[(eq+2)*65+tt] = vv.z;
            sv[(eq+3)*65+tt] = vv.w;
        }
        for (int idx = t; idx < 512; idx += 256) {
            const int tt = idx >> 3;
            const int mq = (idx & 7) * 4;
            const float4 kk = *(const float4*)&g_kp[(size_t)(base + tt) * 32 + mq];
            sk[(mq+0)*65+tt] = kk.x;
            sk[(mq+1)*65+tt] = kk.y;
            sk[(mq+2)*65+tt] = kk.z;
            sk[(mq+3)*65+tt] = kk.w;
        }
        __syncthreads();

        for (int tt = 0; tt < 64; tt++) {
            const float ve = sv[e * 65 + tt];
            #pragma unroll
            for (int i = 0; i < 8; i++) acc[i] += ve * sk[(mb + i) * 65 + tt];
        }
        if (t < MRF) {
            for (int tt = 0; tt < 64; tt++) ksum += sk[t * 65 + tt];
        }
    }

    const int slot = b * NCH + c;
    #pragma unroll
    for (int i = 0; i < 8; i++)
        g_part_kptv[slot * (64 * MRF) + e * MRF + mb + i] = acc[i];
    if (t < MRF) g_part_ksum[slot * MRF + t] = ksum;
}

// ============================================================================
// Reduce 2a (grid BATCH x 8): finalize kptv + ksum
// ============================================================================
__global__ __launch_bounds__(256) void reduce2a_kernel()
{
    const int b = blockIdx.y;
    const int j = blockIdx.x;
    const int t = threadIdx.x;
    const int idx = j * 256 + t;          // 0..2047

    float acc = 0.0f;
    const float* p = &g_part_kptv[b * NCH * 2048 + idx];
    #pragma unroll 4
    for (int c = 0; c < NCH; c++) acc += p[(size_t)c * 2048];
    g_kptv[b * 2048 + idx] = acc;

    if (j == 0 && t < MRF) {
        float s = 0.0f;
        const float* q = &g_part_ksum[b * NCH * MRF + t];
        #pragma unroll 4
        for (int c = 0; c < NCH; c++) s += q[(size_t)c * MRF];
        g_ksum[b * MRF + t] = s;
    }
}

// ============================================================================
// Wc2 (grid BATCH x 8): Wc2[j][m] = sum_e wproj[j][e] * kptv[e][m]
// ============================================================================
__global__ __launch_bounds__(256) void wc2_kernel(const float* __restrict__ wproj)
{
    const int b = blockIdx.y;
    const int idx = blockIdx.x * 256 + threadIdx.x;   // 0..2047
    const int j = idx >> 5;
    const int m = idx & 31;
    float s = 0.0f;
    #pragma unroll 8
    for (int e = 0; e < 64; e++)
        s += wproj[j * 64 + e] * g_kptv[b * 2048 + e * 32 + m];
    g_wc2[b * 2048 + idx] = s;
}

// ============================================================================
// Pass 2 (unchanged from R10 winner)
// ============================================================================
#define Q2_AH 2048
#define Q2_AL 20480
#define Q2_BH 38912
#define Q2_BL 48128
#define P2_BYTES (57344 + 1024)

__global__ __launch_bounds__(128, 3) void pass2_kernel(
    const float* __restrict__ bproj,
    const float* __restrict__ ln2g,  const float* __restrict__ ln2b,
    const float* __restrict__ wfc1,  const float* __restrict__ bfc1,
    const float* __restrict__ wfc2,  const float* __restrict__ bfc2,
    float* __restrict__ out)
{
    extern __shared__ char smem_raw[];
    char* smem = (char*)(((size_t)smem_raw + 1023) & ~(size_t)1023);
    float* cst = (float*)smem;

    const int tid  = threadIdx.x;
    const int w    = tid >> 5;
    const int lane = tid & 31;
    const int g    = lane >> 2;
    const int tig  = lane & 3;
    const int n0   = blockIdx.x * TILE;
    const int b    = n0 / L;

    if (tid < 64) {
        cst[16 + tid]  = bproj[tid];
        cst[80 + tid]  = ln2g[tid];
        cst[144 + tid] = ln2b[tid];
        cst[208 + tid] = bfc1[tid];
        cst[272 + tid] = bfc2[tid];
    }
    if (tid < 32) cst[336 + tid] = g_ksum[b * 32 + tid];
    stage_w<32>(smem + Q2_BH, smem + Q2_BL, g_wc2 + b * 2048, 64, tid);

    float qf[2][4][4];
    #pragma unroll
    for (int mt = 0; mt < 2; mt++) {
        const int t0 = w * 32 + mt * 16 + g;
        #pragma unroll
        for (int nt = 0; nt < 4; nt++) {
            const int col = nt * 8 + 2 * tig;
            const float2 a = *(const float2*)&g_qp[(size_t)(n0 + t0) * 32 + col];
            const float2 bb = *(const float2*)&g_qp[(size_t)(n0 + t0 + 8) * 32 + col];
            qf[mt][nt][0] = a.x;  qf[mt][nt][1] = a.y;
            qf[mt][nt][2] = bb.x; qf[mt][nt][3] = bb.y;
        }
    }
    __syncthreads();

    #pragma unroll
    for (int mt = 0; mt < 2; mt++)
        #pragma unroll
        for (int hf = 0; hf < 2; hf++) {
            float p = 0.0f;
            #pragma unroll
            for (int nt = 0; nt < 4; nt++) {
                const int col = nt * 8 + 2 * tig;
                p += qf[mt][nt][2*hf]     * cst[336 + col]
                   + qf[mt][nt][2*hf + 1] * cst[336 + col + 1];
            }
            const float invD = 1.0f / (qsum(p) + 1e-8f);
            #pragma unroll
            for (int nt = 0; nt < 4; nt++) {
                qf[mt][nt][2*hf]     *= invD;
                qf[mt][nt][2*hf + 1] *= invD;
            }
        }
    frag_to_A<4>(smem + Q2_AH, smem + Q2_AL, qf, w, lane);
    __syncthreads();

    float acc[2][8][4];
    #pragma unroll
    for (int mt = 0; mt < 2; mt++)
        #pragma unroll
        for (int nt = 0; nt < 8; nt++)
            #pragma unroll
            for (int i = 0; i < 4; i++) acc[mt][nt][i] = 0.0f;
    mma_tile<2, 8>(smem + Q2_AH, smem + Q2_AL, smem + Q2_BH, smem + Q2_BL,
                   acc, w, lane);
    add_bias<8>(acc, &cst[16], lane);

    float y[2][8][4];
    #pragma unroll
    for (int mt = 0; mt < 2; mt++) {
        const int t0 = w * 32 + mt * 16 + g;
        #pragma unroll
        for (int nt = 0; nt < 8; nt++) {
            const int col = nt * 8 + 2 * tig;
            const float2 va = *(const float2*)&g_v[(size_t)(n0 + t0) * 64 + col];
            const float2 vb = *(const float2*)&g_v[(size_t)(n0 + t0 + 8) * 64 + col];
            y[mt][nt][0] = acc[mt][nt][0] + va.x;
            y[mt][nt][1] = acc[mt][nt][1] + va.y;
            y[mt][nt][2] = acc[mt][nt][2] + vb.x;
            y[mt][nt][3] = acc[mt][nt][3] + vb.y;
        }
    }

    float nmu[2][2], rsg[2][2];
    #pragma unroll
    for (int mt = 0; mt < 2; mt++)
        #pragma unroll
        for (int hf = 0; hf < 2; hf++) {
            float p1 = 0.0f, p2 = 0.0f;
            #pragma unroll
            for (int nt = 0; nt < 8; nt++) {
                const float v0 = y[mt][nt][2*hf];
                const float v1 = y[mt][nt][2*hf + 1];
                p1 += v0 + v1;
                p2 += v0 * v0 + v1 * v1;
            }
            const float s1 = qsum(p1);
            const float s2 = qsum(p2);
            const float muv = s1 * (1.0f / 64.0f);
            const float var = s2 * (1.0f / 64.0f) - muv * muv;
            nmu[mt][hf] = -muv;
            rsg[mt][hf] = rsqrtf(var + 1e-5f);
        }

    __syncthreads();
    stage_w<64>(smem + Q2_BH, smem + Q2_BL, wfc1, 64, tid);
    #pragma unroll
    for (int mt = 0; mt < 2; mt++) {
        const int t0 = w * 32 + mt * 16 + g;
        #pragma unroll
        for (int nt = 0; nt < 8; nt++) {
            const int col = nt * 8 + 2 * tig;
            const float2 gg = *(const float2*)&cst[80 + col];
            const float2 bb = *(const float2*)&cst[144 + col];
            const float z0 = (y[mt][nt][0] + nmu[mt][0]) * rsg[mt][0] * gg.x + bb.x;
            const float z1 = (y[mt][nt][1] + nmu[mt][0]) * rsg[mt][0] * gg.y + bb.y;
            const float z2 = (y[mt][nt][2] + nmu[mt][1]) * rsg[mt][1] * gg.x + bb.x;
            const float z3 = (y[mt][nt][3] + nmu[mt][1]) * rsg[mt][1] * gg.y + bb.y;
            u32 hi, lo;
            const int co = col * 2;
            split_pair(z0, z1, hi, lo);
            *(u32*)(smem + Q2_AH + t0 * 144 + co) = hi;
            *(u32*)(smem + Q2_AL + t0 * 144 + co) = lo;
            split_pair(z2, z3, hi, lo);
            *(u32*)(smem + Q2_AH + (t0 + 8) * 144 + co) = hi;
            *(u32*)(smem + Q2_AL + (t0 + 8) * 144 + co) = lo;
        }
    }
    __syncthreads();

    #pragma unroll
    for (int mt = 0; mt < 2; mt++)
        #pragma unroll
        for (int nt = 0; nt < 8; nt++)
            #pragma unroll
            for (int i = 0; i < 4; i++) acc[mt][nt][i] = 0.0f;
    mma_tile<4, 8>(smem + Q2_AH, smem + Q2_AL, smem + Q2_BH, smem + Q2_BL,
                   acc, w, lane);
    add_bias<8>(acc, &cst[208], lane);
    #pragma unroll
    for (int mt = 0; mt < 2; mt++)
        #pragma unroll
        for (int nt = 0; nt < 8; nt++)
            #pragma unroll
            for (int i = 0; i < 4; i++) {
                const float v = acc[mt][nt][i];
                acc[mt][nt][i] = 0.5f * v * (1.0f + erff(v * 0.7071067811865476f));
            }
    __syncthreads();
    stage_w<64>(smem + Q2_BH, smem + Q2_BL, wfc2, 64, tid);
    frag_to_A<8>(smem + Q2_AH, smem + Q2_AL, acc, w, lane);
    __syncthreads();

    #pragma unroll
    for (int mt = 0; mt < 2; mt++)
        #pragma unroll
        for (int nt = 0; nt < 8; nt++)
            #pragma unroll
            for (int i = 0; i < 4; i++) acc[mt][nt][i] = 0.0f;
    mma_tile<4, 8>(smem + Q2_AH, smem + Q2_AL, smem + Q2_BH, smem + Q2_BL,
                   acc, w, lane);
    add_bias<8>(acc, &cst[272], lane);
    #pragma unroll
    for (int mt = 0; mt < 2; mt++) {
        const int t0 = w * 32 + mt * 16 + g;
        #pragma unroll
        for (int nt = 0; nt < 8; nt++) {
            const int col = nt * 8 + 2 * tig;
            *(float2*)&out[(size_t)(n0 + t0) * 64 + col] = make_float2(
                acc[mt][nt][0] + y[mt][nt][0], acc[mt][nt][1] + y[mt][nt][1]);
            *(float2*)&out[(size_t)(n0 + t0 + 8) * 64 + col] = make_float2(
                acc[mt][nt][2] + y[mt][nt][2], acc[mt][nt][3] + y[mt][nt][3]);
        }
    }
}

// ============================================================================
extern "C" void kernel_launch(void* const* d_in, const int* in_sizes, int n_in,
                              void* d_out, int out_size)
{
    const float* x     = (const float*)d_in[0];
    const float* ln1g  = (const float*)d_in[1];
    const float* ln1b  = (const float*)d_in[2];
    const float* wkqv  = (const float*)d_in[3];
    const float* bkqv  = (const float*)d_in[4];
    const float* wproj = (const float*)d_in[5];
    const float* bproj = (const float*)d_in[6];
    const float* ln2g  = (const float*)d_in[7];
    const float* ln2b  = (const float*)d_in[8];
    const float* wfc1  = (const float*)d_in[9];
    const float* bfc1  = (const float*)d_in[10];
    const float* wfc2  = (const float*)d_in[11];
    const float* bfc2  = (const float*)d_in[12];
    const float* wrf   = (const float*)d_in[13];

    cudaFuncSetAttribute(pass1_kernel, cudaFuncAttributeMaxDynamicSharedMemorySize, P1_BYTES);
    cudaFuncSetAttribute(pass2_kernel, cudaFuncAttributeMaxDynamicSharedMemorySize, P2_BYTES);

    setup_kernel<<<16, 256>>>(wkqv, bkqv, wrf);
    pass1_kernel<<<NBLK, 128, P1_BYTES>>>(x, ln1g, ln1b, wkqv, bkqv);
    reduce1_kernel<<<dim3(NCH, BATCH), 256>>>();
    reduce2a_kernel<<<dim3(8, BATCH), 256>>>();
    wc2_kernel<<<dim3(8, BATCH), 256>>>(wproj);
    pass2_kernel<<<NBLK, 128, P2_BYTES>>>(bproj, ln2g, ln2b,
                                          wfc1, bfc1, wfc2, bfc2, (float*)d_out);
}

// round 13
// speedup vs baseline: 2.0316x; 1.0517x over previous
#include <cuda_runtime.h>
#include <cuda_bf16.h>
#include <stdint.h>
#include <math.h>

#define BATCH 4
#define S 96
#define DP 48
#define L (DP*DP*DP)            // 110592
#define NTOK (BATCH*L)          // 442368
#define MRF 32
#define NCH 108
#define TILE 128
#define NBLK (NTOK/TILE)        // 3456

typedef unsigned int u32;

// ---------------- scratch (token-major) ----------------
__device__ float g_kp[(size_t)NTOK * MRF];        // [tok][m]
__device__ float g_qp[(size_t)NTOK * MRF];        // [tok][m]
__device__ float g_v [(size_t)NTOK * 64];         // [tok][e]
__device__ float g_part_kptv[BATCH * NCH * 64 * MRF];
__device__ float g_part_ksum[BATCH * NCH * MRF];
__device__ float g_kptv[BATCH * 64 * MRF];        // [b][e][m]
__device__ float g_ksum[BATCH * MRF];
__device__ float g_wc[2 * 32 * 64];               // fused wrf@W{k,q}  [c][m][e]
__device__ float g_bc[2 * 32];                    // fused wrf@b{k,q}

// pre-split bf16 weight tiles, 144-B rows (36 u32/row), uint4-aligned
__device__ uint4 g_wkh[3 * 64 * 9], g_wkl[3 * 64 * 9];   // wkqv k/q/v
__device__ uint4 g_wch[2 * 32 * 9], g_wcl[2 * 32 * 9];   // fused RF (32 rows)
__device__ uint4 g_f1h[64 * 9],     g_f1l[64 * 9];       // wfc1
__device__ uint4 g_f2h[64 * 9],     g_f2l[64 * 9];       // wfc2
__device__ uint4 g_w2h[BATCH * 64 * 9], g_w2l[BATCH * 64 * 9];  // fused wproj@kptv^T

// ============================================================================
// mma.sync m16n8k16 bf16 core. A tiles [128][72] bf16, 144-B rows, no swizzle.
// ============================================================================
__device__ __forceinline__ void mma16816(float* c, const u32* a, u32 b0, u32 b1) {
    asm volatile(
        "mma.sync.aligned.m16n8k16.row.col.f32.bf16.bf16.f32 "
        "{%0,%1,%2,%3}, {%4,%5,%6,%7}, {%8,%9}, {%0,%1,%2,%3};"
        : "+f"(c[0]), "+f"(c[1]), "+f"(c[2]), "+f"(c[3])
        : "r"(a[0]), "r"(a[1]), "r"(a[2]), "r"(a[3]), "r"(b0), "r"(b1));
}

// 3-term split: Ahi*Bhi + Alo*Bhi + Ahi*Blo.
template<int KSTEPS, int NT>
__device__ __forceinline__ void mma_tile(
    const char* ah, const char* al,
    const char* bh, const char* bl,
    float (&acc)[2][NT][4], int w, int lane)
{
    const int g = lane >> 2;
    const int tig = lane & 3;
    #pragma unroll
    for (int ks = 0; ks < KSTEPS; ks++) {
        const int coff = ks * 32 + tig * 4;
        u32 Ah[2][4], Al[2][4];
        #pragma unroll
        for (int mt = 0; mt < 2; mt++) {
            const int r0 = (w * 32 + mt * 16 + g) * 144 + coff;
            const int r8 = r0 + 8 * 144;
            Ah[mt][0] = *(const u32*)(ah + r0);
            Ah[mt][1] = *(const u32*)(ah + r8);
            Ah[mt][2] = *(const u32*)(ah + r0 + 16);
            Ah[mt][3] = *(const u32*)(ah + r8 + 16);
            Al[mt][0] = *(const u32*)(al + r0);
            Al[mt][1] = *(const u32*)(al + r8);
            Al[mt][2] = *(const u32*)(al + r0 + 16);
            Al[mt][3] = *(const u32*)(al + r8 + 16);
        }
        #pragma unroll
        for (int nt = 0; nt < NT; nt++) {
            const int bo = (nt * 8 + g) * 144 + coff;
            const u32 Bh0 = *(const u32*)(bh + bo);
            const u32 Bh1 = *(const u32*)(bh + bo + 16);
            const u32 Bl0 = *(const u32*)(bl + bo);
            const u32 Bl1 = *(const u32*)(bl + bo + 16);
            #pragma unroll
            for (int mt = 0; mt < 2; mt++) {
                mma16816(acc[mt][nt], Ah[mt], Bh0, Bh1);
                mma16816(acc[mt][nt], Al[mt], Bh0, Bh1);
                mma16816(acc[mt][nt], Ah[mt], Bl0, Bl1);
            }
        }
    }
}

__device__ __forceinline__ float qsum(float v) {
    v += __shfl_xor_sync(0xffffffffu, v, 1);
    v += __shfl_xor_sync(0xffffffffu, v, 2);
    return v;
}

__device__ __forceinline__ void split_pair(float x0, float x1, u32& hi, u32& lo) {
    __nv_bfloat16 h0 = __float2bfloat16_rn(x0);
    __nv_bfloat16 h1 = __float2bfloat16_rn(x1);
    float r0 = x0 - __bfloat162float(h0);
    float r1 = x1 - __bfloat162float(h1);
    __nv_bfloat16 l0 = __float2bfloat16_rn(r0);
    __nv_bfloat16 l1 = __float2bfloat16_rn(r1);
    __nv_bfloat162 hh = __halves2bfloat162(h0, h1);
    __nv_bfloat162 ll = __halves2bfloat162(l0, l1);
    hi = *(u32*)&hh;
    lo = *(u32*)&ll;
}

template<int NT>
__device__ __forceinline__ void frag_to_A(char* ah, char* al,
                                          const float (&acc)[2][NT][4],
                                          int w, int lane) {
    const int g = lane >> 2, tig = lane & 3;
    #pragma unroll
    for (int mt = 0; mt < 2; mt++) {
        const int t0 = w * 32 + mt * 16 + g;
        #pragma unroll
        for (int nt = 0; nt < NT; nt++) {
            const int co = (nt * 8 + 2 * tig) * 2;
            u32 hi, lo;
            split_pair(acc[mt][nt][0], acc[mt][nt][1], hi, lo);
            *(u32*)(ah + t0 * 144 + co) = hi;
            *(u32*)(al + t0 * 144 + co) = lo;
            split_pair(acc[mt][nt][2], acc[mt][nt][3], hi, lo);
            *(u32*)(ah + (t0 + 8) * 144 + co) = hi;
            *(u32*)(al + (t0 + 8) * 144 + co) = lo;
        }
    }
}

template<int NT>
__device__ __forceinline__ void frag_to_gmem(float* dst, int C,
                                             const float (&acc)[2][NT][4],
                                             int w, int lane, int n0) {
    const int g = lane >> 2, tig = lane & 3;
    #pragma unroll
    for (int mt = 0; mt < 2; mt++) {
        const int t0 = w * 32 + mt * 16 + g;
        #pragma unroll
        for (int nt = 0; nt < NT; nt++) {
            const int col = nt * 8 + 2 * tig;
            *(float2*)&dst[(size_t)(n0 + t0) * C + col] =
                make_float2(acc[mt][nt][0], acc[mt][nt][1]);
            *(float2*)&dst[(size_t)(n0 + t0 + 8) * C + col] =
                make_float2(acc[mt][nt][2], acc[mt][nt][3]);
        }
    }
}

template<int NT>
__device__ __forceinline__ void add_bias(float (&acc)[2][NT][4],
                                         const float* bias, int lane) {
    const int tig = lane & 3;
    #pragma unroll
    for (int nt = 0; nt < NT; nt++) {
        const float2 bb = *(const float2*)&bias[nt * 8 + 2 * tig];
        #pragma unroll
        for (int mt = 0; mt < 2; mt++) {
            acc[mt][nt][0] += bb.x;
            acc[mt][nt][1] += bb.y;
            acc[mt][nt][2] += bb.x;
            acc[mt][nt][3] += bb.y;
        }
    }
}

template<int NE>
__device__ __forceinline__ void store_row(char* ahi, char* alo, int row,
                                          const float* v) {
    #pragma unroll
    for (int ch = 0; ch < NE / 8; ch++) {
        u32 h0, l0, h1, l1, h2, l2, h3, l3;
        split_pair(v[ch*8+0], v[ch*8+1], h0, l0);
        split_pair(v[ch*8+2], v[ch*8+3], h1, l1);
        split_pair(v[ch*8+4], v[ch*8+5], h2, l2);
        split_pair(v[ch*8+6], v[ch*8+7], h3, l3);
        const int off = row * 144 + ch * 16;
        *(uint4*)(ahi + off) = make_uint4(h0, h1, h2, h3);
        *(uint4*)(alo + off) = make_uint4(l0, l1, l2, l3);
    }
}

// copy pre-split tile (rows*9 uint4 each for hi/lo) gmem -> smem
__device__ __forceinline__ void stage_pre(char* dh, char* dl,
                                          const uint4* __restrict__ gh,
                                          const uint4* __restrict__ gl,
                                          int rows, int tid) {
    uint4* sh = (uint4*)dh;
    uint4* sl = (uint4*)dl;
    const int n = rows * 9;
    for (int p = tid; p < n; p += 128) {
        sh[p] = gh[p];
        sl[p] = gl[p];
    }
}

// ============================================================================
// Setup 1 (grid 16): Wc = wrf @ W{k,q}, bc = wrf @ b{k,q}
// ============================================================================
__global__ __launch_bounds__(256) void setup_kernel(
    const float* __restrict__ wkqv, const float* __restrict__ bkqv,
    const float* __restrict__ wrf)
{
    const int i = blockIdx.x * 256 + threadIdx.x;   // 0..4095
    const int c = i >> 11;
    const int m = (i >> 6) & 31;
    const int e = i & 63;
    float s = 0.0f;
    #pragma unroll 8
    for (int d = 0; d < 64; d++)
        s += wrf[m * 64 + d] * wkqv[c * 4096 + d * 64 + e];
    g_wc[i] = s;

    if (blockIdx.x == 0 && threadIdx.x < 64) {
        const int cc = threadIdx.x >> 5;
        const int mm = threadIdx.x & 31;
        float sb = 0.0f;
        #pragma unroll 8
        for (int d = 0; d < 64; d++)
            sb += wrf[mm * 64 + d] * bkqv[cc * 64 + d];
        g_bc[threadIdx.x] = sb;
    }
}

// ============================================================================
// Setup 2 (grid 54): pre-split all static weights into 144-B-row tiles
// flat idx: [0,6912) wkqv | [6912,9216) wfc1 | [9216,11520) wfc2 | [11520,13824) wc
// each idx = (row-global * 36 + word), word<32 => pair, word>=32 => pad 0
// ============================================================================
__global__ __launch_bounds__(256) void setup_split_kernel(
    const float* __restrict__ wkqv,
    const float* __restrict__ wfc1, const float* __restrict__ wfc2)
{
    const int i = blockIdx.x * 256 + threadIdx.x;
    if (i >= 13824) return;
    const int word = i % 36;
    const int rowg = i / 36;

    const float* src = 0;
    u32* dsth = 0;
    u32* dstl = 0;
    int row = 0, cols = 64;
    if (i < 6912) {               // wkqv: rowg in [0,192)
        src = wkqv; row = rowg;
        dsth = (u32*)g_wkh; dstl = (u32*)g_wkl;
    } else if (i < 9216) {        // wfc1
        src = wfc1; row = rowg - 192;
        dsth = (u32*)g_f1h; dstl = (u32*)g_f1l;
    } else if (i < 11520) {       // wfc2
        src = wfc2; row = rowg - 256;
        dsth = (u32*)g_f2h; dstl = (u32*)g_f2l;
    } else {                      // wc: rows 0..63 across both c
        src = g_wc; row = rowg - 320;
        dsth = (u32*)g_wch; dstl = (u32*)g_wcl;
    }

    u32 hi = 0, lo = 0;
    if (word < 32) {
        const float2 wv = *(const float2*)(src + row * cols + word * 2);
        split_pair(wv.x, wv.y, hi, lo);
    }
    dsth[row * 36 + word] = hi;
    dstl[row * 36 + word] = lo;
}

// ============================================================================
// Pass 1 (GEMM logic unchanged; staging now pre-split copies)
// ============================================================================
#define Q1_AH  2048
#define Q1_AL  20480
#define Q1_BH  38912
#define Q1_BL  48128
#define Q1_B2H 57344
#define Q1_B2L 61952
#define P1_BYTES (66560 + 1024)

__global__ __launch_bounds__(128, 3) void pass1_kernel(
    const float* __restrict__ x,
    const float* __restrict__ ln1g, const float* __restrict__ ln1b,
    const float* __restrict__ bkqv)
{
    extern __shared__ char smem_raw[];
    char* smem = (char*)(((size_t)smem_raw + 1023) & ~(size_t)1023);
    float* cst = (float*)smem;

    const int tid  = threadIdx.x;
    const int w    = tid >> 5;
    const int lane = tid & 31;
    const int g    = lane >> 2;
    const int tig  = lane & 3;
    const int n0   = blockIdx.x * TILE;
    const int b    = n0 / L;
    const int l0   = n0 % L;

    if (tid < 64) {
        cst[16 + tid]  = ln1g[tid];
        cst[80 + tid]  = ln1b[tid];
        cst[336 + tid] = g_bc[tid];
    }
    for (int i = tid; i < 192; i += 128) cst[144 + i] = bkqv[i];

    const int l  = l0 + tid;
    const int dz = l / (DP * DP);
    const int hy = (l / DP) % DP;
    const int wx = l % DP;
    const float* xb = x + (size_t)b * S * S * S;
    float h[64];
    float sum = 0.0f, sq = 0.0f;
    #pragma unroll
    for (int kd = 0; kd < 4; kd++) {
        const int iz = 2 * dz - 1 + kd;
        const bool zok = (unsigned)iz < (unsigned)S;
        #pragma unroll
        for (int kh = 0; kh < 4; kh++) {
            const int iy = 2 * hy - 1 + kh;
            const bool yok = zok && ((unsigned)iy < (unsigned)S);
            #pragma unroll
            for (int kw = 0; kw < 4; kw++) {
                const int ix = 2 * wx - 1 + kw;
                const float v = (yok && (unsigned)ix < (unsigned)S)
                              ? xb[((size_t)iz * S + iy) * S + ix] : 0.0f;
                h[kd * 16 + kh * 4 + kw] = v;
                sum += v;
                sq += v * v;
            }
        }
    }
    const float mu  = sum * (1.0f / 64.0f);
    const float var = sq * (1.0f / 64.0f) - mu * mu;
    const float rs  = rsqrtf(var + 1e-5f);

    __syncthreads();
    #pragma unroll
    for (int f = 0; f < 64; f++)
        h[f] = (h[f] - mu) * rs * cst[16 + f] + cst[80 + f];
    store_row<64>(smem + Q1_AH, smem + Q1_AL, tid, h);

    const float rfscale = 0.1767766952966369f;

    for (int c = 0; c < 3; c++) {
        __syncthreads();
        stage_pre(smem + Q1_BH, smem + Q1_BL, g_wkh + c * 576, g_wkl + c * 576,
                  64, tid);
        if (c < 2)
            stage_pre(smem + Q1_B2H, smem + Q1_B2L, g_wch + c * 288,
                      g_wcl + c * 288, 32, tid);
        __syncthreads();

        float acc[2][8][4];
        #pragma unroll
        for (int mt = 0; mt < 2; mt++)
            #pragma unroll
            for (int nt = 0; nt < 8; nt++)
                #pragma unroll
                for (int i = 0; i < 4; i++) acc[mt][nt][i] = 0.0f;
        mma_tile<4, 8>(smem + Q1_AH, smem + Q1_AL, smem + Q1_BH, smem + Q1_BL,
                       acc, w, lane);
        add_bias<8>(acc, &cst[144 + c * 64], lane);

        if (c < 2) {
            float xd[2][2];
            #pragma unroll
            for (int mt = 0; mt < 2; mt++)
                #pragma unroll
                for (int hf = 0; hf < 2; hf++) {
                    float p = 0.0f;
                    #pragma unroll
                    for (int nt = 0; nt < 8; nt++) {
                        const float v0 = acc[mt][nt][2*hf];
                        const float v1 = acc[mt][nt][2*hf + 1];
                        p += v0 * v0 + v1 * v1;
                    }
                    xd[mt][hf] = 0.5f * qsum(p);
                }

            float ac2[2][4][4];
            #pragma unroll
            for (int mt = 0; mt < 2; mt++)
                #pragma unroll
                for (int nt = 0; nt < 4; nt++)
                    #pragma unroll
                    for (int i = 0; i < 4; i++) ac2[mt][nt][i] = 0.0f;
            mma_tile<4, 4>(smem + Q1_AH, smem + Q1_AL,
                           smem + Q1_B2H, smem + Q1_B2L, ac2, w, lane);
            add_bias<4>(ac2, &cst[336 + c * 32], lane);

            float* dst = (c == 0) ? g_kp : g_qp;
            #pragma unroll
            for (int mt = 0; mt < 2; mt++) {
                const int t0 = w * 32 + mt * 16 + g;
                #pragma unroll
                for (int nt = 0; nt < 4; nt++) {
                    const int col = nt * 8 + 2 * tig;
                    *(float2*)&dst[(size_t)(n0 + t0) * 32 + col] = make_float2(
                        __expf(ac2[mt][nt][0] - xd[mt][0]) * rfscale,
                        __expf(ac2[mt][nt][1] - xd[mt][0]) * rfscale);
                    *(float2*)&dst[(size_t)(n0 + t0 + 8) * 32 + col] = make_float2(
                        __expf(ac2[mt][nt][2] - xd[mt][1]) * rfscale,
                        __expf(ac2[mt][nt][3] - xd[mt][1]) * rfscale);
                }
            }
        } else {
            frag_to_gmem<8>(g_v, 64, acc, w, lane, n0);
        }
    }
}

// ============================================================================
// Reduce 1 (unchanged)
// ============================================================================
__global__ __launch_bounds__(256) void reduce1_kernel()
{
    __shared__ float sv[64 * 65];
    __shared__ float sk[MRF * 65];

    const int b = blockIdx.y;
    const int c = blockIdx.x;
    const int t = threadIdx.x;
    const int n0 = b * L + c * 1024;

    const int e  = t >> 2;
    const int mb = (t & 3) * 8;

    float acc[8];
    #pragma unroll
    for (int i = 0; i < 8; i++) acc[i] = 0.0f;
    float ksum = 0.0f;

    for (int tile = 0; tile < 16; tile++) {
        const int base = n0 + tile * 64;
        __syncthreads();
        for (int idx = t; idx < 1024; idx += 256) {
            const int tt = idx >> 4;
            const int eq = (idx & 15) * 4;
            const float4 vv = *(const float4*)&g_v[(size_t)(base + tt) * 64 + eq];
            sv[(eq+0)*65+tt] = vv.x;
            sv[(eq+1)*65+tt] = vv.y;
            sv[(eq+2)*65+tt] = vv.z;
            sv[(eq+3)*65+tt] = vv.w;
        }
        for (int idx = t; idx < 512; idx += 256) {
            const int tt = idx >> 3;
            const int mq = (idx & 7) * 4;
            const float4 kk = *(const float4*)&g_kp[(size_t)(base + tt) * 32 + mq];
            sk[(mq+0)*65+tt] = kk.x;
            sk[(mq+1)*65+tt] = kk.y;
            sk[(mq+2)*65+tt] = kk.z;
            sk[(mq+3)*65+tt] = kk.w;
        }
        __syncthreads();

        for (int tt = 0; tt < 64; tt++) {
            const float ve = sv[e * 65 + tt];
            #pragma unroll
            for (int i = 0; i < 8; i++) acc[i] += ve * sk[(mb + i) * 65 + tt];
        }
        if (t < MRF) {
            for (int tt = 0; tt < 64; tt++) ksum += sk[t * 65 + tt];
        }
    }

    const int slot = b * NCH + c;
    #pragma unroll
    for (int i = 0; i < 8; i++)
        g_part_kptv[slot * (64 * MRF) + e * MRF + mb + i] = acc[i];
    if (t < MRF) g_part_ksum[slot * MRF + t] = ksum;
}

// ============================================================================
// Reduce 2a (grid 32 x BATCH): chunk-parallel finalize kptv + ksum
// thread (e4, part): sums chunks part, part+4, ... then quad shuffle-reduce
// ============================================================================
__global__ __launch_bounds__(256) void reduce2a_kernel()
{
    const int b = blockIdx.y;
    const int t = threadIdx.x;
    const int e4   = t >> 2;              // 0..63
    const int part = t & 3;
    const int idx  = blockIdx.x * 64 + e4;   // 0..2047

    float acc = 0.0f;
    const float* p = &g_part_kptv[b * NCH * 2048 + idx];
    for (int c = part; c < NCH; c += 4) acc += p[(size_t)c * 2048];
    acc += __shfl_xor_sync(0xffffffffu, acc, 1);
    acc += __shfl_xor_sync(0xffffffffu, acc, 2);
    if (part == 0) g_kptv[b * 2048 + idx] = acc;

    if (blockIdx.x == 0 && t < 128) {
        const int m = t >> 2;             // 0..31
        float s = 0.0f;
        const float* q = &g_part_ksum[b * NCH * MRF + m];
        for (int c = part; c < NCH; c += 4) s += q[(size_t)c * MRF];
        s += __shfl_xor_sync(0xffffffffu, s, 1);
        s += __shfl_xor_sync(0xffffffffu, s, 2);
        if (part == 0) g_ksum[b * MRF + m] = s;
    }
}

// ============================================================================
// Wc2 (grid 9 x BATCH): Wc2[j][m] = sum_e wproj[j][e]*kptv[e][m], split output
// ============================================================================
__global__ __launch_bounds__(256) void wc2_kernel(const float* __restrict__ wproj)
{
    const int b = blockIdx.y;
    const int i = blockIdx.x * 256 + threadIdx.x;
    if (i >= 2304) return;
    const int j = i / 36;
    const int word = i % 36;

    u32 hi = 0, lo = 0;
    if (word < 32) {
        const int m = word * 2;
        float s0 = 0.0f, s1 = 0.0f;
        #pragma unroll 8
        for (int e = 0; e < 64; e++) {
            const float wp = wproj[j * 64 + e];
            s0 += wp * g_kptv[b * 2048 + e * 32 + m];
            s1 += wp * g_kptv[b * 2048 + e * 32 + m + 1];
        }
        split_pair(s0, s1, hi, lo);
    }
    ((u32*)g_w2h)[b * 2304 + j * 36 + word] = hi;
    ((u32*)g_w2l)[b * 2304 + j * 36 + word] = lo;
}

// ============================================================================
// Pass 2 (GEMM logic unchanged; staging now pre-split copies)
// ============================================================================
#define Q2_AH 2048
#define Q2_AL 20480
#define Q2_BH 38912
#define Q2_BL 48128
#define P2_BYTES (57344 + 1024)

__global__ __launch_bounds__(128, 3) void pass2_kernel(
    const float* __restrict__ bproj,
    const float* __restrict__ ln2g,  const float* __restrict__ ln2b,
    const float* __restrict__ bfc1,  const float* __restrict__ bfc2,
    float* __restrict__ out)
{
    extern __shared__ char smem_raw[];
    char* smem = (char*)(((size_t)smem_raw + 1023) & ~(size_t)1023);
    float* cst = (float*)smem;

    const int tid  = threadIdx.x;
    const int w    = tid >> 5;
    const int lane = tid & 31;
    const int g    = lane >> 2;
    const int tig  = lane & 3;
    const int n0   = blockIdx.x * TILE;
    const int b    = n0 / L;

    if (tid < 64) {
        cst[16 + tid]  = bproj[tid];
        cst[80 + tid]  = ln2g[tid];
        cst[144 + tid] = ln2b[tid];
        cst[208 + tid] = bfc1[tid];
        cst[272 + tid] = bfc2[tid];
    }
    if (tid < 32) cst[336 + tid] = g_ksum[b * 32 + tid];
    stage_pre(smem + Q2_BH, smem + Q2_BL, g_w2h + b * 576, g_w2l + b * 576,
              64, tid);

    float qf[2][4][4];
    #pragma unroll
    for (int mt = 0; mt < 2; mt++) {
        const int t0 = w * 32 + mt * 16 + g;
        #pragma unroll
        for (int nt = 0; nt < 4; nt++) {
            const int col = nt * 8 + 2 * tig;
            const float2 a = *(const float2*)&g_qp[(size_t)(n0 + t0) * 32 + col];
            const float2 bb = *(const float2*)&g_qp[(size_t)(n0 + t0 + 8) * 32 + col];
            qf[mt][nt][0] = a.x;  qf[mt][nt][1] = a.y;
            qf[mt][nt][2] = bb.x; qf[mt][nt][3] = bb.y;
        }
    }
    __syncthreads();

    #pragma unroll
    for (int mt = 0; mt < 2; mt++)
        #pragma unroll
        for (int hf = 0; hf < 2; hf++) {
            float p = 0.0f;
            #pragma unroll
            for (int nt = 0; nt < 4; nt++) {
                const int col = nt * 8 + 2 * tig;
                p += qf[mt][nt][2*hf]     * cst[336 + col]
                   + qf[mt][nt][2*hf + 1] * cst[336 + col + 1];
            }
            const float invD = 1.0f / (qsum(p) + 1e-8f);
            #pragma unroll
            for (int nt = 0; nt < 4; nt++) {
                qf[mt][nt][2*hf]     *= invD;
                qf[mt][nt][2*hf + 1] *= invD;
            }
        }
    frag_to_A<4>(smem + Q2_AH, smem + Q2_AL, qf, w, lane);
    __syncthreads();

    float acc[2][8][4];
    #pragma unroll
    for (int mt = 0; mt < 2; mt++)
        #pragma unroll
        for (int nt = 0; nt < 8; nt++)
            #pragma unroll
            for (int i = 0; i < 4; i++) acc[mt][nt][i] = 0.0f;
    mma_tile<2, 8>(smem + Q2_AH, smem + Q2_AL, smem + Q2_BH, smem + Q2_BL,
                   acc, w, lane);
    add_bias<8>(acc, &cst[16], lane);

    float y[2][8][4];
    #pragma unroll
    for (int mt = 0; mt < 2; mt++) {
        const int t0 = w * 32 + mt * 16 + g;
        #pragma unroll
        for (int nt = 0; nt < 8; nt++) {
            const int col = nt * 8 + 2 * tig;
            const float2 va = *(const float2*)&g_v[(size_t)(n0 + t0) * 64 + col];
            const float2 vb = *(const float2*)&g_v[(size_t)(n0 + t0 + 8) * 64 + col];
            y[mt][nt][0] = acc[mt][nt][0] + va.x;
            y[mt][nt][1] = acc[mt][nt][1] + va.y;
            y[mt][nt][2] = acc[mt][nt][2] + vb.x;
            y[mt][nt][3] = acc[mt][nt][3] + vb.y;
        }
    }

    float nmu[2][2], rsg[2][2];
    #pragma unroll
    for (int mt = 0; mt < 2; mt++)
        #pragma unroll
        for (int hf = 0; hf < 2; hf++) {
            float p1 = 0.0f, p2 = 0.0f;
            #pragma unroll
            for (int nt = 0; nt < 8; nt++) {
                const float v0 = y[mt][nt][2*hf];
                const float v1 = y[mt][nt][2*hf + 1];
                p1 += v0 + v1;
                p2 += v0 * v0 + v1 * v1;
            }
            const float s1 = qsum(p1);
            const float s2 = qsum(p2);
            const float muv = s1 * (1.0f / 64.0f);
            const float var = s2 * (1.0f / 64.0f) - muv * muv;
            nmu[mt][hf] = -muv;
            rsg[mt][hf] = rsqrtf(var + 1e-5f);
        }

    __syncthreads();
    stage_pre(smem + Q2_BH, smem + Q2_BL, g_f1h, g_f1l, 64, tid);
    #pragma unroll
    for (int mt = 0; mt < 2; mt++) {
        const int t0 = w * 32 + mt * 16 + g;
        #pragma unroll
        for (int nt = 0; nt < 8; nt++) {
            const int col = nt * 8 + 2 * tig;
            const float2 gg = *(const float2*)&cst[80 + col];
            const float2 bb = *(const float2*)&cst[144 + col];
            const float z0 = (y[mt][nt][0] + nmu[mt][0]) * rsg[mt][0] * gg.x + bb.x;
            const float z1 = (y[mt][nt][1] + nmu[mt][0]) * rsg[mt][0] * gg.y + bb.y;
            const float z2 = (y[mt][nt][2] + nmu[mt][1]) * rsg[mt][1] * gg.x + bb.x;
            const float z3 = (y[mt][nt][3] + nmu[mt][1]) * rsg[mt][1] * gg.y + bb.y;
            u32 hi, lo;
            const int co = col * 2;
            split_pair(z0, z1, hi, lo);
            *(u32*)(smem + Q2_AH + t0 * 144 + co) = hi;
            *(u32*)(smem + Q2_AL + t0 * 144 + co) = lo;
            split_pair(z2, z3, hi, lo);
            *(u32*)(smem + Q2_AH + (t0 + 8) * 144 + co) = hi;
            *(u32*)(smem + Q2_AL + (t0 + 8) * 144 + co) = lo;
        }
    }
    __syncthreads();

    #pragma unroll
    for (int mt = 0; mt < 2; mt++)
        #pragma unroll
        for (int nt = 0; nt < 8; nt++)
            #pragma unroll
            for (int i = 0; i < 4; i++) acc[mt][nt][i] = 0.0f;
    mma_tile<4, 8>(smem + Q2_AH, smem + Q2_AL, smem + Q2_BH, smem + Q2_BL,
                   acc, w, lane);
    add_bias<8>(acc, &cst[208], lane);
    #pragma unroll
    for (int mt = 0; mt < 2; mt++)
        #pragma unroll
        for (int nt = 0; nt < 8; nt++)
            #pragma unroll
            for (int i = 0; i < 4; i++) {
                const float v = acc[mt][nt][i];
                acc[mt][nt][i] = 0.5f * v * (1.0f + erff(v * 0.7071067811865476f));
            }
    __syncthreads();
    stage_pre(smem + Q2_BH, smem + Q2_BL, g_f2h, g_f2l, 64, tid);
    frag_to_A<8>(smem + Q2_AH, smem + Q2_AL, acc, w, lane);
    __syncthreads();

    #pragma unroll
    for (int mt = 0; mt < 2; mt++)
        #pragma unroll
        for (int nt = 0; nt < 8; nt++)
            #pragma unroll
            for (int i = 0; i < 4; i++) acc[mt][nt][i] = 0.0f;
    mma_tile<4, 8>(smem + Q2_AH, smem + Q2_AL, smem + Q2_BH, smem + Q2_BL,
                   acc, w, lane);
    add_bias<8>(acc, &cst[272], lane);
    #pragma unroll
    for (int mt = 0; mt < 2; mt++) {
        const int t0 = w * 32 + mt * 16 + g;
        #pragma unroll
        for (int nt = 0; nt < 8; nt++) {
            const int col = nt * 8 + 2 * tig;
            *(float2*)&out[(size_t)(n0 + t0) * 64 + col] = make_float2(
                acc[mt][nt][0] + y[mt][nt][0], acc[mt][nt][1] + y[mt][nt][1]);
            *(float2*)&out[(size_t)(n0 + t0 + 8) * 64 + col] = make_float2(
                acc[mt][nt][2] + y[mt][nt][2], acc[mt][nt][3] + y[mt][nt][3]);
        }
    }
}

// ============================================================================
extern "C" void kernel_launch(void* const* d_in, const int* in_sizes, int n_in,
                              void* d_out, int out_size)
{
    const float* x     = (const float*)d_in[0];
    const float* ln1g  = (const float*)d_in[1];
    const float* ln1b  = (const float*)d_in[2];
    const float* wkqv  = (const float*)d_in[3];
    const float* bkqv  = (const float*)d_in[4];
    const float* wproj = (const float*)d_in[5];
    const float* bproj = (const float*)d_in[6];
    const float* ln2g  = (const float*)d_in[7];
    const float* ln2b  = (const float*)d_in[8];
    const float* wfc1  = (const float*)d_in[9];
    const float* bfc1  = (const float*)d_in[10];
    const float* wfc2  = (const float*)d_in[11];
    const float* bfc2  = (const float*)d_in[12];
    const float* wrf   = (const float*)d_in[13];

    cudaFuncSetAttribute(pass1_kernel, cudaFuncAttributeMaxDynamicSharedMemorySize, P1_BYTES);
    cudaFuncSetAttribute(pass2_kernel, cudaFuncAttributeMaxDynamicSharedMemorySize, P2_BYTES);

    setup_kernel<<<16, 256>>>(wkqv, bkqv, wrf);
    setup_split_kernel<<<54, 256>>>(wkqv, wfc1, wfc2);
    pass1_kernel<<<NBLK, 128, P1_BYTES>>>(x, ln1g, ln1b, bkqv);
    reduce1_kernel<<<dim3(NCH, BATCH), 256>>>();
    reduce2a_kernel<<<dim3(32, BATCH), 256>>>();
    wc2_kernel<<<dim3(9, BATCH), 256>>>(wproj);
    pass2_kernel<<<NBLK, 128, P2_BYTES>>>(bproj, ln2g, ln2b,
                                          bfc1, bfc2, (float*)d_out);
}

// round 14
// speedup vs baseline: 2.1500x; 1.0583x over previous
#include <cuda_runtime.h>
#include <cuda_bf16.h>
#include <stdint.h>
#include <math.h>

#define BATCH 4
#define S 96
#define DP 48
#define L (DP*DP*DP)            // 110592
#define NTOK (BATCH*L)          // 442368
#define MRF 32
#define NCH 108
#define TILE 128
#define NBLK (NTOK/TILE)        // 3456

typedef unsigned int u32;

// ---------------- scratch (token-major) ----------------
__device__ float g_kp[(size_t)NTOK * MRF];        // [tok][m]
__device__ float g_qp[(size_t)NTOK * MRF];        // [tok][m]
__device__ float g_v [(size_t)NTOK * 64];         // [tok][e]
__device__ float g_part_kptv[BATCH * NCH * 64 * MRF];
__device__ float g_part_ksum[BATCH * NCH * MRF];
__device__ float g_kptv[BATCH * 64 * MRF];        // [b][e][m]
__device__ float g_ksum[BATCH * MRF];
__device__ float g_wc[2 * 32 * 64];               // fused wrf@W{k,q}  [c][m][e]
__device__ float g_bc[2 * 32];                    // fused wrf@b{k,q}

// pre-split bf16 weight tiles, 144-B rows (36 u32/row), uint4-aligned
__device__ uint4 g_wkh[3 * 64 * 9], g_wkl[3 * 64 * 9];   // wkqv k/q/v
__device__ uint4 g_wch[2 * 32 * 9], g_wcl[2 * 32 * 9];   // fused RF (32 rows)
__device__ uint4 g_f1h[64 * 9],     g_f1l[64 * 9];       // wfc1
__device__ uint4 g_f2h[64 * 9],     g_f2l[64 * 9];       // wfc2
__device__ uint4 g_w2h[BATCH * 64 * 9], g_w2l[BATCH * 64 * 9];  // fused wproj@kptv^T

// ============================================================================
// mma.sync m16n8k16 bf16 core. A tiles [128][72] bf16, 144-B rows, no swizzle.
// ============================================================================
__device__ __forceinline__ void mma16816(float* c, const u32* a, u32 b0, u32 b1) {
    asm volatile(
        "mma.sync.aligned.m16n8k16.row.col.f32.bf16.bf16.f32 "
        "{%0,%1,%2,%3}, {%4,%5,%6,%7}, {%8,%9}, {%0,%1,%2,%3};"
        : "+f"(c[0]), "+f"(c[1]), "+f"(c[2]), "+f"(c[3])
        : "r"(a[0]), "r"(a[1]), "r"(a[2]), "r"(a[3]), "r"(b0), "r"(b1));
}

// 3-term split: Ahi*Bhi + Alo*Bhi + Ahi*Blo.
template<int KSTEPS, int NT>
__device__ __forceinline__ void mma_tile(
    const char* ah, const char* al,
    const char* bh, const char* bl,
    float (&acc)[2][NT][4], int w, int lane)
{
    const int g = lane >> 2;
    const int tig = lane & 3;
    #pragma unroll
    for (int ks = 0; ks < KSTEPS; ks++) {
        const int coff = ks * 32 + tig * 4;
        u32 Ah[2][4], Al[2][4];
        #pragma unroll
        for (int mt = 0; mt < 2; mt++) {
            const int r0 = (w * 32 + mt * 16 + g) * 144 + coff;
            const int r8 = r0 + 8 * 144;
            Ah[mt][0] = *(const u32*)(ah + r0);
            Ah[mt][1] = *(const u32*)(ah + r8);
            Ah[mt][2] = *(const u32*)(ah + r0 + 16);
            Ah[mt][3] = *(const u32*)(ah + r8 + 16);
            Al[mt][0] = *(const u32*)(al + r0);
            Al[mt][1] = *(const u32*)(al + r8);
            Al[mt][2] = *(const u32*)(al + r0 + 16);
            Al[mt][3] = *(const u32*)(al + r8 + 16);
        }
        #pragma unroll
        for (int nt = 0; nt < NT; nt++) {
            const int bo = (nt * 8 + g) * 144 + coff;
            const u32 Bh0 = *(const u32*)(bh + bo);
            const u32 Bh1 = *(const u32*)(bh + bo + 16);
            const u32 Bl0 = *(const u32*)(bl + bo);
            const u32 Bl1 = *(const u32*)(bl + bo + 16);
            #pragma unroll
            for (int mt = 0; mt < 2; mt++) {
                mma16816(acc[mt][nt], Ah[mt], Bh0, Bh1);
                mma16816(acc[mt][nt], Al[mt], Bh0, Bh1);
                mma16816(acc[mt][nt], Ah[mt], Bl0, Bl1);
            }
        }
    }
}

__device__ __forceinline__ float qsum(float v) {
    v += __shfl_xor_sync(0xffffffffu, v, 1);
    v += __shfl_xor_sync(0xffffffffu, v, 2);
    return v;
}

__device__ __forceinline__ void split_pair(float x0, float x1, u32& hi, u32& lo) {
    __nv_bfloat16 h0 = __float2bfloat16_rn(x0);
    __nv_bfloat16 h1 = __float2bfloat16_rn(x1);
    float r0 = x0 - __bfloat162float(h0);
    float r1 = x1 - __bfloat162float(h1);
    __nv_bfloat16 l0 = __float2bfloat16_rn(r0);
    __nv_bfloat16 l1 = __float2bfloat16_rn(r1);
    __nv_bfloat162 hh = __halves2bfloat162(h0, h1);
    __nv_bfloat162 ll = __halves2bfloat162(l0, l1);
    hi = *(u32*)&hh;
    lo = *(u32*)&ll;
}

template<int NT>
__device__ __forceinline__ void frag_to_A(char* ah, char* al,
                                          const float (&acc)[2][NT][4],
                                          int w, int lane) {
    const int g = lane >> 2, tig = lane & 3;
    #pragma unroll
    for (int mt = 0; mt < 2; mt++) {
        const int t0 = w * 32 + mt * 16 + g;
        #pragma unroll
        for (int nt = 0; nt < NT; nt++) {
            const int co = (nt * 8 + 2 * tig) * 2;
            u32 hi, lo;
            split_pair(acc[mt][nt][0], acc[mt][nt][1], hi, lo);
            *(u32*)(ah + t0 * 144 + co) = hi;
            *(u32*)(al + t0 * 144 + co) = lo;
            split_pair(acc[mt][nt][2], acc[mt][nt][3], hi, lo);
            *(u32*)(ah + (t0 + 8) * 144 + co) = hi;
            *(u32*)(al + (t0 + 8) * 144 + co) = lo;
        }
    }
}

template<int NT>
__device__ __forceinline__ void frag_to_gmem(float* dst, int C,
                                             const float (&acc)[2][NT][4],
                                             int w, int lane, int n0) {
    const int g = lane >> 2, tig = lane & 3;
    #pragma unroll
    for (int mt = 0; mt < 2; mt++) {
        const int t0 = w * 32 + mt * 16 + g;
        #pragma unroll
        for (int nt = 0; nt < NT; nt++) {
            const int col = nt * 8 + 2 * tig;
            *(float2*)&dst[(size_t)(n0 + t0) * C + col] =
                make_float2(acc[mt][nt][0], acc[mt][nt][1]);
            *(float2*)&dst[(size_t)(n0 + t0 + 8) * C + col] =
                make_float2(acc[mt][nt][2], acc[mt][nt][3]);
        }
    }
}

template<int NT>
__device__ __forceinline__ void add_bias(float (&acc)[2][NT][4],
                                         const float* bias, int lane) {
    const int tig = lane & 3;
    #pragma unroll
    for (int nt = 0; nt < NT; nt++) {
        const float2 bb = *(const float2*)&bias[nt * 8 + 2 * tig];
        #pragma unroll
        for (int mt = 0; mt < 2; mt++) {
            acc[mt][nt][0] += bb.x;
            acc[mt][nt][1] += bb.y;
            acc[mt][nt][2] += bb.x;
            acc[mt][nt][3] += bb.y;
        }
    }
}

template<int NE>
__device__ __forceinline__ void store_row(char* ahi, char* alo, int row,
                                          const float* v) {
    #pragma unroll
    for (int ch = 0; ch < NE / 8; ch++) {
        u32 h0, l0, h1, l1, h2, l2, h3, l3;
        split_pair(v[ch*8+0], v[ch*8+1], h0, l0);
        split_pair(v[ch*8+2], v[ch*8+3], h1, l1);
        split_pair(v[ch*8+4], v[ch*8+5], h2, l2);
        split_pair(v[ch*8+6], v[ch*8+7], h3, l3);
        const int off = row * 144 + ch * 16;
        *(uint4*)(ahi + off) = make_uint4(h0, h1, h2, h3);
        *(uint4*)(alo + off) = make_uint4(l0, l1, l2, l3);
    }
}

// copy pre-split tile (rows*9 uint4 each for hi/lo) gmem -> smem
__device__ __forceinline__ void stage_pre(char* dh, char* dl,
                                          const uint4* __restrict__ gh,
                                          const uint4* __restrict__ gl,
                                          int rows, int tid) {
    uint4* sh = (uint4*)dh;
    uint4* sl = (uint4*)dl;
    const int n = rows * 9;
    for (int p = tid; p < n; p += 128) {
        sh[p] = gh[p];
        sl[p] = gl[p];
    }
}

// ============================================================================
// Setup 1 (grid 16): Wc = wrf @ W{k,q}, bc = wrf @ b{k,q}
// ============================================================================
__global__ __launch_bounds__(256) void setup_kernel(
    const float* __restrict__ wkqv, const float* __restrict__ bkqv,
    const float* __restrict__ wrf)
{
    const int i = blockIdx.x * 256 + threadIdx.x;   // 0..4095
    const int c = i >> 11;
    const int m = (i >> 6) & 31;
    const int e = i & 63;
    float s = 0.0f;
    #pragma unroll 8
    for (int d = 0; d < 64; d++)
        s += wrf[m * 64 + d] * wkqv[c * 4096 + d * 64 + e];
    g_wc[i] = s;

    if (blockIdx.x == 0 && threadIdx.x < 64) {
        const int cc = threadIdx.x >> 5;
        const int mm = threadIdx.x & 31;
        float sb = 0.0f;
        #pragma unroll 8
        for (int d = 0; d < 64; d++)
            sb += wrf[mm * 64 + d] * bkqv[cc * 64 + d];
        g_bc[threadIdx.x] = sb;
    }
}

// ============================================================================
// Setup 2 (grid 54): pre-split all static weights into 144-B-row tiles
// ============================================================================
__global__ __launch_bounds__(256) void setup_split_kernel(
    const float* __restrict__ wkqv,
    const float* __restrict__ wfc1, const float* __restrict__ wfc2)
{
    const int i = blockIdx.x * 256 + threadIdx.x;
    if (i >= 13824) return;
    const int word = i % 36;
    const int rowg = i / 36;

    const float* src = 0;
    u32* dsth = 0;
    u32* dstl = 0;
    int row = 0, cols = 64;
    if (i < 6912) {               // wkqv
        src = wkqv; row = rowg;
        dsth = (u32*)g_wkh; dstl = (u32*)g_wkl;
    } else if (i < 9216) {        // wfc1
        src = wfc1; row = rowg - 192;
        dsth = (u32*)g_f1h; dstl = (u32*)g_f1l;
    } else if (i < 11520) {       // wfc2
        src = wfc2; row = rowg - 256;
        dsth = (u32*)g_f2h; dstl = (u32*)g_f2l;
    } else {                      // wc
        src = g_wc; row = rowg - 320;
        dsth = (u32*)g_wch; dstl = (u32*)g_wcl;
    }

    u32 hi = 0, lo = 0;
    if (word < 32) {
        const float2 wv = *(const float2*)(src + row * cols + word * 2);
        split_pair(wv.x, wv.y, hi, lo);
    }
    dsth[row * 36 + word] = hi;
    dstl[row * 36 + word] = lo;
}

// ============================================================================
// Pass 1 (unchanged from R12 winner)
// ============================================================================
#define Q1_AH  2048
#define Q1_AL  20480
#define Q1_BH  38912
#define Q1_BL  48128
#define Q1_B2H 57344
#define Q1_B2L 61952
#define P1_BYTES (66560 + 1024)

__global__ __launch_bounds__(128, 3) void pass1_kernel(
    const float* __restrict__ x,
    const float* __restrict__ ln1g, const float* __restrict__ ln1b,
    const float* __restrict__ bkqv)
{
    extern __shared__ char smem_raw[];
    char* smem = (char*)(((size_t)smem_raw + 1023) & ~(size_t)1023);
    float* cst = (float*)smem;

    const int tid  = threadIdx.x;
    const int w    = tid >> 5;
    const int lane = tid & 31;
    const int g    = lane >> 2;
    const int tig  = lane & 3;
    const int n0   = blockIdx.x * TILE;
    const int b    = n0 / L;
    const int l0   = n0 % L;

    if (tid < 64) {
        cst[16 + tid]  = ln1g[tid];
        cst[80 + tid]  = ln1b[tid];
        cst[336 + tid] = g_bc[tid];
    }
    for (int i = tid; i < 192; i += 128) cst[144 + i] = bkqv[i];

    const int l  = l0 + tid;
    const int dz = l / (DP * DP);
    const int hy = (l / DP) % DP;
    const int wx = l % DP;
    const float* xb = x + (size_t)b * S * S * S;
    float h[64];
    float sum = 0.0f, sq = 0.0f;
    #pragma unroll
    for (int kd = 0; kd < 4; kd++) {
        const int iz = 2 * dz - 1 + kd;
        const bool zok = (unsigned)iz < (unsigned)S;
        #pragma unroll
        for (int kh = 0; kh < 4; kh++) {
            const int iy = 2 * hy - 1 + kh;
            const bool yok = zok && ((unsigned)iy < (unsigned)S);
            #pragma unroll
            for (int kw = 0; kw < 4; kw++) {
                const int ix = 2 * wx - 1 + kw;
                const float v = (yok && (unsigned)ix < (unsigned)S)
                              ? xb[((size_t)iz * S + iy) * S + ix] : 0.0f;
                h[kd * 16 + kh * 4 + kw] = v;
                sum += v;
                sq += v * v;
            }
        }
    }
    const float mu  = sum * (1.0f / 64.0f);
    const float var = sq * (1.0f / 64.0f) - mu * mu;
    const float rs  = rsqrtf(var + 1e-5f);

    __syncthreads();
    #pragma unroll
    for (int f = 0; f < 64; f++)
        h[f] = (h[f] - mu) * rs * cst[16 + f] + cst[80 + f];
    store_row<64>(smem + Q1_AH, smem + Q1_AL, tid, h);

    const float rfscale = 0.1767766952966369f;

    for (int c = 0; c < 3; c++) {
        __syncthreads();
        stage_pre(smem + Q1_BH, smem + Q1_BL, g_wkh + c * 576, g_wkl + c * 576,
                  64, tid);
        if (c < 2)
            stage_pre(smem + Q1_B2H, smem + Q1_B2L, g_wch + c * 288,
                      g_wcl + c * 288, 32, tid);
        __syncthreads();

        float acc[2][8][4];
        #pragma unroll
        for (int mt = 0; mt < 2; mt++)
            #pragma unroll
            for (int nt = 0; nt < 8; nt++)
                #pragma unroll
                for (int i = 0; i < 4; i++) acc[mt][nt][i] = 0.0f;
        mma_tile<4, 8>(smem + Q1_AH, smem + Q1_AL, smem + Q1_BH, smem + Q1_BL,
                       acc, w, lane);
        add_bias<8>(acc, &cst[144 + c * 64], lane);

        if (c < 2) {
            float xd[2][2];
            #pragma unroll
            for (int mt = 0; mt < 2; mt++)
                #pragma unroll
                for (int hf = 0; hf < 2; hf++) {
                    float p = 0.0f;
                    #pragma unroll
                    for (int nt = 0; nt < 8; nt++) {
                        const float v0 = acc[mt][nt][2*hf];
                        const float v1 = acc[mt][nt][2*hf + 1];
                        p += v0 * v0 + v1 * v1;
                    }
                    xd[mt][hf] = 0.5f * qsum(p);
                }

            float ac2[2][4][4];
            #pragma unroll
            for (int mt = 0; mt < 2; mt++)
                #pragma unroll
                for (int nt = 0; nt < 4; nt++)
                    #pragma unroll
                    for (int i = 0; i < 4; i++) ac2[mt][nt][i] = 0.0f;
            mma_tile<4, 4>(smem + Q1_AH, smem + Q1_AL,
                           smem + Q1_B2H, smem + Q1_B2L, ac2, w, lane);
            add_bias<4>(ac2, &cst[336 + c * 32], lane);

            float* dst = (c == 0) ? g_kp : g_qp;
            #pragma unroll
            for (int mt = 0; mt < 2; mt++) {
                const int t0 = w * 32 + mt * 16 + g;
                #pragma unroll
                for (int nt = 0; nt < 4; nt++) {
                    const int col = nt * 8 + 2 * tig;
                    *(float2*)&dst[(size_t)(n0 + t0) * 32 + col] = make_float2(
                        __expf(ac2[mt][nt][0] - xd[mt][0]) * rfscale,
                        __expf(ac2[mt][nt][1] - xd[mt][0]) * rfscale);
                    *(float2*)&dst[(size_t)(n0 + t0 + 8) * 32 + col] = make_float2(
                        __expf(ac2[mt][nt][2] - xd[mt][1]) * rfscale,
                        __expf(ac2[mt][nt][3] - xd[mt][1]) * rfscale);
                }
            }
        } else {
            frag_to_gmem<8>(g_v, 64, acc, w, lane, n0);
        }
    }
}

// ============================================================================
// Reduce 1 v2: register-tiled (4e x 8m), 4-way token split, quad-shuffle merge
// thread: tq = t&3 (token quarter), u = t>>2; eb = (u>>2)*4, mb = (u&3)*8
// ============================================================================
__global__ __launch_bounds__(256) void reduce1_kernel()
{
    __shared__ float sv[64 * 65];   // [e][tt]
    __shared__ float sk[MRF * 65];  // [m][tt]

    const int b = blockIdx.y;
    const int c = blockIdx.x;
    const int t = threadIdx.x;
    const int n0 = b * L + c * 1024;

    const int tq = t & 3;
    const int u  = t >> 2;          // 0..63
    const int eb = (u >> 2) * 4;    // 0..60 step 4
    const int mb = (u & 3) * 8;     // 0,8,16,24

    float acc[4][8];
    #pragma unroll
    for (int i = 0; i < 4; i++)
        #pragma unroll
        for (int j = 0; j < 8; j++) acc[i][j] = 0.0f;
    float ks[8];
    #pragma unroll
    for (int j = 0; j < 8; j++) ks[j] = 0.0f;

    for (int tile = 0; tile < 16; tile++) {
        const int base = n0 + tile * 64;
        __syncthreads();
        for (int idx = t; idx < 1024; idx += 256) {
            const int tt = idx >> 4;
            const int eq = (idx & 15) * 4;
            const float4 vv = *(const float4*)&g_v[(size_t)(base + tt) * 64 + eq];
            sv[(eq+0)*65+tt] = vv.x;
            sv[(eq+1)*65+tt] = vv.y;
            sv[(eq+2)*65+tt] = vv.z;
            sv[(eq+3)*65+tt] = vv.w;
        }
        for (int idx = t; idx < 512; idx += 256) {
            const int tt = idx >> 3;
            const int mq = (idx & 7) * 4;
            const float4 kk = *(const float4*)&g_kp[(size_t)(base + tt) * 32 + mq];
            sk[(mq+0)*65+tt] = kk.x;
            sk[(mq+1)*65+tt] = kk.y;
            sk[(mq+2)*65+tt] = kk.z;
            sk[(mq+3)*65+tt] = kk.w;
        }
        __syncthreads();

        #pragma unroll 4
        for (int j = 0; j < 16; j++) {
            const int tt = tq * 16 + j;
            const float v0 = sv[(eb+0)*65+tt];
            const float v1 = sv[(eb+1)*65+tt];
            const float v2 = sv[(eb+2)*65+tt];
            const float v3 = sv[(eb+3)*65+tt];
            #pragma unroll
            for (int i = 0; i < 8; i++) {
                const float km = sk[(mb+i)*65+tt];
                acc[0][i] += v0 * km;
                acc[1][i] += v1 * km;
                acc[2][i] += v2 * km;
                acc[3][i] += v3 * km;
                if (u < 4) ks[i] += km;
            }
        }
    }

    // merge the 4 token-quarter partials within each lane quad
    const int slot = b * NCH + c;
    #pragma unroll
    for (int i = 0; i < 4; i++)
        #pragma unroll
        for (int j = 0; j < 8; j++) {
            float v = acc[i][j];
            v += __shfl_xor_sync(0xffffffffu, v, 1);
            v += __shfl_xor_sync(0xffffffffu, v, 2);
            if (tq == 0)
                g_part_kptv[slot * (64 * MRF) + (eb + i) * MRF + mb + j] = v;
        }
    if (u < 4) {
        #pragma unroll
        for (int j = 0; j < 8; j++) {
            float s = ks[j];
            s += __shfl_xor_sync(0xffffffffu, s, 1);
            s += __shfl_xor_sync(0xffffffffu, s, 2);
            if (tq == 0) g_part_ksum[slot * MRF + mb + j] = s;
        }
    }
}

// ============================================================================
// Reduce 2a (grid 32 x BATCH): chunk-parallel finalize kptv + ksum
// ============================================================================
__global__ __launch_bounds__(256) void reduce2a_kernel()
{
    const int b = blockIdx.y;
    const int t = threadIdx.x;
    const int e4   = t >> 2;
    const int part = t & 3;
    const int idx  = blockIdx.x * 64 + e4;

    float acc = 0.0f;
    const float* p = &g_part_kptv[b * NCH * 2048 + idx];
    for (int c = part; c < NCH; c += 4) acc += p[(size_t)c * 2048];
    acc += __shfl_xor_sync(0xffffffffu, acc, 1);
    acc += __shfl_xor_sync(0xffffffffu, acc, 2);
    if (part == 0) g_kptv[b * 2048 + idx] = acc;

    if (blockIdx.x == 0 && t < 128) {
        const int m = t >> 2;
        float s = 0.0f;
        const float* q = &g_part_ksum[b * NCH * MRF + m];
        for (int c = part; c < NCH; c += 4) s += q[(size_t)c * MRF];
        s += __shfl_xor_sync(0xffffffffu, s, 1);
        s += __shfl_xor_sync(0xffffffffu, s, 2);
        if (part == 0) g_ksum[b * MRF + m] = s;
    }
}

// ============================================================================
// Wc2 (grid 9 x BATCH): split-bf16 fused wproj@kptv^T
// ============================================================================
__global__ __launch_bounds__(256) void wc2_kernel(const float* __restrict__ wproj)
{
    const int b = blockIdx.y;
    const int i = blockIdx.x * 256 + threadIdx.x;
    if (i >= 2304) return;
    const int j = i / 36;
    const int word = i % 36;

    u32 hi = 0, lo = 0;
    if (word < 32) {
        const int m = word * 2;
        float s0 = 0.0f, s1 = 0.0f;
        #pragma unroll 8
        for (int e = 0; e < 64; e++) {
            const float wp = wproj[j * 64 + e];
            s0 += wp * g_kptv[b * 2048 + e * 32 + m];
            s1 += wp * g_kptv[b * 2048 + e * 32 + m + 1];
        }
        split_pair(s0, s1, hi, lo);
    }
    ((u32*)g_w2h)[b * 2304 + j * 36 + word] = hi;
    ((u32*)g_w2l)[b * 2304 + j * 36 + word] = lo;
}

// ============================================================================
// Pass 2 (unchanged from R12 winner)
// ============================================================================
#define Q2_AH 2048
#define Q2_AL 20480
#define Q2_BH 38912
#define Q2_BL 48128
#define P2_BYTES (57344 + 1024)

__global__ __launch_bounds__(128, 3) void pass2_kernel(
    const float* __restrict__ bproj,
    const float* __restrict__ ln2g,  const float* __restrict__ ln2b,
    const float* __restrict__ bfc1,  const float* __restrict__ bfc2,
    float* __restrict__ out)
{
    extern __shared__ char smem_raw[];
    char* smem = (char*)(((size_t)smem_raw + 1023) & ~(size_t)1023);
    float* cst = (float*)smem;

    const int tid  = threadIdx.x;
    const int w    = tid >> 5;
    const int lane = tid & 31;
    const int g    = lane >> 2;
    const int tig  = lane & 3;
    const int n0   = blockIdx.x * TILE;
    const int b    = n0 / L;

    if (tid < 64) {
        cst[16 + tid]  = bproj[tid];
        cst[80 + tid]  = ln2g[tid];
        cst[144 + tid] = ln2b[tid];
        cst[208 + tid] = bfc1[tid];
        cst[272 + tid] = bfc2[tid];
    }
    if (tid < 32) cst[336 + tid] = g_ksum[b * 32 + tid];
    stage_pre(smem + Q2_BH, smem + Q2_BL, g_w2h + b * 576, g_w2l + b * 576,
              64, tid);

    float qf[2][4][4];
    #pragma unroll
    for (int mt = 0; mt < 2; mt++) {
        const int t0 = w * 32 + mt * 16 + g;
        #pragma unroll
        for (int nt = 0; nt < 4; nt++) {
            const int col = nt * 8 + 2 * tig;
            const float2 a = *(const float2*)&g_qp[(size_t)(n0 + t0) * 32 + col];
            const float2 bb = *(const float2*)&g_qp[(size_t)(n0 + t0 + 8) * 32 + col];
            qf[mt][nt][0] = a.x;  qf[mt][nt][1] = a.y;
            qf[mt][nt][2] = bb.x; qf[mt][nt][3] = bb.y;
        }
    }
    __syncthreads();

    #pragma unroll
    for (int mt = 0; mt < 2; mt++)
        #pragma unroll
        for (int hf = 0; hf < 2; hf++) {
            float p = 0.0f;
            #pragma unroll
            for (int nt = 0; nt < 4; nt++) {
                const int col = nt * 8 + 2 * tig;
                p += qf[mt][nt][2*hf]     * cst[336 + col]
                   + qf[mt][nt][2*hf + 1] * cst[336 + col + 1];
            }
            const float invD = 1.0f / (qsum(p) + 1e-8f);
            #pragma unroll
            for (int nt = 0; nt < 4; nt++) {
                qf[mt][nt][2*hf]     *= invD;
                qf[mt][nt][2*hf + 1] *= invD;
            }
        }
    frag_to_A<4>(smem + Q2_AH, smem + Q2_AL, qf, w, lane);
    __syncthreads();

    float acc[2][8][4];
    #pragma unroll
    for (int mt = 0; mt < 2; mt++)
        #pragma unroll
        for (int nt = 0; nt < 8; nt++)
            #pragma unroll
            for (int i = 0; i < 4; i++) acc[mt][nt][i] = 0.0f;
    mma_tile<2, 8>(smem + Q2_AH, smem + Q2_AL, smem + Q2_BH, smem + Q2_BL,
                   acc, w, lane);
    add_bias<8>(acc, &cst[16], lane);

    float y[2][8][4];
    #pragma unroll
    for (int mt = 0; mt < 2; mt++) {
        const int t0 = w * 32 + mt * 16 + g;
        #pragma unroll
        for (int nt = 0; nt < 8; nt++) {
            const int col = nt * 8 + 2 * tig;
            const float2 va = *(const float2*)&g_v[(size_t)(n0 + t0) * 64 + col];
            const float2 vb = *(const float2*)&g_v[(size_t)(n0 + t0 + 8) * 64 + col];
            y[mt][nt][0] = acc[mt][nt][0] + va.x;
            y[mt][nt][1] = acc[mt][nt][1] + va.y;
            y[mt][nt][2] = acc[mt][nt][2] + vb.x;
            y[mt][nt][3] = acc[mt][nt][3] + vb.y;
        }
    }

    float nmu[2][2], rsg[2][2];
    #pragma unroll
    for (int mt = 0; mt < 2; mt++)
        #pragma unroll
        for (int hf = 0; hf < 2; hf++) {
            float p1 = 0.0f, p2 = 0.0f;
            #pragma unroll
            for (int nt = 0; nt < 8; nt++) {
                const float v0 = y[mt][nt][2*hf];
                const float v1 = y[mt][nt][2*hf + 1];
                p1 += v0 + v1;
                p2 += v0 * v0 + v1 * v1;
            }
            const float s1 = qsum(p1);
            const float s2 = qsum(p2);
            const float muv = s1 * (1.0f / 64.0f);
            const float var = s2 * (1.0f / 64.0f) - muv * muv;
            nmu[mt][hf] = -muv;
            rsg[mt][hf] = rsqrtf(var + 1e-5f);
        }

    __syncthreads();
    stage_pre(smem + Q2_BH, smem + Q2_BL, g_f1h, g_f1l, 64, tid);
    #pragma unroll
    for (int mt = 0; mt < 2; mt++) {
        const int t0 = w * 32 + mt * 16 + g;
        #pragma unroll
        for (int nt = 0; nt < 8; nt++) {
            const int col = nt * 8 + 2 * tig;
            const float2 gg = *(const float2*)&cst[80 + col];
            const float2 bb = *(const float2*)&cst[144 + col];
            const float z0 = (y[mt][nt][0] + nmu[mt][0]) * rsg[mt][0] * gg.x + bb.x;
            const float z1 = (y[mt][nt][1] + nmu[mt][0]) * rsg[mt][0] * gg.y + bb.y;
            const float z2 = (y[mt][nt][2] + nmu[mt][1]) * rsg[mt][1] * gg.x + bb.x;
            const float z3 = (y[mt][nt][3] + nmu[mt][1]) * rsg[mt][1] * gg.y + bb.y;
            u32 hi, lo;
            const int co = col * 2;
            split_pair(z0, z1, hi, lo);
            *(u32*)(smem + Q2_AH + t0 * 144 + co) = hi;
            *(u32*)(smem + Q2_AL + t0 * 144 + co) = lo;
            split_pair(z2, z3, hi, lo);
            *(u32*)(smem + Q2_AH + (t0 + 8) * 144 + co) = hi;
            *(u32*)(smem + Q2_AL + (t0 + 8) * 144 + co) = lo;
        }
    }
    __syncthreads();

    #pragma unroll
    for (int mt = 0; mt < 2; mt++)
        #pragma unroll
        for (int nt = 0; nt < 8; nt++)
            #pragma unroll
            for (int i = 0; i < 4; i++) acc[mt][nt][i] = 0.0f;
    mma_tile<4, 8>(smem + Q2_AH, smem + Q2_AL, smem + Q2_BH, smem + Q2_BL,
                   acc, w, lane);
    add_bias<8>(acc, &cst[208], lane);
    #pragma unroll
    for (int mt = 0; mt < 2; mt++)
        #pragma unroll
        for (int nt = 0; nt < 8; nt++)
            #pragma unroll
            for (int i = 0; i < 4; i++) {
                const float v = acc[mt][nt][i];
                acc[mt][nt][i] = 0.5f * v * (1.0f + erff(v * 0.7071067811865476f));
            }
    __syncthreads();
    stage_pre(smem + Q2_BH, smem + Q2_BL, g_f2h, g_f2l, 64, tid);
    frag_to_A<8>(smem + Q2_AH, smem + Q2_AL, acc, w, lane);
    __syncthreads();

    #pragma unroll
    for (int mt = 0; mt < 2; mt++)
        #pragma unroll
        for (int nt = 0; nt < 8; nt++)
            #pragma unroll
            for (int i = 0; i < 4; i++) acc[mt][nt][i] = 0.0f;
    mma_tile<4, 8>(smem + Q2_AH, smem + Q2_AL, smem + Q2_BH, smem + Q2_BL,
                   acc, w, lane);
    add_bias<8>(acc, &cst[272], lane);
    #pragma unroll
    for (int mt = 0; mt < 2; mt++) {
        const int t0 = w * 32 + mt * 16 + g;
        #pragma unroll
        for (int nt = 0; nt < 8; nt++) {
            const int col = nt * 8 + 2 * tig;
            *(float2*)&out[(size_t)(n0 + t0) * 64 + col] = make_float2(
                acc[mt][nt][0] + y[mt][nt][0], acc[mt][nt][1] + y[mt][nt][1]);
            *(float2*)&out[(size_t)(n0 + t0 + 8) * 64 + col] = make_float2(
                acc[mt][nt][2] + y[mt][nt][2], acc[mt][nt][3] + y[mt][nt][3]);
        }
    }
}

// ============================================================================
extern "C" void kernel_launch(void* const* d_in, const int* in_sizes, int n_in,
                              void* d_out, int out_size)
{
    const float* x     = (const float*)d_in[0];
    const float* ln1g  = (const float*)d_in[1];
    const float* ln1b  = (const float*)d_in[2];
    const float* wkqv  = (const float*)d_in[3];
    const float* bkqv  = (const float*)d_in[4];
    const float* wproj = (const float*)d_in[5];
    const float* bproj = (const float*)d_in[6];
    const float* ln2g  = (const float*)d_in[7];
    const float* ln2b  = (const float*)d_in[8];
    const float* wfc1  = (const float*)d_in[9];
    const float* bfc1  = (const float*)d_in[10];
    const float* wfc2  = (const float*)d_in[11];
    const float* bfc2  = (const float*)d_in[12];
    const float* wrf   = (const float*)d_in[13];

    cudaFuncSetAttribute(pass1_kernel, cudaFuncAttributeMaxDynamicSharedMemorySize, P1_BYTES);
    cudaFuncSetAttribute(pass2_kernel, cudaFuncAttributeMaxDynamicSharedMemorySize, P2_BYTES);

    setup_kernel<<<16, 256>>>(wkqv, bkqv, wrf);
    setup_split_kernel<<<54, 256>>>(wkqv, wfc1, wfc2);
    pass1_kernel<<<NBLK, 128, P1_BYTES>>>(x, ln1g, ln1b, bkqv);
    reduce1_kernel<<<dim3(NCH, BATCH), 256>>>();
    reduce2a_kernel<<<dim3(32, BATCH), 256>>>();
    wc2_kernel<<<dim3(9, BATCH), 256>>>(wproj);
    pass2_kernel<<<NBLK, 128, P2_BYTES>>>(bproj, ln2g, ln2b,
                                          bfc1, bfc2, (float*)d_out);
}

// round 15
// speedup vs baseline: 2.1556x; 1.0026x over previous
#include <cuda_runtime.h>
#include <cuda_bf16.h>
#include <stdint.h>
#include <math.h>

#define BATCH 4
#define S 96
#define DP 48
#define L (DP*DP*DP)            // 110592
#define NTOK (BATCH*L)          // 442368
#define MRF 32
#define NCH 108
#define TILE 128
#define NBLK (NTOK/TILE)        // 3456

typedef unsigned int u32;

// ---------------- scratch (token-major) ----------------
__device__ float g_kp[(size_t)NTOK * MRF];        // [tok][m]
__device__ float g_qp[(size_t)NTOK * MRF];        // [tok][m]
__device__ float g_v [(size_t)NTOK * 64];         // [tok][e]
__device__ float g_part_kptv[BATCH * NCH * 64 * MRF];
__device__ float g_part_ksum[BATCH * NCH * MRF];
__device__ float g_kptv[BATCH * 64 * MRF];        // [b][e][m]
__device__ float g_ksum[BATCH * MRF];
__device__ float g_wc[2 * 32 * 64];               // fused wrf@W{k,q}  [c][m][e]
__device__ float g_bc[2 * 32];                    // fused wrf@b{k,q}

// pre-split bf16 weight tiles, 144-B rows (36 u32/row), uint4-aligned
__device__ uint4 g_wkh[3 * 64 * 9], g_wkl[3 * 64 * 9];   // wkqv k/q/v
__device__ uint4 g_wch[2 * 32 * 9], g_wcl[2 * 32 * 9];   // fused RF (32 rows)
__device__ uint4 g_f1h[64 * 9],     g_f1l[64 * 9];       // wfc1
__device__ uint4 g_f2h[64 * 9],     g_f2l[64 * 9];       // wfc2
__device__ uint4 g_w2h[BATCH * 64 * 9], g_w2l[BATCH * 64 * 9];  // fused wproj@kptv^T

// ============================================================================
// mma.sync m16n8k16 bf16 core. A tiles [128][72] bf16, 144-B rows, no swizzle.
// ============================================================================
__device__ __forceinline__ void mma16816(float* c, const u32* a, u32 b0, u32 b1) {
    asm volatile(
        "mma.sync.aligned.m16n8k16.row.col.f32.bf16.bf16.f32 "
        "{%0,%1,%2,%3}, {%4,%5,%6,%7}, {%8,%9}, {%0,%1,%2,%3};"
        : "+f"(c[0]), "+f"(c[1]), "+f"(c[2]), "+f"(c[3])
        : "r"(a[0]), "r"(a[1]), "r"(a[2]), "r"(a[3]), "r"(b0), "r"(b1));
}

// 3-term split: Ahi*Bhi + Alo*Bhi + Ahi*Blo.
template<int KSTEPS, int NT>
__device__ __forceinline__ void mma_tile(
    const char* ah, const char* al,
    const char* bh, const char* bl,
    float (&acc)[2][NT][4], int w, int lane)
{
    const int g = lane >> 2;
    const int tig = lane & 3;
    #pragma unroll
    for (int ks = 0; ks < KSTEPS; ks++) {
        const int coff = ks * 32 + tig * 4;
        u32 Ah[2][4], Al[2][4];
        #pragma unroll
        for (int mt = 0; mt < 2; mt++) {
            const int r0 = (w * 32 + mt * 16 + g) * 144 + coff;
            const int r8 = r0 + 8 * 144;
            Ah[mt][0] = *(const u32*)(ah + r0);
            Ah[mt][1] = *(const u32*)(ah + r8);
            Ah[mt][2] = *(const u32*)(ah + r0 + 16);
            Ah[mt][3] = *(const u32*)(ah + r8 + 16);
            Al[mt][0] = *(const u32*)(al + r0);
            Al[mt][1] = *(const u32*)(al + r8);
            Al[mt][2] = *(const u32*)(al + r0 + 16);
            Al[mt][3] = *(const u32*)(al + r8 + 16);
        }
        #pragma unroll
        for (int nt = 0; nt < NT; nt++) {
            const int bo = (nt * 8 + g) * 144 + coff;
            const u32 Bh0 = *(const u32*)(bh + bo);
            const u32 Bh1 = *(const u32*)(bh + bo + 16);
            const u32 Bl0 = *(const u32*)(bl + bo);
            const u32 Bl1 = *(const u32*)(bl + bo + 16);
            #pragma unroll
            for (int mt = 0; mt < 2; mt++) {
                mma16816(acc[mt][nt], Ah[mt], Bh0, Bh1);
                mma16816(acc[mt][nt], Al[mt], Bh0, Bh1);
                mma16816(acc[mt][nt], Ah[mt], Bl0, Bl1);
            }
        }
    }
}

__device__ __forceinline__ float qsum(float v) {
    v += __shfl_xor_sync(0xffffffffu, v, 1);
    v += __shfl_xor_sync(0xffffffffu, v, 2);
    return v;
}

__device__ __forceinline__ void split_pair(float x0, float x1, u32& hi, u32& lo) {
    __nv_bfloat16 h0 = __float2bfloat16_rn(x0);
    __nv_bfloat16 h1 = __float2bfloat16_rn(x1);
    float r0 = x0 - __bfloat162float(h0);
    float r1 = x1 - __bfloat162float(h1);
    __nv_bfloat16 l0 = __float2bfloat16_rn(r0);
    __nv_bfloat16 l1 = __float2bfloat16_rn(r1);
    __nv_bfloat162 hh = __halves2bfloat162(h0, h1);
    __nv_bfloat162 ll = __halves2bfloat162(l0, l1);
    hi = *(u32*)&hh;
    lo = *(u32*)&ll;
}

template<int NT>
__device__ __forceinline__ void frag_to_A(char* ah, char* al,
                                          const float (&acc)[2][NT][4],
                                          int w, int lane) {
    const int g = lane >> 2, tig = lane & 3;
    #pragma unroll
    for (int mt = 0; mt < 2; mt++) {
        const int t0 = w * 32 + mt * 16 + g;
        #pragma unroll
        for (int nt = 0; nt < NT; nt++) {
            const int co = (nt * 8 + 2 * tig) * 2;
            u32 hi, lo;
            split_pair(acc[mt][nt][0], acc[mt][nt][1], hi, lo);
            *(u32*)(ah + t0 * 144 + co) = hi;
            *(u32*)(al + t0 * 144 + co) = lo;
            split_pair(acc[mt][nt][2], acc[mt][nt][3], hi, lo);
            *(u32*)(ah + (t0 + 8) * 144 + co) = hi;
            *(u32*)(al + (t0 + 8) * 144 + co) = lo;
        }
    }
}

template<int NT>
__device__ __forceinline__ void frag_to_gmem(float* dst, int C,
                                             const float (&acc)[2][NT][4],
                                             int w, int lane, int n0) {
    const int g = lane >> 2, tig = lane & 3;
    #pragma unroll
    for (int mt = 0; mt < 2; mt++) {
        const int t0 = w * 32 + mt * 16 + g;
        #pragma unroll
        for (int nt = 0; nt < NT; nt++) {
            const int col = nt * 8 + 2 * tig;
            *(float2*)&dst[(size_t)(n0 + t0) * C + col] =
                make_float2(acc[mt][nt][0], acc[mt][nt][1]);
            *(float2*)&dst[(size_t)(n0 + t0 + 8) * C + col] =
                make_float2(acc[mt][nt][2], acc[mt][nt][3]);
        }
    }
}

template<int NT>
__device__ __forceinline__ void add_bias(float (&acc)[2][NT][4],
                                         const float* bias, int lane) {
    const int tig = lane & 3;
    #pragma unroll
    for (int nt = 0; nt < NT; nt++) {
        const float2 bb = *(const float2*)&bias[nt * 8 + 2 * tig];
        #pragma unroll
        for (int mt = 0; mt < 2; mt++) {
            acc[mt][nt][0] += bb.x;
            acc[mt][nt][1] += bb.y;
            acc[mt][nt][2] += bb.x;
            acc[mt][nt][3] += bb.y;
        }
    }
}

template<int NE>
__device__ __forceinline__ void store_row(char* ahi, char* alo, int row,
                                          const float* v) {
    #pragma unroll
    for (int ch = 0; ch < NE / 8; ch++) {
        u32 h0, l0, h1, l1, h2, l2, h3, l3;
        split_pair(v[ch*8+0], v[ch*8+1], h0, l0);
        split_pair(v[ch*8+2], v[ch*8+3], h1, l1);
        split_pair(v[ch*8+4], v[ch*8+5], h2, l2);
        split_pair(v[ch*8+6], v[ch*8+7], h3, l3);
        const int off = row * 144 + ch * 16;
        *(uint4*)(ahi + off) = make_uint4(h0, h1, h2, h3);
        *(uint4*)(alo + off) = make_uint4(l0, l1, l2, l3);
    }
}

// copy pre-split tile (rows*9 uint4 each for hi/lo) gmem -> smem
__device__ __forceinline__ void stage_pre(char* dh, char* dl,
                                          const uint4* __restrict__ gh,
                                          const uint4* __restrict__ gl,
                                          int rows, int tid) {
    uint4* sh = (uint4*)dh;
    uint4* sl = (uint4*)dl;
    const int n = rows * 9;
    for (int p = tid; p < n; p += 128) {
        sh[p] = gh[p];
        sl[p] = gl[p];
    }
}

// ============================================================================
// Setup 1 (grid 16): Wc = wrf @ W{k,q}, bc = wrf @ b{k,q}
// ============================================================================
__global__ __launch_bounds__(256) void setup_kernel(
    const float* __restrict__ wkqv, const float* __restrict__ bkqv,
    const float* __restrict__ wrf)
{
    const int i = blockIdx.x * 256 + threadIdx.x;   // 0..4095
    const int c = i >> 11;
    const int m = (i >> 6) & 31;
    const int e = i & 63;
    float s = 0.0f;
    #pragma unroll 8
    for (int d = 0; d < 64; d++)
        s += wrf[m * 64 + d] * wkqv[c * 4096 + d * 64 + e];
    g_wc[i] = s;

    if (blockIdx.x == 0 && threadIdx.x < 64) {
        const int cc = threadIdx.x >> 5;
        const int mm = threadIdx.x & 31;
        float sb = 0.0f;
        #pragma unroll 8
        for (int d = 0; d < 64; d++)
            sb += wrf[mm * 64 + d] * bkqv[cc * 64 + d];
        g_bc[threadIdx.x] = sb;
    }
}

// ============================================================================
// Setup 2 (grid 54): pre-split all static weights into 144-B-row tiles
// ============================================================================
__global__ __launch_bounds__(256) void setup_split_kernel(
    const float* __restrict__ wkqv,
    const float* __restrict__ wfc1, const float* __restrict__ wfc2)
{
    const int i = blockIdx.x * 256 + threadIdx.x;
    if (i >= 13824) return;
    const int word = i % 36;
    const int rowg = i / 36;

    const float* src = 0;
    u32* dsth = 0;
    u32* dstl = 0;
    int row = 0, cols = 64;
    if (i < 6912) {               // wkqv
        src = wkqv; row = rowg;
        dsth = (u32*)g_wkh; dstl = (u32*)g_wkl;
    } else if (i < 9216) {        // wfc1
        src = wfc1; row = rowg - 192;
        dsth = (u32*)g_f1h; dstl = (u32*)g_f1l;
    } else if (i < 11520) {       // wfc2
        src = wfc2; row = rowg - 256;
        dsth = (u32*)g_f2h; dstl = (u32*)g_f2l;
    } else {                      // wc
        src = g_wc; row = rowg - 320;
        dsth = (u32*)g_wch; dstl = (u32*)g_wcl;
    }

    u32 hi = 0, lo = 0;
    if (word < 32) {
        const float2 wv = *(const float2*)(src + row * cols + word * 2);
        split_pair(wv.x, wv.y, hi, lo);
    }
    dsth[row * 36 + word] = hi;
    dstl[row * 36 + word] = lo;
}

// ============================================================================
// Pass 1 (unchanged from R12 winner)
// ============================================================================
#define Q1_AH  2048
#define Q1_AL  20480
#define Q1_BH  38912
#define Q1_BL  48128
#define Q1_B2H 57344
#define Q1_B2L 61952
#define P1_BYTES (66560 + 1024)

__global__ __launch_bounds__(128, 3) void pass1_kernel(
    const float* __restrict__ x,
    const float* __restrict__ ln1g, const float* __restrict__ ln1b,
    const float* __restrict__ bkqv)
{
    extern __shared__ char smem_raw[];
    char* smem = (char*)(((size_t)smem_raw + 1023) & ~(size_t)1023);
    float* cst = (float*)smem;

    const int tid  = threadIdx.x;
    const int w    = tid >> 5;
    const int lane = tid & 31;
    const int g    = lane >> 2;
    const int tig  = lane & 3;
    const int n0   = blockIdx.x * TILE;
    const int b    = n0 / L;
    const int l0   = n0 % L;

    if (tid < 64) {
        cst[16 + tid]  = ln1g[tid];
        cst[80 + tid]  = ln1b[tid];
        cst[336 + tid] = g_bc[tid];
    }
    for (int i = tid; i < 192; i += 128) cst[144 + i] = bkqv[i];

    const int l  = l0 + tid;
    const int dz = l / (DP * DP);
    const int hy = (l / DP) % DP;
    const int wx = l % DP;
    const float* xb = x + (size_t)b * S * S * S;
    float h[64];
    float sum = 0.0f, sq = 0.0f;
    #pragma unroll
    for (int kd = 0; kd < 4; kd++) {
        const int iz = 2 * dz - 1 + kd;
        const bool zok = (unsigned)iz < (unsigned)S;
        #pragma unroll
        for (int kh = 0; kh < 4; kh++) {
            const int iy = 2 * hy - 1 + kh;
            const bool yok = zok && ((unsigned)iy < (unsigned)S);
            #pragma unroll
            for (int kw = 0; kw < 4; kw++) {
                const int ix = 2 * wx - 1 + kw;
                const float v = (yok && (unsigned)ix < (unsigned)S)
                              ? xb[((size_t)iz * S + iy) * S + ix] : 0.0f;
                h[kd * 16 + kh * 4 + kw] = v;
                sum += v;
                sq += v * v;
            }
        }
    }
    const float mu  = sum * (1.0f / 64.0f);
    const float var = sq * (1.0f / 64.0f) - mu * mu;
    const float rs  = rsqrtf(var + 1e-5f);

    __syncthreads();
    #pragma unroll
    for (int f = 0; f < 64; f++)
        h[f] = (h[f] - mu) * rs * cst[16 + f] + cst[80 + f];
    store_row<64>(smem + Q1_AH, smem + Q1_AL, tid, h);

    const float rfscale = 0.1767766952966369f;

    for (int c = 0; c < 3; c++) {
        __syncthreads();
        stage_pre(smem + Q1_BH, smem + Q1_BL, g_wkh + c * 576, g_wkl + c * 576,
                  64, tid);
        if (c < 2)
            stage_pre(smem + Q1_B2H, smem + Q1_B2L, g_wch + c * 288,
                      g_wcl + c * 288, 32, tid);
        __syncthreads();

        float acc[2][8][4];
        #pragma unroll
        for (int mt = 0; mt < 2; mt++)
            #pragma unroll
            for (int nt = 0; nt < 8; nt++)
                #pragma unroll
                for (int i = 0; i < 4; i++) acc[mt][nt][i] = 0.0f;
        mma_tile<4, 8>(smem + Q1_AH, smem + Q1_AL, smem + Q1_BH, smem + Q1_BL,
                       acc, w, lane);
        add_bias<8>(acc, &cst[144 + c * 64], lane);

        if (c < 2) {
            float xd[2][2];
            #pragma unroll
            for (int mt = 0; mt < 2; mt++)
                #pragma unroll
                for (int hf = 0; hf < 2; hf++) {
                    float p = 0.0f;
                    #pragma unroll
                    for (int nt = 0; nt < 8; nt++) {
                        const float v0 = acc[mt][nt][2*hf];
                        const float v1 = acc[mt][nt][2*hf + 1];
                        p += v0 * v0 + v1 * v1;
                    }
                    xd[mt][hf] = 0.5f * qsum(p);
                }

            float ac2[2][4][4];
            #pragma unroll
            for (int mt = 0; mt < 2; mt++)
                #pragma unroll
                for (int nt = 0; nt < 4; nt++)
                    #pragma unroll
                    for (int i = 0; i < 4; i++) ac2[mt][nt][i] = 0.0f;
            mma_tile<4, 4>(smem + Q1_AH, smem + Q1_AL,
                           smem + Q1_B2H, smem + Q1_B2L, ac2, w, lane);
            add_bias<4>(ac2, &cst[336 + c * 32], lane);

            float* dst = (c == 0) ? g_kp : g_qp;
            #pragma unroll
            for (int mt = 0; mt < 2; mt++) {
                const int t0 = w * 32 + mt * 16 + g;
                #pragma unroll
                for (int nt = 0; nt < 4; nt++) {
                    const int col = nt * 8 + 2 * tig;
                    *(float2*)&dst[(size_t)(n0 + t0) * 32 + col] = make_float2(
                        __expf(ac2[mt][nt][0] - xd[mt][0]) * rfscale,
                        __expf(ac2[mt][nt][1] - xd[mt][0]) * rfscale);
                    *(float2*)&dst[(size_t)(n0 + t0 + 8) * 32 + col] = make_float2(
                        __expf(ac2[mt][nt][2] - xd[mt][1]) * rfscale,
                        __expf(ac2[mt][nt][3] - xd[mt][1]) * rfscale);
                }
            }
        } else {
            frag_to_gmem<8>(g_v, 64, acc, w, lane, n0);
        }
    }
}

// ============================================================================
// Reduce 1 v2: register-tiled (4e x 8m), 4-way token split, quad-shuffle merge
// thread: tq = t&3 (token quarter), u = t>>2; eb = (u>>2)*4, mb = (u&3)*8
// ============================================================================
__global__ __launch_bounds__(256) void reduce1_kernel()
{
    __shared__ float sv[64 * 65];   // [e][tt]
    __shared__ float sk[MRF * 65];  // [m][tt]

    const int b = blockIdx.y;
    const int c = blockIdx.x;
    const int t = threadIdx.x;
    const int n0 = b * L + c * 1024;

    const int tq = t & 3;
    const int u  = t >> 2;          // 0..63
    const int eb = (u >> 2) * 4;    // 0..60 step 4
    const int mb = (u & 3) * 8;     // 0,8,16,24

    float acc[4][8];
    #pragma unroll
    for (int i = 0; i < 4; i++)
        #pragma unroll
        for (int j = 0; j < 8; j++) acc[i][j] = 0.0f;
    float ks[8];
    #pragma unroll
    for (int j = 0; j < 8; j++) ks[j] = 0.0f;

    for (int tile = 0; tile < 16; tile++) {
        const int base = n0 + tile * 64;
        __syncthreads();
        for (int idx = t; idx < 1024; idx += 256) {
            const int tt = idx >> 4;
            const int eq = (idx & 15) * 4;
            const float4 vv = *(const float4*)&g_v[(size_t)(base + tt) * 64 + eq];
            sv[(eq+0)*65+tt] = vv.x;
            sv[(eq+1)*65+tt] = vv.y;
            sv[(eq+2)*65+tt] = vv.z;
            sv[(eq+3)*65+tt] = vv.w;
        }
        for (int idx = t; idx < 512; idx += 256) {
            const int tt = idx >> 3;
            const int mq = (idx & 7) * 4;
            const float4 kk = *(const float4*)&g_kp[(size_t)(base + tt) * 32 + mq];
            sk[(mq+0)*65+tt] = kk.x;
            sk[(mq+1)*65+tt] = kk.y;
            sk[(mq+2)*65+tt] = kk.z;
            sk[(mq+3)*65+tt] = kk.w;
        }
        __syncthreads();

        #pragma unroll 4
        for (int j = 0; j < 16; j++) {
            const int tt = tq * 16 + j;
            const float v0 = sv[(eb+0)*65+tt];
            const float v1 = sv[(eb+1)*65+tt];
            const float v2 = sv[(eb+2)*65+tt];
            const float v3 = sv[(eb+3)*65+tt];
            #pragma unroll
            for (int i = 0; i < 8; i++) {
                const float km = sk[(mb+i)*65+tt];
                acc[0][i] += v0 * km;
                acc[1][i] += v1 * km;
                acc[2][i] += v2 * km;
                acc[3][i] += v3 * km;
                if (u < 4) ks[i] += km;
            }
        }
    }

    // merge the 4 token-quarter partials within each lane quad
    const int slot = b * NCH + c;
    #pragma unroll
    for (int i = 0; i < 4; i++)
        #pragma unroll
        for (int j = 0; j < 8; j++) {
            float v = acc[i][j];
            v += __shfl_xor_sync(0xffffffffu, v, 1);
            v += __shfl_xor_sync(0xffffffffu, v, 2);
            if (tq == 0)
                g_part_kptv[slot * (64 * MRF) + (eb + i) * MRF + mb + j] = v;
        }
    if (u < 4) {
        #pragma unroll
        for (int j = 0; j < 8; j++) {
            float s = ks[j];
            s += __shfl_xor_sync(0xffffffffu, s, 1);
            s += __shfl_xor_sync(0xffffffffu, s, 2);
            if (tq == 0) g_part_ksum[slot * MRF + mb + j] = s;
        }
    }
}

// ============================================================================
// Reduce 2a (grid 32 x BATCH): chunk-parallel finalize kptv + ksum
// ============================================================================
__global__ __launch_bounds__(256) void reduce2a_kernel()
{
    const int b = blockIdx.y;
    const int t = threadIdx.x;
    const int e4   = t >> 2;
    const int part = t & 3;
    const int idx  = blockIdx.x * 64 + e4;

    float acc = 0.0f;
    const float* p = &g_part_kptv[b * NCH * 2048 + idx];
    for (int c = part; c < NCH; c += 4) acc += p[(size_t)c * 2048];
    acc += __shfl_xor_sync(0xffffffffu, acc, 1);
    acc += __shfl_xor_sync(0xffffffffu, acc, 2);
    if (part == 0) g_kptv[b * 2048 + idx] = acc;

    if (blockIdx.x == 0 && t < 128) {
        const int m = t >> 2;
        float s = 0.0f;
        const float* q = &g_part_ksum[b * NCH * MRF + m];
        for (int c = part; c < NCH; c += 4) s += q[(size_t)c * MRF];
        s += __shfl_xor_sync(0xffffffffu, s, 1);
        s += __shfl_xor_sync(0xffffffffu, s, 2);
        if (part == 0) g_ksum[b * MRF + m] = s;
    }
}

// ============================================================================
// Wc2 (grid 9 x BATCH): split-bf16 fused wproj@kptv^T
// ============================================================================
__global__ __launch_bounds__(256) void wc2_kernel(const float* __restrict__ wproj)
{
    const int b = blockIdx.y;
    const int i = blockIdx.x * 256 + threadIdx.x;
    if (i >= 2304) return;
    const int j = i / 36;
    const int word = i % 36;

    u32 hi = 0, lo = 0;
    if (word < 32) {
        const int m = word * 2;
        float s0 = 0.0f, s1 = 0.0f;
        #pragma unroll 8
        for (int e = 0; e < 64; e++) {
            const float wp = wproj[j * 64 + e];
            s0 += wp * g_kptv[b * 2048 + e * 32 + m];
            s1 += wp * g_kptv[b * 2048 + e * 32 + m + 1];
        }
        split_pair(s0, s1, hi, lo);
    }
    ((u32*)g_w2h)[b * 2304 + j * 36 + word] = hi;
    ((u32*)g_w2l)[b * 2304 + j * 36 + word] = lo;
}

// ============================================================================
// Pass 2 (unchanged from R12 winner)
// ============================================================================
#define Q2_AH 2048
#define Q2_AL 20480
#define Q2_BH 38912
#define Q2_BL 48128
#define P2_BYTES (57344 + 1024)

__global__ __launch_bounds__(128, 3) void pass2_kernel(
    const float* __restrict__ bproj,
    const float* __restrict__ ln2g,  const float* __restrict__ ln2b,
    const float* __restrict__ bfc1,  const float* __restrict__ bfc2,
    float* __restrict__ out)
{
    extern __shared__ char smem_raw[];
    char* smem = (char*)(((size_t)smem_raw + 1023) & ~(size_t)1023);
    float* cst = (float*)smem;

    const int tid  = threadIdx.x;
    const int w    = tid >> 5;
    const int lane = tid & 31;
    const int g    = lane >> 2;
    const int tig  = lane & 3;
    const int n0   = blockIdx.x * TILE;
    const int b    = n0 / L;

    if (tid < 64) {
        cst[16 + tid]  = bproj[tid];
        cst[80 + tid]  = ln2g[tid];
        cst[144 + tid] = ln2b[tid];
        cst[208 + tid] = bfc1[tid];
        cst[272 + tid] = bfc2[tid];
    }
    if (tid < 32) cst[336 + tid] = g_ksum[b * 32 + tid];
    stage_pre(smem + Q2_BH, smem + Q2_BL, g_w2h + b * 576, g_w2l + b * 576,
              64, tid);

    float qf[2][4][4];
    #pragma unroll
    for (int mt = 0; mt < 2; mt++) {
        const int t0 = w * 32 + mt * 16 + g;
        #pragma unroll
        for (int nt = 0; nt < 4; nt++) {
            const int col = nt * 8 + 2 * tig;
            const float2 a = *(const float2*)&g_qp[(size_t)(n0 + t0) * 32 + col];
            const float2 bb = *(const float2*)&g_qp[(size_t)(n0 + t0 + 8) * 32 + col];
            qf[mt][nt][0] = a.x;  qf[mt][nt][1] = a.y;
            qf[mt][nt][2] = bb.x; qf[mt][nt][3] = bb.y;
        }
    }
    __syncthreads();

    #pragma unroll
    for (int mt = 0; mt < 2; mt++)
        #pragma unroll
        for (int hf = 0; hf < 2; hf++) {
            float p = 0.0f;
            #pragma unroll
            for (int nt = 0; nt < 4; nt++) {
                const int col = nt * 8 + 2 * tig;
                p += qf[mt][nt][2*hf]     * cst[336 + col]
                   + qf[mt][nt][2*hf + 1] * cst[336 + col + 1];
            }
            const float invD = 1.0f / (qsum(p) + 1e-8f);
            #pragma unroll
            for (int nt = 0; nt < 4; nt++) {
                qf[mt][nt][2*hf]     *= invD;
                qf[mt][nt][2*hf + 1] *= invD;
            }
        }
    frag_to_A<4>(smem + Q2_AH, smem + Q2_AL, qf, w, lane);
    __syncthreads();

    float acc[2][8][4];
    #pragma unroll
    for (int mt = 0; mt < 2; mt++)
        #pragma unroll
        for (int nt = 0; nt < 8; nt++)
            #pragma unroll
            for (int i = 0; i < 4; i++) acc[mt][nt][i] = 0.0f;
    mma_tile<2, 8>(smem + Q2_AH, smem + Q2_AL, smem + Q2_BH, smem + Q2_BL,
                   acc, w, lane);
    add_bias<8>(acc, &cst[16], lane);

    float y[2][8][4];
    #pragma unroll
    for (int mt = 0; mt < 2; mt++) {
        const int t0 = w * 32 + mt * 16 + g;
        #pragma unroll
        for (int nt = 0; nt < 8; nt++) {
            const int col = nt * 8 + 2 * tig;
            const float2 va = *(const float2*)&g_v[(size_t)(n0 + t0) * 64 + col];
            const float2 vb = *(const float2*)&g_v[(size_t)(n0 + t0 + 8) * 64 + col];
            y[mt][nt][0] = acc[mt][nt][0] + va.x;
            y[mt][nt][1] = acc[mt][nt][1] + va.y;
            y[mt][nt][2] = acc[mt][nt][2] + vb.x;
            y[mt][nt][3] = acc[mt][nt][3] + vb.y;
        }
    }

    float nmu[2][2], rsg[2][2];
    #pragma unroll
    for (int mt = 0; mt < 2; mt++)
        #pragma unroll
        for (int hf = 0; hf < 2; hf++) {
            float p1 = 0.0f, p2 = 0.0f;
            #pragma unroll
            for (int nt = 0; nt < 8; nt++) {
                const float v0 = y[mt][nt][2*hf];
                const float v1 = y[mt][nt][2*hf + 1];
                p1 += v0 + v1;
                p2 += v0 * v0 + v1 * v1;
            }
            const float s1 = qsum(p1);
            const float s2 = qsum(p2);
            const float muv = s1 * (1.0f / 64.0f);
            const float var = s2 * (1.0f / 64.0f) - muv * muv;
            nmu[mt][hf] = -muv;
            rsg[mt][hf] = rsqrtf(var + 1e-5f);
        }

    __syncthreads();
    stage_pre(smem + Q2_BH, smem + Q2_BL, g_f1h, g_f1l, 64, tid);
    #pragma unroll
    for (int mt = 0; mt < 2; mt++) {
        const int t0 = w * 32 + mt * 16 + g;
        #pragma unroll
        for (int nt = 0; nt < 8; nt++) {
            const int col = nt * 8 + 2 * tig;
            const float2 gg = *(const float2*)&cst[80 + col];
            const float2 bb = *(const float2*)&cst[144 + col];
            const float z0 = (y[mt][nt][0] + nmu[mt][0]) * rsg[mt][0] * gg.x + bb.x;
            const float z1 = (y[mt][nt][1] + nmu[mt][0]) * rsg[mt][0] * gg.y + bb.y;
            const float z2 = (y[mt][nt][2] + nmu[mt][1]) * rsg[mt][1] * gg.x + bb.x;
            const float z3 = (y[mt][nt][3] + nmu[mt][1]) * rsg[mt][1] * gg.y + bb.y;
            u32 hi, lo;
            const int co = col * 2;
            split_pair(z0, z1, hi, lo);
            *(u32*)(smem + Q2_AH + t0 * 144 + co) = hi;
            *(u32*)(smem + Q2_AL + t0 * 144 + co) = lo;
            split_pair(z2, z3, hi, lo);
            *(u32*)(smem + Q2_AH + (t0 + 8) * 144 + co) = hi;
            *(u32*)(smem + Q2_AL + (t0 + 8) * 144 + co) = lo;
        }
    }
    __syncthreads();

    #pragma unroll
    for (int mt = 0; mt < 2; mt++)
        #pragma unroll
        for (int nt = 0; nt < 8; nt++)
            #pragma unroll
            for (int i = 0; i < 4; i++) acc[mt][nt][i] = 0.0f;
    mma_tile<4, 8>(smem + Q2_AH, smem + Q2_AL, smem + Q2_BH, smem + Q2_BL,
                   acc, w, lane);
    add_bias<8>(acc, &cst[208], lane);
    #pragma unroll
    for (int mt = 0; mt < 2; mt++)
        #pragma unroll
        for (int nt = 0; nt < 8; nt++)
            #pragma unroll
            for (int i = 0; i < 4; i++) {
                const float v = acc[mt][nt][i];
                acc[mt][nt][i] = 0.5f * v * (1.0f + erff(v * 0.7071067811865476f));
            }
    __syncthreads();
    stage_pre(smem + Q2_BH, smem + Q2_BL, g_f2h, g_f2l, 64, tid);
    frag_to_A<8>(smem + Q2_AH, smem + Q2_AL, acc, w, lane);
    __syncthreads();

    #pragma unroll
    for (int mt = 0; mt < 2; mt++)
        #pragma unroll
        for (int nt = 0; nt < 8; nt++)
            #pragma unroll
            for (int i = 0; i < 4; i++) acc[mt][nt][i] = 0.0f;
    mma_tile<4, 8>(smem + Q2_AH, smem + Q2_AL, smem + Q2_BH, smem + Q2_BL,
                   acc, w, lane);
    add_bias<8>(acc, &cst[272], lane);
    #pragma unroll
    for (int mt = 0; mt < 2; mt++) {
        const int t0 = w * 32 + mt * 16 + g;
        #pragma unroll
        for (int nt = 0; nt < 8; nt++) {
            const int col = nt * 8 + 2 * tig;
            *(float2*)&out[(size_t)(n0 + t0) * 64 + col] = make_float2(
                acc[mt][nt][0] + y[mt][nt][0], acc[mt][nt][1] + y[mt][nt][1]);
            *(float2*)&out[(size_t)(n0 + t0 + 8) * 64 + col] = make_float2(
                acc[mt][nt][2] + y[mt][nt][2], acc[mt][nt][3] + y[mt][nt][3]);
        }
    }
}

// ============================================================================
extern "C" void kernel_launch(void* const* d_in, const int* in_sizes, int n_in,
                              void* d_out, int out_size)
{
    const float* x     = (const float*)d_in[0];
    const float* ln1g  = (const float*)d_in[1];
    const float* ln1b  = (const float*)d_in[2];
    const float* wkqv  = (const float*)d_in[3];
    const float* bkqv  = (const float*)d_in[4];
    const float* wproj = (const float*)d_in[5];
    const float* bproj = (const float*)d_in[6];
    const float* ln2g  = (const float*)d_in[7];
    const float* ln2b  = (const float*)d_in[8];
    const float* wfc1  = (const float*)d_in[9];
    const float* bfc1  = (const float*)d_in[10];
    const float* wfc2  = (const float*)d_in[11];
    const float* bfc2  = (const float*)d_in[12];
    const float* wrf   = (const float*)d_in[13];

    cudaFuncSetAttribute(pass1_kernel, cudaFuncAttributeMaxDynamicSharedMemorySize, P1_BYTES);
    cudaFuncSetAttribute(pass2_kernel, cudaFuncAttributeMaxDynamicSharedMemorySize, P2_BYTES);

    setup_kernel<<<16, 256>>>(wkqv, bkqv, wrf);
    setup_split_kernel<<<54, 256>>>(wkqv, wfc1, wfc2);
    pass1_kernel<<<NBLK, 128, P1_BYTES>>>(x, ln1g, ln1b, bkqv);
    reduce1_kernel<<<dim3(NCH, BATCH), 256>>>();
    reduce2a_kernel<<<dim3(32, BATCH), 256>>>();
    wc2_kernel<<<dim3(9, BATCH), 256>>>(wproj);
    pass2_kernel<<<NBLK, 128, P2_BYTES>>>(bproj, ln2g, ln2b,
                                          bfc1, bfc2, (float*)d_out);
}

// round 16
// speedup vs baseline: 2.2957x; 1.0650x over previous
#include <cuda_runtime.h>
#include <cuda_bf16.h>
#include <stdint.h>
#include <math.h>

#define BATCH 4
#define S 96
#define DP 48
#define L (DP*DP*DP)            // 110592
#define NTOK (BATCH*L)          // 442368
#define MRF 32
#define NCH 108
#define NCH4 (NCH*4)            // 432 partial chunks (token-quarter split)
#define TILE 128
#define NBLK (NTOK/TILE)        // 3456

typedef unsigned int u32;

// ---------------- scratch (token-major) ----------------
__device__ float g_kp[(size_t)NTOK * MRF];        // [tok][m]
__device__ float g_qp[(size_t)NTOK * MRF];        // [tok][m]
__device__ float g_v [(size_t)NTOK * 64];         // [tok][e]
__device__ float g_part_kptv[BATCH * NCH4 * 64 * MRF];
__device__ float g_part_ksum[BATCH * NCH4 * MRF];
__device__ float g_kptv[BATCH * 64 * MRF];        // [b][e][m]
__device__ float g_ksum[BATCH * MRF];
__device__ float g_wc[2 * 32 * 64];               // fused wrf@W{k,q}  [c][m][e]
__device__ float g_bc[2 * 32];                    // fused wrf@b{k,q}

// pre-split bf16 weight tiles, 144-B rows (36 u32/row), uint4-aligned
__device__ uint4 g_wkh[3 * 64 * 9], g_wkl[3 * 64 * 9];   // wkqv k/q/v
__device__ uint4 g_wch[2 * 32 * 9], g_wcl[2 * 32 * 9];   // fused RF (32 rows)
__device__ uint4 g_f1h[64 * 9],     g_f1l[64 * 9];       // wfc1
__device__ uint4 g_f2h[64 * 9],     g_f2l[64 * 9];       // wfc2
__device__ uint4 g_w2h[BATCH * 64 * 9], g_w2l[BATCH * 64 * 9];  // fused wproj@kptv^T

// ============================================================================
// mma.sync m16n8k16 bf16 core. A tiles [128][72] bf16, 144-B rows, no swizzle.
// ============================================================================
__device__ __forceinline__ void mma16816(float* c, const u32* a, u32 b0, u32 b1) {
    asm volatile(
        "mma.sync.aligned.m16n8k16.row.col.f32.bf16.bf16.f32 "
        "{%0,%1,%2,%3}, {%4,%5,%6,%7}, {%8,%9}, {%0,%1,%2,%3};"
        : "+f"(c[0]), "+f"(c[1]), "+f"(c[2]), "+f"(c[3])
        : "r"(a[0]), "r"(a[1]), "r"(a[2]), "r"(a[3]), "r"(b0), "r"(b1));
}

// 3-term split: Ahi*Bhi + Alo*Bhi + Ahi*Blo.
template<int KSTEPS, int NT>
__device__ __forceinline__ void mma_tile(
    const char* ah, const char* al,
    const char* bh, const char* bl,
    float (&acc)[2][NT][4], int w, int lane)
{
    const int g = lane >> 2;
    const int tig = lane & 3;
    #pragma unroll
    for (int ks = 0; ks < KSTEPS; ks++) {
        const int coff = ks * 32 + tig * 4;
        u32 Ah[2][4], Al[2][4];
        #pragma unroll
        for (int mt = 0; mt < 2; mt++) {
            const int r0 = (w * 32 + mt * 16 + g) * 144 + coff;
            const int r8 = r0 + 8 * 144;
            Ah[mt][0] = *(const u32*)(ah + r0);
            Ah[mt][1] = *(const u32*)(ah + r8);
            Ah[mt][2] = *(const u32*)(ah + r0 + 16);
            Ah[mt][3] = *(const u32*)(ah + r8 + 16);
            Al[mt][0] = *(const u32*)(al + r0);
            Al[mt][1] = *(const u32*)(al + r8);
            Al[mt][2] = *(const u32*)(al + r0 + 16);
            Al[mt][3] = *(const u32*)(al + r8 + 16);
        }
        #pragma unroll
        for (int nt = 0; nt < NT; nt++) {
            const int bo = (nt * 8 + g) * 144 + coff;
            const u32 Bh0 = *(const u32*)(bh + bo);
            const u32 Bh1 = *(const u32*)(bh + bo + 16);
            const u32 Bl0 = *(const u32*)(bl + bo);
            const u32 Bl1 = *(const u32*)(bl + bo + 16);
            #pragma unroll
            for (int mt = 0; mt < 2; mt++) {
                mma16816(acc[mt][nt], Ah[mt], Bh0, Bh1);
                mma16816(acc[mt][nt], Al[mt], Bh0, Bh1);
                mma16816(acc[mt][nt], Ah[mt], Bl0, Bl1);
            }
        }
    }
}

__device__ __forceinline__ float qsum(float v) {
    v += __shfl_xor_sync(0xffffffffu, v, 1);
    v += __shfl_xor_sync(0xffffffffu, v, 2);
    return v;
}

__device__ __forceinline__ void split_pair(float x0, float x1, u32& hi, u32& lo) {
    __nv_bfloat16 h0 = __float2bfloat16_rn(x0);
    __nv_bfloat16 h1 = __float2bfloat16_rn(x1);
    float r0 = x0 - __bfloat162float(h0);
    float r1 = x1 - __bfloat162float(h1);
    __nv_bfloat16 l0 = __float2bfloat16_rn(r0);
    __nv_bfloat16 l1 = __float2bfloat16_rn(r1);
    __nv_bfloat162 hh = __halves2bfloat162(h0, h1);
    __nv_bfloat162 ll = __halves2bfloat162(l0, l1);
    hi = *(u32*)&hh;
    lo = *(u32*)&ll;
}

template<int NT>
__device__ __forceinline__ void frag_to_A(char* ah, char* al,
                                          const float (&acc)[2][NT][4],
                                          int w, int lane) {
    const int g = lane >> 2, tig = lane & 3;
    #pragma unroll
    for (int mt = 0; mt < 2; mt++) {
        const int t0 = w * 32 + mt * 16 + g;
        #pragma unroll
        for (int nt = 0; nt < NT; nt++) {
            const int co = (nt * 8 + 2 * tig) * 2;
            u32 hi, lo;
            split_pair(acc[mt][nt][0], acc[mt][nt][1], hi, lo);
            *(u32*)(ah + t0 * 144 + co) = hi;
            *(u32*)(al + t0 * 144 + co) = lo;
            split_pair(acc[mt][nt][2], acc[mt][nt][3], hi, lo);
            *(u32*)(ah + (t0 + 8) * 144 + co) = hi;
            *(u32*)(al + (t0 + 8) * 144 + co) = lo;
        }
    }
}

template<int NT>
__device__ __forceinline__ void frag_to_gmem(float* dst, int C,
                                             const float (&acc)[2][NT][4],
                                             int w, int lane, int n0) {
    const int g = lane >> 2, tig = lane & 3;
    #pragma unroll
    for (int mt = 0; mt < 2; mt++) {
        const int t0 = w * 32 + mt * 16 + g;
        #pragma unroll
        for (int nt = 0; nt < NT; nt++) {
            const int col = nt * 8 + 2 * tig;
            *(float2*)&dst[(size_t)(n0 + t0) * C + col] =
                make_float2(acc[mt][nt][0], acc[mt][nt][1]);
            *(float2*)&dst[(size_t)(n0 + t0 + 8) * C + col] =
                make_float2(acc[mt][nt][2], acc[mt][nt][3]);
        }
    }
}

template<int NT>
__device__ __forceinline__ void add_bias(float (&acc)[2][NT][4],
                                         const float* bias, int lane) {
    const int tig = lane & 3;
    #pragma unroll
    for (int nt = 0; nt < NT; nt++) {
        const float2 bb = *(const float2*)&bias[nt * 8 + 2 * tig];
        #pragma unroll
        for (int mt = 0; mt < 2; mt++) {
            acc[mt][nt][0] += bb.x;
            acc[mt][nt][1] += bb.y;
            acc[mt][nt][2] += bb.x;
            acc[mt][nt][3] += bb.y;
        }
    }
}

template<int NE>
__device__ __forceinline__ void store_row(char* ahi, char* alo, int row,
                                          const float* v) {
    #pragma unroll
    for (int ch = 0; ch < NE / 8; ch++) {
        u32 h0, l0, h1, l1, h2, l2, h3, l3;
        split_pair(v[ch*8+0], v[ch*8+1], h0, l0);
        split_pair(v[ch*8+2], v[ch*8+3], h1, l1);
        split_pair(v[ch*8+4], v[ch*8+5], h2, l2);
        split_pair(v[ch*8+6], v[ch*8+7], h3, l3);
        const int off = row * 144 + ch * 16;
        *(uint4*)(ahi + off) = make_uint4(h0, h1, h2, h3);
        *(uint4*)(alo + off) = make_uint4(l0, l1, l2, l3);
    }
}

// copy pre-split tile (rows*9 uint4 each for hi/lo) gmem -> smem
__device__ __forceinline__ void stage_pre(char* dh, char* dl,
                                          const uint4* __restrict__ gh,
                                          const uint4* __restrict__ gl,
                                          int rows, int tid) {
    uint4* sh = (uint4*)dh;
    uint4* sl = (uint4*)dl;
    const int n = rows * 9;
    for (int p = tid; p < n; p += 128) {
        sh[p] = gh[p];
        sl[p] = gl[p];
    }
}

// ============================================================================
// Setup 1 (grid 16): Wc = wrf @ W{k,q}, bc = wrf @ b{k,q}
// ============================================================================
__global__ __launch_bounds__(256) void setup_kernel(
    const float* __restrict__ wkqv, const float* __restrict__ bkqv,
    const float* __restrict__ wrf)
{
    const int i = blockIdx.x * 256 + threadIdx.x;   // 0..4095
    const int c = i >> 11;
    const int m = (i >> 6) & 31;
    const int e = i & 63;
    float s = 0.0f;
    #pragma unroll 8
    for (int d = 0; d < 64; d++)
        s += wrf[m * 64 + d] * wkqv[c * 4096 + d * 64 + e];
    g_wc[i] = s;

    if (blockIdx.x == 0 && threadIdx.x < 64) {
        const int cc = threadIdx.x >> 5;
        const int mm = threadIdx.x & 31;
        float sb = 0.0f;
        #pragma unroll 8
        for (int d = 0; d < 64; d++)
            sb += wrf[mm * 64 + d] * bkqv[cc * 64 + d];
        g_bc[threadIdx.x] = sb;
    }
}

// ============================================================================
// Setup 2 (grid 54): pre-split all static weights into 144-B-row tiles
// ============================================================================
__global__ __launch_bounds__(256) void setup_split_kernel(
    const float* __restrict__ wkqv,
    const float* __restrict__ wfc1, const float* __restrict__ wfc2)
{
    const int i = blockIdx.x * 256 + threadIdx.x;
    if (i >= 13824) return;
    const int word = i % 36;
    const int rowg = i / 36;

    const float* src = 0;
    u32* dsth = 0;
    u32* dstl = 0;
    int row = 0, cols = 64;
    if (i < 6912) {               // wkqv
        src = wkqv; row = rowg;
        dsth = (u32*)g_wkh; dstl = (u32*)g_wkl;
    } else if (i < 9216) {        // wfc1
        src = wfc1; row = rowg - 192;
        dsth = (u32*)g_f1h; dstl = (u32*)g_f1l;
    } else if (i < 11520) {       // wfc2
        src = wfc2; row = rowg - 256;
        dsth = (u32*)g_f2h; dstl = (u32*)g_f2l;
    } else {                      // wc
        src = g_wc; row = rowg - 320;
        dsth = (u32*)g_wch; dstl = (u32*)g_wcl;
    }

    u32 hi = 0, lo = 0;
    if (word < 32) {
        const float2 wv = *(const float2*)(src + row * cols + word * 2);
        split_pair(wv.x, wv.y, hi, lo);
    }
    dsth[row * 36 + word] = hi;
    dstl[row * 36 + word] = lo;
}

// ============================================================================
// Pass 1 (unchanged from R13 winner)
// ============================================================================
#define Q1_AH  2048
#define Q1_AL  20480
#define Q1_BH  38912
#define Q1_BL  48128
#define Q1_B2H 57344
#define Q1_B2L 61952
#define P1_BYTES (66560 + 1024)

__global__ __launch_bounds__(128, 3) void pass1_kernel(
    const float* __restrict__ x,
    const float* __restrict__ ln1g, const float* __restrict__ ln1b,
    const float* __restrict__ bkqv)
{
    extern __shared__ char smem_raw[];
    char* smem = (char*)(((size_t)smem_raw + 1023) & ~(size_t)1023);
    float* cst = (float*)smem;

    const int tid  = threadIdx.x;
    const int w    = tid >> 5;
    const int lane = tid & 31;
    const int g    = lane >> 2;
    const int tig  = lane & 3;
    const int n0   = blockIdx.x * TILE;
    const int b    = n0 / L;
    const int l0   = n0 % L;

    if (tid < 64) {
        cst[16 + tid]  = ln1g[tid];
        cst[80 + tid]  = ln1b[tid];
        cst[336 + tid] = g_bc[tid];
    }
    for (int i = tid; i < 192; i += 128) cst[144 + i] = bkqv[i];

    const int l  = l0 + tid;
    const int dz = l / (DP * DP);
    const int hy = (l / DP) % DP;
    const int wx = l % DP;
    const float* xb = x + (size_t)b * S * S * S;
    float h[64];
    float sum = 0.0f, sq = 0.0f;
    #pragma unroll
    for (int kd = 0; kd < 4; kd++) {
        const int iz = 2 * dz - 1 + kd;
        const bool zok = (unsigned)iz < (unsigned)S;
        #pragma unroll
        for (int kh = 0; kh < 4; kh++) {
            const int iy = 2 * hy - 1 + kh;
            const bool yok = zok && ((unsigned)iy < (unsigned)S);
            #pragma unroll
            for (int kw = 0; kw < 4; kw++) {
                const int ix = 2 * wx - 1 + kw;
                const float v = (yok && (unsigned)ix < (unsigned)S)
                              ? xb[((size_t)iz * S + iy) * S + ix] : 0.0f;
                h[kd * 16 + kh * 4 + kw] = v;
                sum += v;
                sq += v * v;
            }
        }
    }
    const float mu  = sum * (1.0f / 64.0f);
    const float var = sq * (1.0f / 64.0f) - mu * mu;
    const float rs  = rsqrtf(var + 1e-5f);

    __syncthreads();
    #pragma unroll
    for (int f = 0; f < 64; f++)
        h[f] = (h[f] - mu) * rs * cst[16 + f] + cst[80 + f];
    store_row<64>(smem + Q1_AH, smem + Q1_AL, tid, h);

    const float rfscale = 0.1767766952966369f;

    for (int c = 0; c < 3; c++) {
        __syncthreads();
        stage_pre(smem + Q1_BH, smem + Q1_BL, g_wkh + c * 576, g_wkl + c * 576,
                  64, tid);
        if (c < 2)
            stage_pre(smem + Q1_B2H, smem + Q1_B2L, g_wch + c * 288,
                      g_wcl + c * 288, 32, tid);
        __syncthreads();

        float acc[2][8][4];
        #pragma unroll
        for (int mt = 0; mt < 2; mt++)
            #pragma unroll
            for (int nt = 0; nt < 8; nt++)
                #pragma unroll
                for (int i = 0; i < 4; i++) acc[mt][nt][i] = 0.0f;
        mma_tile<4, 8>(smem + Q1_AH, smem + Q1_AL, smem + Q1_BH, smem + Q1_BL,
                       acc, w, lane);
        add_bias<8>(acc, &cst[144 + c * 64], lane);

        if (c < 2) {
            float xd[2][2];
            #pragma unroll
            for (int mt = 0; mt < 2; mt++)
                #pragma unroll
                for (int hf = 0; hf < 2; hf++) {
                    float p = 0.0f;
                    #pragma unroll
                    for (int nt = 0; nt < 8; nt++) {
                        const float v0 = acc[mt][nt][2*hf];
                        const float v1 = acc[mt][nt][2*hf + 1];
                        p += v0 * v0 + v1 * v1;
                    }
                    xd[mt][hf] = 0.5f * qsum(p);
                }

            float ac2[2][4][4];
            #pragma unroll
            for (int mt = 0; mt < 2; mt++)
                #pragma unroll
                for (int nt = 0; nt < 4; nt++)
                    #pragma unroll
                    for (int i = 0; i < 4; i++) ac2[mt][nt][i] = 0.0f;
            mma_tile<4, 4>(smem + Q1_AH, smem + Q1_AL,
                           smem + Q1_B2H, smem + Q1_B2L, ac2, w, lane);
            add_bias<4>(ac2, &cst[336 + c * 32], lane);

            float* dst = (c == 0) ? g_kp : g_qp;
            #pragma unroll
            for (int mt = 0; mt < 2; mt++) {
                const int t0 = w * 32 + mt * 16 + g;
                #pragma unroll
                for (int nt = 0; nt < 4; nt++) {
                    const int col = nt * 8 + 2 * tig;
                    *(float2*)&dst[(size_t)(n0 + t0) * 32 + col] = make_float2(
                        __expf(ac2[mt][nt][0] - xd[mt][0]) * rfscale,
                        __expf(ac2[mt][nt][1] - xd[mt][0]) * rfscale);
                    *(float2*)&dst[(size_t)(n0 + t0 + 8) * 32 + col] = make_float2(
                        __expf(ac2[mt][nt][2] - xd[mt][1]) * rfscale,
                        __expf(ac2[mt][nt][3] - xd[mt][1]) * rfscale);
                }
            }
        } else {
            frag_to_gmem<8>(g_v, 64, acc, w, lane, n0);
        }
    }
}

// ============================================================================
// Reduce 1 v3: token-major smem tiles, conflict-free float4 loads.
// tq = t>>6 (token quarter; whole warps share a token row), u = t&63,
// e4 = (u&15)*4, mb = (u>>4)*8. Partials per (chunk, tq) -> NCH4 slots.
// ============================================================================
__global__ __launch_bounds__(256) void reduce1_kernel()
{
    __shared__ float sv[64 * 68];   // [token][e], pad 68
    __shared__ float sk[64 * 36];   // [token][m], pad 36

    const int b = blockIdx.y;
    const int c = blockIdx.x;
    const int t = threadIdx.x;
    const int n0 = b * L + c * 1024;

    const int tq = t >> 6;          // 0..3
    const int u  = t & 63;
    const int e4 = (u & 15) * 4;    // 0..60
    const int mb = (u >> 4) * 8;    // 0,8,16,24
    const bool do_ks = ((u & 15) == 0);

    float acc[4][8];
    #pragma unroll
    for (int i = 0; i < 4; i++)
        #pragma unroll
        for (int j = 0; j < 8; j++) acc[i][j] = 0.0f;
    float ks[8];
    #pragma unroll
    for (int j = 0; j < 8; j++) ks[j] = 0.0f;

    for (int tile = 0; tile < 16; tile++) {
        const int base = n0 + tile * 64;
        __syncthreads();
        for (int idx = t; idx < 1024; idx += 256) {
            const int tt = idx >> 4;
            const int eq = (idx & 15) * 4;
            *(float4*)&sv[tt * 68 + eq] =
                *(const float4*)&g_v[(size_t)(base + tt) * 64 + eq];
        }
        for (int idx = t; idx < 512; idx += 256) {
            const int tt = idx >> 3;
            const int mq = (idx & 7) * 4;
            *(float4*)&sk[tt * 36 + mq] =
                *(const float4*)&g_kp[(size_t)(base + tt) * 32 + mq];
        }
        __syncthreads();

        #pragma unroll 4
        for (int j = 0; j < 16; j++) {
            const int tt = tq * 16 + j;
            const float4 v4 = *(const float4*)&sv[tt * 68 + e4];
            const float4 k0 = *(const float4*)&sk[tt * 36 + mb];
            const float4 k1 = *(const float4*)&sk[tt * 36 + mb + 4];
            const float km[8] = {k0.x, k0.y, k0.z, k0.w, k1.x, k1.y, k1.z, k1.w};
            #pragma unroll
            for (int jj = 0; jj < 8; jj++) {
                acc[0][jj] += v4.x * km[jj];
                acc[1][jj] += v4.y * km[jj];
                acc[2][jj] += v4.z * km[jj];
                acc[3][jj] += v4.w * km[jj];
            }
            if (do_ks) {
                #pragma unroll
                for (int jj = 0; jj < 8; jj++) ks[jj] += km[jj];
            }
        }
    }

    const int slot = (b * NCH + c) * 4 + tq;
    #pragma unroll
    for (int i = 0; i < 4; i++) {
        float* p = &g_part_kptv[(size_t)slot * 2048 + (e4 + i) * 32 + mb];
        *(float4*)p       = make_float4(acc[i][0], acc[i][1], acc[i][2], acc[i][3]);
        *(float4*)(p + 4) = make_float4(acc[i][4], acc[i][5], acc[i][6], acc[i][7]);
    }
    if (do_ks) {
        float* p = &g_part_ksum[(size_t)slot * 32 + mb];
        *(float4*)p       = make_float4(ks[0], ks[1], ks[2], ks[3]);
        *(float4*)(p + 4) = make_float4(ks[4], ks[5], ks[6], ks[7]);
    }
}

// ============================================================================
// Reduce 2a (grid 32 x BATCH): chunk-parallel finalize kptv + ksum (NCH4)
// ============================================================================
__global__ __launch_bounds__(256) void reduce2a_kernel()
{
    const int b = blockIdx.y;
    const int t = threadIdx.x;
    const int e4   = t >> 2;
    const int part = t & 3;
    const int idx  = blockIdx.x * 64 + e4;

    float acc = 0.0f;
    const float* p = &g_part_kptv[(size_t)b * NCH4 * 2048 + idx];
    for (int c = part; c < NCH4; c += 4) acc += p[(size_t)c * 2048];
    acc += __shfl_xor_sync(0xffffffffu, acc, 1);
    acc += __shfl_xor_sync(0xffffffffu, acc, 2);
    if (part == 0) g_kptv[b * 2048 + idx] = acc;

    if (blockIdx.x == 0 && t < 128) {
        const int m = t >> 2;
        float s = 0.0f;
        const float* q = &g_part_ksum[(size_t)b * NCH4 * MRF + m];
        for (int c = part; c < NCH4; c += 4) s += q[(size_t)c * MRF];
        s += __shfl_xor_sync(0xffffffffu, s, 1);
        s += __shfl_xor_sync(0xffffffffu, s, 2);
        if (part == 0) g_ksum[b * MRF + m] = s;
    }
}

// ============================================================================
// Wc2 (grid 9 x BATCH): split-bf16 fused wproj@kptv^T
// ============================================================================
__global__ __launch_bounds__(256) void wc2_kernel(const float* __restrict__ wproj)
{
    const int b = blockIdx.y;
    const int i = blockIdx.x * 256 + threadIdx.x;
    if (i >= 2304) return;
    const int j = i / 36;
    const int word = i % 36;

    u32 hi = 0, lo = 0;
    if (word < 32) {
        const int m = word * 2;
        float s0 = 0.0f, s1 = 0.0f;
        #pragma unroll 8
        for (int e = 0; e < 64; e++) {
            const float wp = wproj[j * 64 + e];
            s0 += wp * g_kptv[b * 2048 + e * 32 + m];
            s1 += wp * g_kptv[b * 2048 + e * 32 + m + 1];
        }
        split_pair(s0, s1, hi, lo);
    }
    ((u32*)g_w2h)[b * 2304 + j * 36 + word] = hi;
    ((u32*)g_w2l)[b * 2304 + j * 36 + word] = lo;
}

// ============================================================================
// Pass 2 (unchanged from R13 winner)
// ============================================================================
#define Q2_AH 2048
#define Q2_AL 20480
#define Q2_BH 38912
#define Q2_BL 48128
#define P2_BYTES (57344 + 1024)

__global__ __launch_bounds__(128, 3) void pass2_kernel(
    const float* __restrict__ bproj,
    const float* __restrict__ ln2g,  const float* __restrict__ ln2b,
    const float* __restrict__ bfc1,  const float* __restrict__ bfc2,
    float* __restrict__ out)
{
    extern __shared__ char smem_raw[];
    char* smem = (char*)(((size_t)smem_raw + 1023) & ~(size_t)1023);
    float* cst = (float*)smem;

    const int tid  = threadIdx.x;
    const int w    = tid >> 5;
    const int lane = tid & 31;
    const int g    = lane >> 2;
    const int tig  = lane & 3;
    const int n0   = blockIdx.x * TILE;
    const int b    = n0 / L;

    if (tid < 64) {
        cst[16 + tid]  = bproj[tid];
        cst[80 + tid]  = ln2g[tid];
        cst[144 + tid] = ln2b[tid];
        cst[208 + tid] = bfc1[tid];
        cst[272 + tid] = bfc2[tid];
    }
    if (tid < 32) cst[336 + tid] = g_ksum[b * 32 + tid];
    stage_pre(smem + Q2_BH, smem + Q2_BL, g_w2h + b * 576, g_w2l + b * 576,
              64, tid);

    float qf[2][4][4];
    #pragma unroll
    for (int mt = 0; mt < 2; mt++) {
        const int t0 = w * 32 + mt * 16 + g;
        #pragma unroll
        for (int nt = 0; nt < 4; nt++) {
            const int col = nt * 8 + 2 * tig;
            const float2 a = *(const float2*)&g_qp[(size_t)(n0 + t0) * 32 + col];
            const float2 bb = *(const float2*)&g_qp[(size_t)(n0 + t0 + 8) * 32 + col];
            qf[mt][nt][0] = a.x;  qf[mt][nt][1] = a.y;
            qf[mt][nt][2] = bb.x; qf[mt][nt][3] = bb.y;
        }
    }
    __syncthreads();

    #pragma unroll
    for (int mt = 0; mt < 2; mt++)
        #pragma unroll
        for (int hf = 0; hf < 2; hf++) {
            float p = 0.0f;
            #pragma unroll
            for (int nt = 0; nt < 4; nt++) {
                const int col = nt * 8 + 2 * tig;
                p += qf[mt][nt][2*hf]     * cst[336 + col]
                   + qf[mt][nt][2*hf + 1] * cst[336 + col + 1];
            }
            const float invD = 1.0f / (qsum(p) + 1e-8f);
            #pragma unroll
            for (int nt = 0; nt < 4; nt++) {
                qf[mt][nt][2*hf]     *= invD;
                qf[mt][nt][2*hf + 1] *= invD;
            }
        }
    frag_to_A<4>(smem + Q2_AH, smem + Q2_AL, qf, w, lane);
    __syncthreads();

    float acc[2][8][4];
    #pragma unroll
    for (int mt = 0; mt < 2; mt++)
        #pragma unroll
        for (int nt = 0; nt < 8; nt++)
            #pragma unroll
            for (int i = 0; i < 4; i++) acc[mt][nt][i] = 0.0f;
    mma_tile<2, 8>(smem + Q2_AH, smem + Q2_AL, smem + Q2_BH, smem + Q2_BL,
                   acc, w, lane);
    add_bias<8>(acc, &cst[16], lane);

    float y[2][8][4];
    #pragma unroll
    for (int mt = 0; mt < 2; mt++) {
        const int t0 = w * 32 + mt * 16 + g;
        #pragma unroll
        for (int nt = 0; nt < 8; nt++) {
            const int col = nt * 8 + 2 * tig;
            const float2 va = *(const float2*)&g_v[(size_t)(n0 + t0) * 64 + col];
            const float2 vb = *(const float2*)&g_v[(size_t)(n0 + t0 + 8) * 64 + col];
            y[mt][nt][0] = acc[mt][nt][0] + va.x;
            y[mt][nt][1] = acc[mt][nt][1] + va.y;
            y[mt][nt][2] = acc[mt][nt][2] + vb.x;
            y[mt][nt][3] = acc[mt][nt][3] + vb.y;
        }
    }

    float nmu[2][2], rsg[2][2];
    #pragma unroll
    for (int mt = 0; mt < 2; mt++)
        #pragma unroll
        for (int hf = 0; hf < 2; hf++) {
            float p1 = 0.0f, p2 = 0.0f;
            #pragma unroll
            for (int nt = 0; nt < 8; nt++) {
                const float v0 = y[mt][nt][2*hf];
                const float v1 = y[mt][nt][2*hf + 1];
                p1 += v0 + v1;
                p2 += v0 * v0 + v1 * v1;
            }
            const float s1 = qsum(p1);
            const float s2 = qsum(p2);
            const float muv = s1 * (1.0f / 64.0f);
            const float var = s2 * (1.0f / 64.0f) - muv * muv;
            nmu[mt][hf] = -muv;
            rsg[mt][hf] = rsqrtf(var + 1e-5f);
        }

    __syncthreads();
    stage_pre(smem + Q2_BH, smem + Q2_BL, g_f1h, g_f1l, 64, tid);
    #pragma unroll
    for (int mt = 0; mt < 2; mt++) {
        const int t0 = w * 32 + mt * 16 + g;
        #pragma unroll
        for (int nt = 0; nt < 8; nt++) {
            const int col = nt * 8 + 2 * tig;
            const float2 gg = *(const float2*)&cst[80 + col];
            const float2 bb = *(const float2*)&cst[144 + col];
            const float z0 = (y[mt][nt][0] + nmu[mt][0]) * rsg[mt][0] * gg.x + bb.x;
            const float z1 = (y[mt][nt][1] + nmu[mt][0]) * rsg[mt][0] * gg.y + bb.y;
            const float z2 = (y[mt][nt][2] + nmu[mt][1]) * rsg[mt][1] * gg.x + bb.x;
            const float z3 = (y[mt][nt][3] + nmu[mt][1]) * rsg[mt][1] * gg.y + bb.y;
            u32 hi, lo;
            const int co = col * 2;
            split_pair(z0, z1, hi, lo);
            *(u32*)(smem + Q2_AH + t0 * 144 + co) = hi;
            *(u32*)(smem + Q2_AL + t0 * 144 + co) = lo;
            split_pair(z2, z3, hi, lo);
            *(u32*)(smem + Q2_AH + (t0 + 8) * 144 + co) = hi;
            *(u32*)(smem + Q2_AL + (t0 + 8) * 144 + co) = lo;
        }
    }
    __syncthreads();

    #pragma unroll
    for (int mt = 0; mt < 2; mt++)
        #pragma unroll
        for (int nt = 0; nt < 8; nt++)
            #pragma unroll
            for (int i = 0; i < 4; i++) acc[mt][nt][i] = 0.0f;
    mma_tile<4, 8>(smem + Q2_AH, smem + Q2_AL, smem + Q2_BH, smem + Q2_BL,
                   acc, w, lane);
    add_bias<8>(acc, &cst[208], lane);
    #pragma unroll
    for (int mt = 0; mt < 2; mt++)
        #pragma unroll
        for (int nt = 0; nt < 8; nt++)
            #pragma unroll
            for (int i = 0; i < 4; i++) {
                const float v = acc[mt][nt][i];
                acc[mt][nt][i] = 0.5f * v * (1.0f + erff(v * 0.7071067811865476f));
            }
    __syncthreads();
    stage_pre(smem + Q2_BH, smem + Q2_BL, g_f2h, g_f2l, 64, tid);
    frag_to_A<8>(smem + Q2_AH, smem + Q2_AL, acc, w, lane);
    __syncthreads();

    #pragma unroll
    for (int mt = 0; mt < 2; mt++)
        #pragma unroll
        for (int nt = 0; nt < 8; nt++)
            #pragma unroll
            for (int i = 0; i < 4; i++) acc[mt][nt][i] = 0.0f;
    mma_tile<4, 8>(smem + Q2_AH, smem + Q2_AL, smem + Q2_BH, smem + Q2_BL,
                   acc, w, lane);
    add_bias<8>(acc, &cst[272], lane);
    #pragma unroll
    for (int mt = 0; mt < 2; mt++) {
        const int t0 = w * 32 + mt * 16 + g;
        #pragma unroll
        for (int nt = 0; nt < 8; nt++) {
            const int col = nt * 8 + 2 * tig;
            *(float2*)&out[(size_t)(n0 + t0) * 64 + col] = make_float2(
                acc[mt][nt][0] + y[mt][nt][0], acc[mt][nt][1] + y[mt][nt][1]);
            *(float2*)&out[(size_t)(n0 + t0 + 8) * 64 + col] = make_float2(
                acc[mt][nt][2] + y[mt][nt][2], acc[mt][nt][3] + y[mt][nt][3]);
        }
    }
}

// ============================================================================
extern "C" void kernel_launch(void* const* d_in, const int* in_sizes, int n_in,
                              void* d_out, int out_size)
{
    const float* x     = (const float*)d_in[0];
    const float* ln1g  = (const float*)d_in[1];
    const float* ln1b  = (const float*)d_in[2];
    const float* wkqv  = (const float*)d_in[3];
    const float* bkqv  = (const float*)d_in[4];
    const float* wproj = (const float*)d_in[5];
    const float* bproj = (const float*)d_in[6];
    const float* ln2g  = (const float*)d_in[7];
    const float* ln2b  = (const float*)d_in[8];
    const float* wfc1  = (const float*)d_in[9];
    const float* bfc1  = (const float*)d_in[10];
    const float* wfc2  = (const float*)d_in[11];
    const float* bfc2  = (const float*)d_in[12];
    const float* wrf   = (const float*)d_in[13];

    cudaFuncSetAttribute(pass1_kernel, cudaFuncAttributeMaxDynamicSharedMemorySize, P1_BYTES);
    cudaFuncSetAttribute(pass2_kernel, cudaFuncAttributeMaxDynamicSharedMemorySize, P2_BYTES);

    setup_kernel<<<16, 256>>>(wkqv, bkqv, wrf);
    setup_split_kernel<<<54, 256>>>(wkqv, wfc1, wfc2);
    pass1_kernel<<<NBLK, 128, P1_BYTES>>>(x, ln1g, ln1b, bkqv);
    reduce1_kernel<<<dim3(NCH, BATCH), 256>>>();
    reduce2a_kernel<<<dim3(32, BATCH), 256>>>();
    wc2_kernel<<<dim3(9, BATCH), 256>>>(wproj);
    pass2_kernel<<<NBLK, 128, P2_BYTES>>>(bproj, ln2g, ln2b,
                                          bfc1, bfc2, (float*)d_out);
}

// round 17
// speedup vs baseline: 2.3137x; 1.0078x over previous
#include <cuda_runtime.h>
#include <cuda_bf16.h>
#include <stdint.h>
#include <math.h>

#define BATCH 4
#define S 96
#define DP 48
#define L (DP*DP*DP)            // 110592
#define NTOK (BATCH*L)          // 442368
#define MRF 32
#define NCH 108
#define NCH4 (NCH*4)            // 432 partial chunks
#define TILE 128
#define NBLK (NTOK/TILE)        // 3456

typedef unsigned int u32;
typedef unsigned long long u64;

// ---------------- scratch (token-major) ----------------
__device__ float g_kp[(size_t)NTOK * MRF];        // [tok][m]
__device__ float g_qp[(size_t)NTOK * MRF];        // [tok][m]
__device__ float g_v [(size_t)NTOK * 64];         // [tok][e]
__device__ float g_part_kptv[BATCH * NCH4 * 64 * MRF];
__device__ float g_part_ksum[BATCH * NCH4 * MRF];
__device__ float g_kptv[BATCH * 64 * MRF];        // [b][e][m]
__device__ float g_ksum[BATCH * MRF];
__device__ float g_wc[2 * 32 * 64];               // fused wrf@W{k,q}  [c][m][e]
__device__ float g_bc[2 * 32];                    // fused wrf@b{k,q}

// pre-split bf16 weight tiles, 144-B rows (36 u32/row), uint4-aligned
__device__ uint4 g_wkh[3 * 64 * 9], g_wkl[3 * 64 * 9];   // wkqv k/q/v
__device__ uint4 g_wch[2 * 32 * 9], g_wcl[2 * 32 * 9];   // fused RF (32 rows)
__device__ uint4 g_f1h[64 * 9],     g_f1l[64 * 9];       // wfc1
__device__ uint4 g_f2h[64 * 9],     g_f2l[64 * 9];       // wfc2
__device__ uint4 g_w2h[BATCH * 64 * 9], g_w2l[BATCH * 64 * 9];  // fused wproj@kptv^T

// ---------------- f32x2 helpers ----------------
__device__ __forceinline__ u64 dup2(float v) {
    u64 r; asm("mov.b64 %0, {%1, %1};" : "=l"(r) : "f"(v)); return r;
}
__device__ __forceinline__ void fma2(u64 &d, u64 a, u64 b) {
    asm("fma.rn.f32x2 %0, %1, %2, %0;" : "+l"(d) : "l"(a), "l"(b));
}
__device__ __forceinline__ u64 add2(u64 a, u64 b) {
    u64 r; asm("add.rn.f32x2 %0, %1, %2;" : "=l"(r) : "l"(a), "l"(b)); return r;
}
__device__ __forceinline__ float2 up2(u64 v) {
    float lo, hi; asm("mov.b64 {%0, %1}, %2;" : "=f"(lo), "=f"(hi) : "l"(v));
    return make_float2(lo, hi);
}

// ============================================================================
// mma.sync m16n8k16 bf16 core. A tiles [128][72] bf16, 144-B rows, no swizzle.
// ============================================================================
__device__ __forceinline__ void mma16816(float* c, const u32* a, u32 b0, u32 b1) {
    asm volatile(
        "mma.sync.aligned.m16n8k16.row.col.f32.bf16.bf16.f32 "
        "{%0,%1,%2,%3}, {%4,%5,%6,%7}, {%8,%9}, {%0,%1,%2,%3};"
        : "+f"(c[0]), "+f"(c[1]), "+f"(c[2]), "+f"(c[3])
        : "r"(a[0]), "r"(a[1]), "r"(a[2]), "r"(a[3]), "r"(b0), "r"(b1));
}

// 3-term split: Ahi*Bhi + Alo*Bhi + Ahi*Blo.
template<int KSTEPS, int NT>
__device__ __forceinline__ void mma_tile(
    const char* ah, const char* al,
    const char* bh, const char* bl,
    float (&acc)[2][NT][4], int w, int lane)
{
    const int g = lane >> 2;
    const int tig = lane & 3;
    #pragma unroll
    for (int ks = 0; ks < KSTEPS; ks++) {
        const int coff = ks * 32 + tig * 4;
        u32 Ah[2][4], Al[2][4];
        #pragma unroll
        for (int mt = 0; mt < 2; mt++) {
            const int r0 = (w * 32 + mt * 16 + g) * 144 + coff;
            const int r8 = r0 + 8 * 144;
            Ah[mt][0] = *(const u32*)(ah + r0);
            Ah[mt][1] = *(const u32*)(ah + r8);
            Ah[mt][2] = *(const u32*)(ah + r0 + 16);
            Ah[mt][3] = *(const u32*)(ah + r8 + 16);
            Al[mt][0] = *(const u32*)(al + r0);
            Al[mt][1] = *(const u32*)(al + r8);
            Al[mt][2] = *(const u32*)(al + r0 + 16);
            Al[mt][3] = *(const u32*)(al + r8 + 16);
        }
        #pragma unroll
        for (int nt = 0; nt < NT; nt++) {
            const int bo = (nt * 8 + g) * 144 + coff;
            const u32 Bh0 = *(const u32*)(bh + bo);
            const u32 Bh1 = *(const u32*)(bh + bo + 16);
            const u32 Bl0 = *(const u32*)(bl + bo);
            const u32 Bl1 = *(const u32*)(bl + bo + 16);
            #pragma unroll
            for (int mt = 0; mt < 2; mt++) {
                mma16816(acc[mt][nt], Ah[mt], Bh0, Bh1);
                mma16816(acc[mt][nt], Al[mt], Bh0, Bh1);
                mma16816(acc[mt][nt], Ah[mt], Bl0, Bl1);
            }
        }
    }
}

__device__ __forceinline__ float qsum(float v) {
    v += __shfl_xor_sync(0xffffffffu, v, 1);
    v += __shfl_xor_sync(0xffffffffu, v, 2);
    return v;
}

__device__ __forceinline__ void split_pair(float x0, float x1, u32& hi, u32& lo) {
    __nv_bfloat16 h0 = __float2bfloat16_rn(x0);
    __nv_bfloat16 h1 = __float2bfloat16_rn(x1);
    float r0 = x0 - __bfloat162float(h0);
    float r1 = x1 - __bfloat162float(h1);
    __nv_bfloat16 l0 = __float2bfloat16_rn(r0);
    __nv_bfloat16 l1 = __float2bfloat16_rn(r1);
    __nv_bfloat162 hh = __halves2bfloat162(h0, h1);
    __nv_bfloat162 ll = __halves2bfloat162(l0, l1);
    hi = *(u32*)&hh;
    lo = *(u32*)&ll;
}

template<int NT>
__device__ __forceinline__ void frag_to_A(char* ah, char* al,
                                          const float (&acc)[2][NT][4],
                                          int w, int lane) {
    const int g = lane >> 2, tig = lane & 3;
    #pragma unroll
    for (int mt = 0; mt < 2; mt++) {
        const int t0 = w * 32 + mt * 16 + g;
        #pragma unroll
        for (int nt = 0; nt < NT; nt++) {
            const int co = (nt * 8 + 2 * tig) * 2;
            u32 hi, lo;
            split_pair(acc[mt][nt][0], acc[mt][nt][1], hi, lo);
            *(u32*)(ah + t0 * 144 + co) = hi;
            *(u32*)(al + t0 * 144 + co) = lo;
            split_pair(acc[mt][nt][2], acc[mt][nt][3], hi, lo);
            *(u32*)(ah + (t0 + 8) * 144 + co) = hi;
            *(u32*)(al + (t0 + 8) * 144 + co) = lo;
        }
    }
}

template<int NT>
__device__ __forceinline__ void frag_to_gmem(float* dst, int C,
                                             const float (&acc)[2][NT][4],
                                             int w, int lane, int n0) {
    const int g = lane >> 2, tig = lane & 3;
    #pragma unroll
    for (int mt = 0; mt < 2; mt++) {
        const int t0 = w * 32 + mt * 16 + g;
        #pragma unroll
        for (int nt = 0; nt < NT; nt++) {
            const int col = nt * 8 + 2 * tig;
            *(float2*)&dst[(size_t)(n0 + t0) * C + col] =
                make_float2(acc[mt][nt][0], acc[mt][nt][1]);
            *(float2*)&dst[(size_t)(n0 + t0 + 8) * C + col] =
                make_float2(acc[mt][nt][2], acc[mt][nt][3]);
        }
    }
}

template<int NT>
__device__ __forceinline__ void add_bias(float (&acc)[2][NT][4],
                                         const float* bias, int lane) {
    const int tig = lane & 3;
    #pragma unroll
    for (int nt = 0; nt < NT; nt++) {
        const float2 bb = *(const float2*)&bias[nt * 8 + 2 * tig];
        #pragma unroll
        for (int mt = 0; mt < 2; mt++) {
            acc[mt][nt][0] += bb.x;
            acc[mt][nt][1] += bb.y;
            acc[mt][nt][2] += bb.x;
            acc[mt][nt][3] += bb.y;
        }
    }
}

template<int NE>
__device__ __forceinline__ void store_row(char* ahi, char* alo, int row,
                                          const float* v) {
    #pragma unroll
    for (int ch = 0; ch < NE / 8; ch++) {
        u32 h0, l0, h1, l1, h2, l2, h3, l3;
        split_pair(v[ch*8+0], v[ch*8+1], h0, l0);
        split_pair(v[ch*8+2], v[ch*8+3], h1, l1);
        split_pair(v[ch*8+4], v[ch*8+5], h2, l2);
        split_pair(v[ch*8+6], v[ch*8+7], h3, l3);
        const int off = row * 144 + ch * 16;
        *(uint4*)(ahi + off) = make_uint4(h0, h1, h2, h3);
        *(uint4*)(alo + off) = make_uint4(l0, l1, l2, l3);
    }
}

// copy pre-split tile (rows*9 uint4 each for hi/lo) gmem -> smem
__device__ __forceinline__ void stage_pre(char* dh, char* dl,
                                          const uint4* __restrict__ gh,
                                          const uint4* __restrict__ gl,
                                          int rows, int tid) {
    uint4* sh = (uint4*)dh;
    uint4* sl = (uint4*)dl;
    const int n = rows * 9;
    for (int p = tid; p < n; p += 128) {
        sh[p] = gh[p];
        sl[p] = gl[p];
    }
}

// ============================================================================
// Setup 1 (grid 16): Wc = wrf @ W{k,q}, bc = wrf @ b{k,q}
// ============================================================================
__global__ __launch_bounds__(256) void setup_kernel(
    const float* __restrict__ wkqv, const float* __restrict__ bkqv,
    const float* __restrict__ wrf)
{
    const int i = blockIdx.x * 256 + threadIdx.x;   // 0..4095
    const int c = i >> 11;
    const int m = (i >> 6) & 31;
    const int e = i & 63;
    float s = 0.0f;
    #pragma unroll 8
    for (int d = 0; d < 64; d++)
        s += wrf[m * 64 + d] * wkqv[c * 4096 + d * 64 + e];
    g_wc[i] = s;

    if (blockIdx.x == 0 && threadIdx.x < 64) {
        const int cc = threadIdx.x >> 5;
        const int mm = threadIdx.x & 31;
        float sb = 0.0f;
        #pragma unroll 8
        for (int d = 0; d < 64; d++)
            sb += wrf[mm * 64 + d] * bkqv[cc * 64 + d];
        g_bc[threadIdx.x] = sb;
    }
}

// ============================================================================
// Setup 2 (grid 54): pre-split all static weights into 144-B-row tiles
// ============================================================================
__global__ __launch_bounds__(256) void setup_split_kernel(
    const float* __restrict__ wkqv,
    const float* __restrict__ wfc1, const float* __restrict__ wfc2)
{
    const int i = blockIdx.x * 256 + threadIdx.x;
    if (i >= 13824) return;
    const int word = i % 36;
    const int rowg = i / 36;

    const float* src = 0;
    u32* dsth = 0;
    u32* dstl = 0;
    int row = 0, cols = 64;
    if (i < 6912) {               // wkqv
        src = wkqv; row = rowg;
        dsth = (u32*)g_wkh; dstl = (u32*)g_wkl;
    } else if (i < 9216) {        // wfc1
        src = wfc1; row = rowg - 192;
        dsth = (u32*)g_f1h; dstl = (u32*)g_f1l;
    } else if (i < 11520) {       // wfc2
        src = wfc2; row = rowg - 256;
        dsth = (u32*)g_f2h; dstl = (u32*)g_f2l;
    } else {                      // wc
        src = g_wc; row = rowg - 320;
        dsth = (u32*)g_wch; dstl = (u32*)g_wcl;
    }

    u32 hi = 0, lo = 0;
    if (word < 32) {
        const float2 wv = *(const float2*)(src + row * cols + word * 2);
        split_pair(wv.x, wv.y, hi, lo);
    }
    dsth[row * 36 + word] = hi;
    dstl[row * 36 + word] = lo;
}

// ============================================================================
// Pass 1: merged 96-row B tile (kqv 64 rows + fused-RF 32 rows), single mma.
// ============================================================================
#define Q1_AH  2048
#define Q1_AL  20480
#define Q1_BH  38912                 // 96 rows x 144 B = 13824
#define Q1_BL  52736
#define P1_BYTES (66560 + 1024)

__global__ __launch_bounds__(128, 3) void pass1_kernel(
    const float* __restrict__ x,
    const float* __restrict__ ln1g, const float* __restrict__ ln1b,
    const float* __restrict__ bkqv)
{
    extern __shared__ char smem_raw[];
    char* smem = (char*)(((size_t)smem_raw + 1023) & ~(size_t)1023);
    float* cst = (float*)smem;

    const int tid  = threadIdx.x;
    const int w    = tid >> 5;
    const int lane = tid & 31;
    const int g    = lane >> 2;
    const int tig  = lane & 3;
    const int n0   = blockIdx.x * TILE;
    const int b    = n0 / L;
    const int l0   = n0 % L;

    if (tid < 64) {
        cst[16 + tid]  = ln1g[tid];
        cst[80 + tid]  = ln1b[tid];
        cst[336 + tid] = g_bc[tid];
    }
    for (int i = tid; i < 192; i += 128) cst[144 + i] = bkqv[i];

    const int l  = l0 + tid;
    const int dz = l / (DP * DP);
    const int hy = (l / DP) % DP;
    const int wx = l % DP;
    const float* xb = x + (size_t)b * S * S * S;
    float h[64];
    float sum = 0.0f, sq = 0.0f;
    #pragma unroll
    for (int kd = 0; kd < 4; kd++) {
        const int iz = 2 * dz - 1 + kd;
        const bool zok = (unsigned)iz < (unsigned)S;
        #pragma unroll
        for (int kh = 0; kh < 4; kh++) {
            const int iy = 2 * hy - 1 + kh;
            const bool yok = zok && ((unsigned)iy < (unsigned)S);
            #pragma unroll
            for (int kw = 0; kw < 4; kw++) {
                const int ix = 2 * wx - 1 + kw;
                const float v = (yok && (unsigned)ix < (unsigned)S)
                              ? xb[((size_t)iz * S + iy) * S + ix] : 0.0f;
                h[kd * 16 + kh * 4 + kw] = v;
                sum += v;
                sq += v * v;
            }
        }
    }
    const float mu  = sum * (1.0f / 64.0f);
    const float var = sq * (1.0f / 64.0f) - mu * mu;
    const float rs  = rsqrtf(var + 1e-5f);

    __syncthreads();
    #pragma unroll
    for (int f = 0; f < 64; f++)
        h[f] = (h[f] - mu) * rs * cst[16 + f] + cst[80 + f];
    store_row<64>(smem + Q1_AH, smem + Q1_AL, tid, h);

    const float rfscale = 0.1767766952966369f;

    for (int c = 0; c < 3; c++) {
        __syncthreads();
        stage_pre(smem + Q1_BH, smem + Q1_BL, g_wkh + c * 576, g_wkl + c * 576,
                  64, tid);
        if (c < 2)
            stage_pre(smem + Q1_BH + 64 * 144, smem + Q1_BL + 64 * 144,
                      g_wch + c * 288, g_wcl + c * 288, 32, tid);
        __syncthreads();

        if (c < 2) {
            float acc[2][12][4];
            #pragma unroll
            for (int mt = 0; mt < 2; mt++)
                #pragma unroll
                for (int nt = 0; nt < 12; nt++)
                    #pragma unroll
                    for (int i = 0; i < 4; i++) acc[mt][nt][i] = 0.0f;
            mma_tile<4, 12>(smem + Q1_AH, smem + Q1_AL,
                            smem + Q1_BH, smem + Q1_BL, acc, w, lane);

            // biases: kqv rows (nt 0..7), fused-RF rows (nt 8..11)
            #pragma unroll
            for (int nt = 0; nt < 8; nt++) {
                const float2 bb = *(const float2*)&cst[144 + c * 64 + nt * 8 + 2 * tig];
                #pragma unroll
                for (int mt = 0; mt < 2; mt++) {
                    acc[mt][nt][0] += bb.x; acc[mt][nt][1] += bb.y;
                    acc[mt][nt][2] += bb.x; acc[mt][nt][3] += bb.y;
                }
            }
            #pragma unroll
            for (int nt = 0; nt < 4; nt++) {
                const float2 bb = *(const float2*)&cst[336 + c * 32 + nt * 8 + 2 * tig];
                #pragma unroll
                for (int mt = 0; mt < 2; mt++) {
                    acc[mt][8 + nt][0] += bb.x; acc[mt][8 + nt][1] += bb.y;
                    acc[mt][8 + nt][2] += bb.x; acc[mt][8 + nt][3] += bb.y;
                }
            }

            // xd per token over kq part
            float xd[2][2];
            #pragma unroll
            for (int mt = 0; mt < 2; mt++)
                #pragma unroll
                for (int hf = 0; hf < 2; hf++) {
                    float p = 0.0f;
                    #pragma unroll
                    for (int nt = 0; nt < 8; nt++) {
                        const float v0 = acc[mt][nt][2*hf];
                        const float v1 = acc[mt][nt][2*hf + 1];
                        p += v0 * v0 + v1 * v1;
                    }
                    xd[mt][hf] = 0.5f * qsum(p);
                }

            float* dst = (c == 0) ? g_kp : g_qp;
            #pragma unroll
            for (int mt = 0; mt < 2; mt++) {
                const int t0 = w * 32 + mt * 16 + g;
                #pragma unroll
                for (int nt = 0; nt < 4; nt++) {
                    const int col = nt * 8 + 2 * tig;
                    *(float2*)&dst[(size_t)(n0 + t0) * 32 + col] = make_float2(
                        __expf(acc[mt][8+nt][0] - xd[mt][0]) * rfscale,
                        __expf(acc[mt][8+nt][1] - xd[mt][0]) * rfscale);
                    *(float2*)&dst[(size_t)(n0 + t0 + 8) * 32 + col] = make_float2(
                        __expf(acc[mt][8+nt][2] - xd[mt][1]) * rfscale,
                        __expf(acc[mt][8+nt][3] - xd[mt][1]) * rfscale);
                }
            }
        } else {
            float acc[2][8][4];
            #pragma unroll
            for (int mt = 0; mt < 2; mt++)
                #pragma unroll
                for (int nt = 0; nt < 8; nt++)
                    #pragma unroll
                    for (int i = 0; i < 4; i++) acc[mt][nt][i] = 0.0f;
            mma_tile<4, 8>(smem + Q1_AH, smem + Q1_AL,
                           smem + Q1_BH, smem + Q1_BL, acc, w, lane);
            add_bias<8>(acc, &cst[144 + c * 64], lane);
            frag_to_gmem<8>(g_v, 64, acc, w, lane, n0);
        }
    }
}

// ============================================================================
// Reduce 1 v4: token-major tiles + packed f32x2 accumulation
// ============================================================================
__global__ __launch_bounds__(256) void reduce1_kernel()
{
    __shared__ __align__(16) float sv[64 * 68];   // [token][e], pad 68
    __shared__ __align__(16) float sk[64 * 36];   // [token][m], pad 36

    const int b = blockIdx.y;
    const int c = blockIdx.x;
    const int t = threadIdx.x;
    const int n0 = b * L + c * 1024;

    const int tq = t >> 6;          // 0..3 (token quarter; warps share a row)
    const int u  = t & 63;
    const int e4 = (u & 15) * 4;    // 0..60
    const int mb = (u >> 4) * 8;    // 0,8,16,24
    const bool do_ks = ((u & 15) == 0);

    u64 acc[4][4];                  // 4 e x 4 m-pairs
    #pragma unroll
    for (int i = 0; i < 4; i++)
        #pragma unroll
        for (int j = 0; j < 4; j++) acc[i][j] = 0ull;
    u64 ks[4];
    #pragma unroll
    for (int j = 0; j < 4; j++) ks[j] = 0ull;

    for (int tile = 0; tile < 16; tile++) {
        const int base = n0 + tile * 64;
        __syncthreads();
        for (int idx = t; idx < 1024; idx += 256) {
            const int tt = idx >> 4;
            const int eq = (idx & 15) * 4;
            *(float4*)&sv[tt * 68 + eq] =
                *(const float4*)&g_v[(size_t)(base + tt) * 64 + eq];
        }
        for (int idx = t; idx < 512; idx += 256) {
            const int tt = idx >> 3;
            const int mq = (idx & 7) * 4;
            *(float4*)&sk[tt * 36 + mq] =
                *(const float4*)&g_kp[(size_t)(base + tt) * 32 + mq];
        }
        __syncthreads();

        #pragma unroll 4
        for (int j = 0; j < 16; j++) {
            const int tt = tq * 16 + j;
            const float4 v4 = *(const float4*)&sv[tt * 68 + e4];
            const u64 k0 = *(const u64*)&sk[tt * 36 + mb];
            const u64 k1 = *(const u64*)&sk[tt * 36 + mb + 2];
            const u64 k2 = *(const u64*)&sk[tt * 36 + mb + 4];
            const u64 k3 = *(const u64*)&sk[tt * 36 + mb + 6];
            const u64 v0 = dup2(v4.x), v1 = dup2(v4.y);
            const u64 v2 = dup2(v4.z), v3 = dup2(v4.w);
            fma2(acc[0][0], v0, k0); fma2(acc[0][1], v0, k1);
            fma2(acc[0][2], v0, k2); fma2(acc[0][3], v0, k3);
            fma2(acc[1][0], v1, k0); fma2(acc[1][1], v1, k1);
            fma2(acc[1][2], v1, k2); fma2(acc[1][3], v1, k3);
            fma2(acc[2][0], v2, k0); fma2(acc[2][1], v2, k1);
            fma2(acc[2][2], v2, k2); fma2(acc[2][3], v2, k3);
            fma2(acc[3][0], v3, k0); fma2(acc[3][1], v3, k1);
            fma2(acc[3][2], v3, k2); fma2(acc[3][3], v3, k3);
            if (do_ks) {
                ks[0] = add2(ks[0], k0); ks[1] = add2(ks[1], k1);
                ks[2] = add2(ks[2], k2); ks[3] = add2(ks[3], k3);
            }
        }
    }

    const int slot = (b * NCH + c) * 4 + tq;
    #pragma unroll
    for (int i = 0; i < 4; i++) {
        float2 p0 = up2(acc[i][0]), p1 = up2(acc[i][1]);
        float2 p2 = up2(acc[i][2]), p3 = up2(acc[i][3]);
        float* p = &g_part_kptv[(size_t)slot * 2048 + (e4 + i) * 32 + mb];
        *(float4*)p       = make_float4(p0.x, p0.y, p1.x, p1.y);
        *(float4*)(p + 4) = make_float4(p2.x, p2.y, p3.x, p3.y);
    }
    if (do_ks) {
        float2 p0 = up2(ks[0]), p1 = up2(ks[1]);
        float2 p2 = up2(ks[2]), p3 = up2(ks[3]);
        float* p = &g_part_ksum[(size_t)slot * 32 + mb];
        *(float4*)p       = make_float4(p0.x, p0.y, p1.x, p1.y);
        *(float4*)(p + 4) = make_float4(p2.x, p2.y, p3.x, p3.y);
    }
}

// ============================================================================
// Reduce 2a (grid 32 x BATCH): chunk-parallel finalize kptv + ksum (NCH4)
// ============================================================================
__global__ __launch_bounds__(256) void reduce2a_kernel()
{
    const int b = blockIdx.y;
    const int t = threadIdx.x;
    const int e4   = t >> 2;
    const int part = t & 3;
    const int idx  = blockIdx.x * 64 + e4;

    float acc = 0.0f;
    const float* p = &g_part_kptv[(size_t)b * NCH4 * 2048 + idx];
    for (int c = part; c < NCH4; c += 4) acc += p[(size_t)c * 2048];
    acc += __shfl_xor_sync(0xffffffffu, acc, 1);
    acc += __shfl_xor_sync(0xffffffffu, acc, 2);
    if (part == 0) g_kptv[b * 2048 + idx] = acc;

    if (blockIdx.x == 0 && t < 128) {
        const int m = t >> 2;
        float s = 0.0f;
        const float* q = &g_part_ksum[(size_t)b * NCH4 * MRF + m];
        for (int c = part; c < NCH4; c += 4) s += q[(size_t)c * MRF];
        s += __shfl_xor_sync(0xffffffffu, s, 1);
        s += __shfl_xor_sync(0xffffffffu, s, 2);
        if (part == 0) g_ksum[b * MRF + m] = s;
    }
}

// ============================================================================
// Wc2 (grid 9 x BATCH): split-bf16 fused wproj@kptv^T
// ============================================================================
__global__ __launch_bounds__(256) void wc2_kernel(const float* __restrict__ wproj)
{
    const int b = blockIdx.y;
    const int i = blockIdx.x * 256 + threadIdx.x;
    if (i >= 2304) return;
    const int j = i / 36;
    const int word = i % 36;

    u32 hi = 0, lo = 0;
    if (word < 32) {
        const int m = word * 2;
        float s0 = 0.0f, s1 = 0.0f;
        #pragma unroll 8
        for (int e = 0; e < 64; e++) {
            const float wp = wproj[j * 64 + e];
            s0 += wp * g_kptv[b * 2048 + e * 32 + m];
            s1 += wp * g_kptv[b * 2048 + e * 32 + m + 1];
        }
        split_pair(s0, s1, hi, lo);
    }
    ((u32*)g_w2h)[b * 2304 + j * 36 + word] = hi;
    ((u32*)g_w2l)[b * 2304 + j * 36 + word] = lo;
}

// ============================================================================
// Pass 2 (unchanged from R15 winner)
// ============================================================================
#define Q2_AH 2048
#define Q2_AL 20480
#define Q2_BH 38912
#define Q2_BL 48128
#define P2_BYTES (57344 + 1024)

__global__ __launch_bounds__(128, 3) void pass2_kernel(
    const float* __restrict__ bproj,
    const float* __restrict__ ln2g,  const float* __restrict__ ln2b,
    const float* __restrict__ bfc1,  const float* __restrict__ bfc2,
    float* __restrict__ out)
{
    extern __shared__ char smem_raw[];
    char* smem = (char*)(((size_t)smem_raw + 1023) & ~(size_t)1023);
    float* cst = (float*)smem;

    const int tid  = threadIdx.x;
    const int w    = tid >> 5;
    const int lane = tid & 31;
    const int g    = lane >> 2;
    const int tig  = lane & 3;
    const int n0   = blockIdx.x * TILE;
    const int b    = n0 / L;

    if (tid < 64) {
        cst[16 + tid]  = bproj[tid];
        cst[80 + tid]  = ln2g[tid];
        cst[144 + tid] = ln2b[tid];
        cst[208 + tid] = bfc1[tid];
        cst[272 + tid] = bfc2[tid];
    }
    if (tid < 32) cst[336 + tid] = g_ksum[b * 32 + tid];
    stage_pre(smem + Q2_BH, smem + Q2_BL, g_w2h + b * 576, g_w2l + b * 576,
              64, tid);

    float qf[2][4][4];
    #pragma unroll
    for (int mt = 0; mt < 2; mt++) {
        const int t0 = w * 32 + mt * 16 + g;
        #pragma unroll
        for (int nt = 0; nt < 4; nt++) {
            const int col = nt * 8 + 2 * tig;
            const float2 a = *(const float2*)&g_qp[(size_t)(n0 + t0) * 32 + col];
            const float2 bb = *(const float2*)&g_qp[(size_t)(n0 + t0 + 8) * 32 + col];
            qf[mt][nt][0] = a.x;  qf[mt][nt][1] = a.y;
            qf[mt][nt][2] = bb.x; qf[mt][nt][3] = bb.y;
        }
    }
    __syncthreads();

    #pragma unroll
    for (int mt = 0; mt < 2; mt++)
        #pragma unroll
        for (int hf = 0; hf < 2; hf++) {
            float p = 0.0f;
            #pragma unroll
            for (int nt = 0; nt < 4; nt++) {
                const int col = nt * 8 + 2 * tig;
                p += qf[mt][nt][2*hf]     * cst[336 + col]
                   + qf[mt][nt][2*hf + 1] * cst[336 + col + 1];
            }
            const float invD = 1.0f / (qsum(p) + 1e-8f);
            #pragma unroll
            for (int nt = 0; nt < 4; nt++) {
                qf[mt][nt][2*hf]     *= invD;
                qf[mt][nt][2*hf + 1] *= invD;
            }
        }
    frag_to_A<4>(smem + Q2_AH, smem + Q2_AL, qf, w, lane);
    __syncthreads();

    float acc[2][8][4];
    #pragma unroll
    for (int mt = 0; mt < 2; mt++)
        #pragma unroll
        for (int nt = 0; nt < 8; nt++)
            #pragma unroll
            for (int i = 0; i < 4; i++) acc[mt][nt][i] = 0.0f;
    mma_tile<2, 8>(smem + Q2_AH, smem + Q2_AL, smem + Q2_BH, smem + Q2_BL,
                   acc, w, lane);
    add_bias<8>(acc, &cst[16], lane);

    float y[2][8][4];
    #pragma unroll
    for (int mt = 0; mt < 2; mt++) {
        const int t0 = w * 32 + mt * 16 + g;
        #pragma unroll
        for (int nt = 0; nt < 8; nt++) {
            const int col = nt * 8 + 2 * tig;
            const float2 va = *(const float2*)&g_v[(size_t)(n0 + t0) * 64 + col];
            const float2 vb = *(const float2*)&g_v[(size_t)(n0 + t0 + 8) * 64 + col];
            y[mt][nt][0] = acc[mt][nt][0] + va.x;
            y[mt][nt][1] = acc[mt][nt][1] + va.y;
            y[mt][nt][2] = acc[mt][nt][2] + vb.x;
            y[mt][nt][3] = acc[mt][nt][3] + vb.y;
        }
    }

    float nmu[2][2], rsg[2][2];
    #pragma unroll
    for (int mt = 0; mt < 2; mt++)
        #pragma unroll
        for (int hf = 0; hf < 2; hf++) {
            float p1 = 0.0f, p2 = 0.0f;
            #pragma unroll
            for (int nt = 0; nt < 8; nt++) {
                const float v0 = y[mt][nt][2*hf];
                const float v1 = y[mt][nt][2*hf + 1];
                p1 += v0 + v1;
                p2 += v0 * v0 + v1 * v1;
            }
            const float s1 = qsum(p1);
            const float s2 = qsum(p2);
            const float muv = s1 * (1.0f / 64.0f);
            const float var = s2 * (1.0f / 64.0f) - muv * muv;
            nmu[mt][hf] = -muv;
            rsg[mt][hf] = rsqrtf(var + 1e-5f);
        }

    __syncthreads();
    stage_pre(smem + Q2_BH, smem + Q2_BL, g_f1h, g_f1l, 64, tid);
    #pragma unroll
    for (int mt = 0; mt < 2; mt++) {
        const int t0 = w * 32 + mt * 16 + g;
        #pragma unroll
        for (int nt = 0; nt < 8; nt++) {
            const int col = nt * 8 + 2 * tig;
            const float2 gg = *(const float2*)&cst[80 + col];
            const float2 bb = *(const float2*)&cst[144 + col];
            const float z0 = (y[mt][nt][0] + nmu[mt][0]) * rsg[mt][0] * gg.x + bb.x;
            const float z1 = (y[mt][nt][1] + nmu[mt][0]) * rsg[mt][0] * gg.y + bb.y;
            const float z2 = (y[mt][nt][2] + nmu[mt][1]) * rsg[mt][1] * gg.x + bb.x;
            const float z3 = (y[mt][nt][3] + nmu[mt][1]) * rsg[mt][1] * gg.y + bb.y;
            u32 hi, lo;
            const int co = col * 2;
            split_pair(z0, z1, hi, lo);
            *(u32*)(smem + Q2_AH + t0 * 144 + co) = hi;
            *(u32*)(smem + Q2_AL + t0 * 144 + co) = lo;
            split_pair(z2, z3, hi, lo);
            *(u32*)(smem + Q2_AH + (t0 + 8) * 144 + co) = hi;
            *(u32*)(smem + Q2_AL + (t0 + 8) * 144 + co) = lo;
        }
    }
    __syncthreads();

    #pragma unroll
    for (int mt = 0; mt < 2; mt++)
        #pragma unroll
        for (int nt = 0; nt < 8; nt++)
            #pragma unroll
            for (int i = 0; i < 4; i++) acc[mt][nt][i] = 0.0f;
    mma_tile<4, 8>(smem + Q2_AH, smem + Q2_AL, smem + Q2_BH, smem + Q2_BL,
                   acc, w, lane);
    add_bias<8>(acc, &cst[208], lane);
    #pragma unroll
    for (int mt = 0; mt < 2; mt++)
        #pragma unroll
        for (int nt = 0; nt < 8; nt++)
            #pragma unroll
            for (int i = 0; i < 4; i++) {
                const float v = acc[mt][nt][i];
                acc[mt][nt][i] = 0.5f * v * (1.0f + erff(v * 0.7071067811865476f));
            }
    __syncthreads();
    stage_pre(smem + Q2_BH, smem + Q2_BL, g_f2h, g_f2l, 64, tid);
    frag_to_A<8>(smem + Q2_AH, smem + Q2_AL, acc, w, lane);
    __syncthreads();

    #pragma unroll
    for (int mt = 0; mt < 2; mt++)
        #pragma unroll
        for (int nt = 0; nt < 8; nt++)
            #pragma unroll
            for (int i = 0; i < 4; i++) acc[mt][nt][i] = 0.0f;
    mma_tile<4, 8>(smem + Q2_AH, smem + Q2_AL, smem + Q2_BH, smem + Q2_BL,
                   acc, w, lane);
    add_bias<8>(acc, &cst[272], lane);
    #pragma unroll
    for (int mt = 0; mt < 2; mt++) {
        const int t0 = w * 32 + mt * 16 + g;
        #pragma unroll
        for (int nt = 0; nt < 8; nt++) {
            const int col = nt * 8 + 2 * tig;
            *(float2*)&out[(size_t)(n0 + t0) * 64 + col] = make_float2(
                acc[mt][nt][0] + y[mt][nt][0], acc[mt][nt][1] + y[mt][nt][1]);
            *(float2*)&out[(size_t)(n0 + t0 + 8) * 64 + col] = make_float2(
                acc[mt][nt][2] + y[mt][nt][2], acc[mt][nt][3] + y[mt][nt][3]);
        }
    }
}

// ============================================================================
extern "C" void kernel_launch(void* const* d_in, const int* in_sizes, int n_in,
                              void* d_out, int out_size)
{
    const float* x     = (const float*)d_in[0];
    const float* ln1g  = (const float*)d_in[1];
    const float* ln1b  = (const float*)d_in[2];
    const float* wkqv  = (const float*)d_in[3];
    const float* bkqv  = (const float*)d_in[4];
    const float* wproj = (const float*)d_in[5];
    const float* bproj = (const float*)d_in[6];
    const float* ln2g  = (const float*)d_in[7];
    const float* ln2b  = (const float*)d_in[8];
    const float* wfc1  = (const float*)d_in[9];
    const float* bfc1  = (const float*)d_in[10];
    const float* wfc2  = (const float*)d_in[11];
    const float* bfc2  = (const float*)d_in[12];
    const float* wrf   = (const float*)d_in[13];

    cudaFuncSetAttribute(pass1_kernel, cudaFuncAttributeMaxDynamicSharedMemorySize, P1_BYTES);
    cudaFuncSetAttribute(pass2_kernel, cudaFuncAttributeMaxDynamicSharedMemorySize, P2_BYTES);

    setup_kernel<<<16, 256>>>(wkqv, bkqv, wrf);
    setup_split_kernel<<<54, 256>>>(wkqv, wfc1, wfc2);
    pass1_kernel<<<NBLK, 128, P1_BYTES>>>(x, ln1g, ln1b, bkqv);
    reduce1_kernel<<<dim3(NCH, BATCH), 256>>>();
    reduce2a_kernel<<<dim3(32, BATCH), 256>>>();
    wc2_kernel<<<dim3(9, BATCH), 256>>>(wproj);
    pass2_kernel<<<NBLK, 128, P2_BYTES>>>(bproj, ln2g, ln2b,
                                          bfc1, bfc2, (float*)d_out);
}